// round 2
// baseline (speedup 1.0000x reference)
#include <cuda_runtime.h>
#include <math_constants.h>

#define NPTS   8192
#define BATCH  2
#define BN_TOT (BATCH*NPTS)      /* 16384 */
#define KNB    20
#define M2     (BN_TOT*KNB)      /* 327680 */

/* ------------------------- device scratch ------------------------- */
__device__ float g_xa[BN_TOT*64];
__device__ float g_xb[BN_TOT*64];
__device__ float g_q [BN_TOT*64];
__device__ float g_k [BN_TOT*64];
__device__ float g_v [BN_TOT*64];
__device__ int   g_idx[M2];
__device__ float g_qw[BN_TOT*256];
__device__ float g_kw[BN_TOT*256];
__device__ float g_w2cat[64*320];
__device__ float g_cvec[256];
__device__ float g_vnb[M2*64];
__device__ float g_sim[M2];
__device__ float g_part[BATCH*64*64];

/* ------------------------- f32x2 helpers -------------------------- */
typedef unsigned long long ull;
__device__ __forceinline__ void fma2(ull &d, ull a, ull b){
    asm("fma.rn.f32x2 %0, %1, %2, %0;" : "+l"(d) : "l"(a), "l"(b));
}
__device__ __forceinline__ float2 unpack2(ull v){
    float2 f; asm("mov.b64 {%0,%1}, %2;" : "=f"(f.x), "=f"(f.y) : "l"(v));
    return f;
}

/* ------------------------- embed: relu(points @ conv_w + b) -------- */
__global__ __launch_bounds__(256) void embed_kernel(
    const float* __restrict__ pts, const float* __restrict__ w,
    const float* __restrict__ b)
{
    int i = blockIdx.x*256 + threadIdx.x;
    int row = i >> 6, c = i & 63;
    float x = pts[row*3+0], y = pts[row*3+1], z = pts[row*3+2];
    float s = x*w[c] + y*w[64+c] + z*w[128+c] + b[c];
    g_xa[i] = fmaxf(s, 0.f);
}

/* ------------------------- KNN ------------------------------------ */
__device__ __forceinline__ bool kless(float d1,int i1,float d2,int i2){
    return d1 < d2 || (d1 == d2 && i1 < i2);
}

__global__ __launch_bounds__(256) void knn_kernel(const float* __restrict__ pts)
{
    const int SPL=8, QPB=32, TILE=256;
    __shared__ float4 sp[TILE];
    __shared__ float  sd[QPB][SPL*KNB];
    __shared__ int    si[QPB][SPL*KNB];
    int t = threadIdx.x;
    int qi = t >> 3, lane = t & 7;
    int gq = blockIdx.x*QPB + qi;
    int b  = gq >> 13;
    const float* qp = pts + gq*3;
    float qx=qp[0], qy=qp[1], qz=qp[2];
    float bd[KNB]; int bi[KNB];
    #pragma unroll
    for (int p=0;p<KNB;p++){ bd[p]=CUDART_INF_F; bi[p]=0x7fffffff; }

    for (int t0=0; t0<NPTS; t0+=TILE){
        __syncthreads();
        {
            const float* pp = pts + (size_t)(b*NPTS + t0 + t)*3;
            sp[t] = make_float4(pp[0], pp[1], pp[2], 0.f);
        }
        __syncthreads();
        for (int c=lane; c<TILE; c+=SPL){
            float4 p = sp[c];
            float dx=qx-p.x, dy=qy-p.y, dz=qz-p.z;
            float d2 = dx*dx + dy*dy + dz*dz;
            int id = t0 + c;
            if (kless(d2, id, bd[KNB-1], bi[KNB-1])){
                float nd=d2; int ni=id; bool done=false;
                #pragma unroll
                for (int p=KNB-1; p>=1; --p){
                    bool sh = kless(nd, ni, bd[p-1], bi[p-1]);
                    if (!done){
                        bd[p] = sh ? bd[p-1] : nd;
                        bi[p] = sh ? bi[p-1] : ni;
                    }
                    done = done || !sh;
                }
                if (!done){ bd[0]=nd; bi[0]=ni; }
            }
        }
    }
    #pragma unroll
    for (int p=0;p<KNB;p++){ sd[qi][lane*KNB+p]=bd[p]; si[qi][lane*KNB+p]=bi[p]; }
    __syncthreads();
    if (lane == 0){
        int ptr[SPL];
        #pragma unroll
        for (int s=0;s<SPL;s++) ptr[s]=0;
        for (int r=0;r<KNB;r++){
            float best=CUDART_INF_F; int besti=0x7fffffff; int bs=0;
            #pragma unroll
            for (int s=0;s<SPL;s++){
                if (ptr[s] < KNB){
                    float d = sd[qi][s*KNB+ptr[s]];
                    int  ii = si[qi][s*KNB+ptr[s]];
                    if (kless(d, ii, best, besti)){ best=d; besti=ii; bs=s; }
                }
            }
            ptr[bs]++;
            g_idx[gq*KNB + r] = besti;
        }
    }
}

/* ------------------------- qkv GEMM (M=16384, K=64, N=192) -------- */
__global__ __launch_bounds__(256) void qkv_kernel(int xsel, const float* __restrict__ W)
{
    __shared__ float As[64][68];
    __shared__ __align__(16) float Bs[16][64];
    const float* X = xsel ? g_xb : g_xa;
    int t = threadIdx.x, tx = t & 15, ty = t >> 4;
    int bm0 = blockIdx.x * 64;
    int bn0 = blockIdx.y * 64;
    #pragma unroll
    for (int i=0;i<4;i++){
        int idx4 = t + i*256;
        int r = idx4 >> 4, c4 = idx4 & 15;
        *(float4*)&As[r][4*c4] = *(const float4*)&X[(size_t)(bm0+r)*64 + 4*c4];
    }
    float acc[4][4] = {};
    for (int ch=0; ch<64; ch+=16){
        __syncthreads();
        {
            int r = t >> 4, c4 = t & 15;
            *(float4*)&Bs[r][4*c4] = *(const float4*)&W[(ch+r)*192 + bn0 + 4*c4];
        }
        __syncthreads();
        #pragma unroll
        for (int k=0;k<16;k++){
            float a0=As[4*ty+0][ch+k], a1=As[4*ty+1][ch+k];
            float a2=As[4*ty+2][ch+k], a3=As[4*ty+3][ch+k];
            float4 bq = *(float4*)&Bs[k][4*tx];
            acc[0][0]+=a0*bq.x; acc[0][1]+=a0*bq.y; acc[0][2]+=a0*bq.z; acc[0][3]+=a0*bq.w;
            acc[1][0]+=a1*bq.x; acc[1][1]+=a1*bq.y; acc[1][2]+=a1*bq.z; acc[1][3]+=a1*bq.w;
            acc[2][0]+=a2*bq.x; acc[2][1]+=a2*bq.y; acc[2][2]+=a2*bq.z; acc[2][3]+=a2*bq.w;
            acc[3][0]+=a3*bq.x; acc[3][1]+=a3*bq.y; acc[3][2]+=a3*bq.z; acc[3][3]+=a3*bq.w;
        }
    }
    float* outp = (bn0 == 0) ? g_q : (bn0 == 64) ? g_k : g_v;
    #pragma unroll
    for (int i=0;i<4;i++){
        float4 o = make_float4(acc[i][0], acc[i][1], acc[i][2], acc[i][3]);
        *(float4*)&outp[(size_t)(bm0+4*ty+i)*64 + 4*tx] = o;
    }
}

/* ---------- prep: W2cat = [pw2 | pw2 @ aw1_bot], cvec ------------- */
__global__ __launch_bounds__(256) void prep_w2cat_kernel(
    const float* __restrict__ pw2, const float* __restrict__ aw1)
{
    int i = blockIdx.x*256 + threadIdx.x;     /* 64*320 */
    int r = i / 320, c = i % 320;
    if (c < 64){
        g_w2cat[i] = pw2[r*64 + c];
    } else {
        int cc = c - 64;
        float s = 0.f;
        #pragma unroll 8
        for (int d=0; d<64; d++)
            s += pw2[r*64 + d] * aw1[(64+d)*256 + cc];
        g_w2cat[i] = s;
    }
}

__global__ void prep_cvec_kernel(
    const float* __restrict__ aw1, const float* __restrict__ pb2,
    const float* __restrict__ ab1)
{
    int c = threadIdx.x;                      /* 256 */
    float s = ab1[c];
    #pragma unroll 8
    for (int d=0; d<64; d++)
        s += pb2[d] * aw1[(64+d)*256 + c];
    g_cvec[c] = s;
}

/* ----------- qW/kW: (16384,64) @ aw1_top(64,256), f32x2 ----------- */
__global__ __launch_bounds__(256) void gemm_qk_kernel(
    const float* __restrict__ X, const float* __restrict__ W,
    float* __restrict__ Y)
{
    __shared__ float2 As2[64][65];
    __shared__ __align__(16) float Bs[16][64];
    int t = threadIdx.x, tx = t & 15, ty = t >> 4;
    int bm0 = blockIdx.x * 64;
    int bn0 = blockIdx.y * 64;
    #pragma unroll
    for (int i=0;i<4;i++){
        int idx4 = t + i*256;
        int r = idx4 >> 4, c4 = idx4 & 15;
        float4 v = *(const float4*)&X[(size_t)(bm0+r)*64 + 4*c4];
        As2[r][4*c4+0] = make_float2(v.x, v.x);
        As2[r][4*c4+1] = make_float2(v.y, v.y);
        As2[r][4*c4+2] = make_float2(v.z, v.z);
        As2[r][4*c4+3] = make_float2(v.w, v.w);
    }
    ull acc[4][2] = {};
    for (int ch=0; ch<64; ch+=16){
        __syncthreads();
        {
            int r = t >> 4, c4 = t & 15;
            *(float4*)&Bs[r][4*c4] = *(const float4*)&W[(ch+r)*256 + bn0 + 4*c4];
        }
        __syncthreads();
        #pragma unroll
        for (int k=0;k<16;k++){
            ull a0 = *(ull*)&As2[4*ty+0][ch+k];
            ull a1 = *(ull*)&As2[4*ty+1][ch+k];
            ull a2 = *(ull*)&As2[4*ty+2][ch+k];
            ull a3 = *(ull*)&As2[4*ty+3][ch+k];
            ulonglong2 b2 = *(ulonglong2*)&Bs[k][4*tx];
            fma2(acc[0][0], a0, b2.x); fma2(acc[0][1], a0, b2.y);
            fma2(acc[1][0], a1, b2.x); fma2(acc[1][1], a1, b2.y);
            fma2(acc[2][0], a2, b2.x); fma2(acc[2][1], a2, b2.y);
            fma2(acc[3][0], a3, b2.x); fma2(acc[3][1], a3, b2.y);
        }
    }
    #pragma unroll
    for (int i=0;i<4;i++){
        float2 lo = unpack2(acc[i][0]), hi = unpack2(acc[i][1]);
        float4 o = make_float4(lo.x, lo.y, hi.x, hi.y);
        *(float4*)&Y[(size_t)(bm0+4*ty+i)*256 + bn0 + 4*tx] = o;
    }
}

/* --- fused: h1 -> H = h1@W2cat -> {vnb, sim} all in one kernel ---- */
__global__ __launch_bounds__(256) void fused_attn_kernel(
    const float* __restrict__ pts,
    const float* __restrict__ pw1, const float* __restrict__ pb1,
    const float* __restrict__ pb2, const float* __restrict__ aw2,
    const float* __restrict__ ab2)
{
    __shared__ float2 As2[64][65];
    __shared__ __align__(16) float Bs[16][64];
    __shared__ float red[64][17];
    int t = threadIdx.x, tx = t & 15, ty = t >> 4;
    int bm0 = blockIdx.x * 64;

    /* compute h1 rows directly into duplicated As2 */
    {
        int r = t >> 2;                       /* 64 rows, 4 threads each */
        int c0 = (t & 3) * 16;
        int m = bm0 + r;
        int gq = m / KNB;
        int b  = gq >> 13;
        int jr = (b<<13) + g_idx[m];
        float rx = pts[gq*3+0] - pts[(size_t)jr*3+0];
        float ry = pts[gq*3+1] - pts[(size_t)jr*3+1];
        float rz = pts[gq*3+2] - pts[(size_t)jr*3+2];
        #pragma unroll
        for (int c=c0; c<c0+16; c++){
            float h = fmaxf(fmaf(rx, pw1[c], fmaf(ry, pw1[64+c],
                            fmaf(rz, pw1[128+c], pb1[c]))), 0.f);
            As2[r][c] = make_float2(h, h);
        }
    }

    /* per-thread row metadata */
    int gq_r[4], jr_r[4];
    #pragma unroll
    for (int i=0;i<4;i++){
        int m = bm0 + 4*ty + i;
        gq_r[i] = m / KNB;
        int b = gq_r[i] >> 13;
        jr_r[i] = (b<<13) + g_idx[m];
    }

    float rsum[4] = {0.f,0.f,0.f,0.f};
    for (int nb=0; nb<5; nb++){
        ull acc[4][2] = {};
        for (int ch=0; ch<64; ch+=16){
            __syncthreads();
            {
                int r = t >> 4, c4 = t & 15;
                *(float4*)&Bs[r][4*c4] =
                    *(const float4*)&g_w2cat[(ch+r)*320 + nb*64 + 4*c4];
            }
            __syncthreads();
            #pragma unroll
            for (int k=0;k<16;k++){
                ull a0 = *(ull*)&As2[4*ty+0][ch+k];
                ull a1 = *(ull*)&As2[4*ty+1][ch+k];
                ull a2 = *(ull*)&As2[4*ty+2][ch+k];
                ull a3 = *(ull*)&As2[4*ty+3][ch+k];
                ulonglong2 b2 = *(ulonglong2*)&Bs[k][4*tx];
                fma2(acc[0][0], a0, b2.x); fma2(acc[0][1], a0, b2.y);
                fma2(acc[1][0], a1, b2.x); fma2(acc[1][1], a1, b2.y);
                fma2(acc[2][0], a2, b2.x); fma2(acc[2][1], a2, b2.y);
                fma2(acc[3][0], a3, b2.x); fma2(acc[3][1], a3, b2.y);
            }
        }
        if (nb == 0){
            /* v_nb = acc + pb2 + v[jr] */
            float4 pb = *(const float4*)&pb2[4*tx];
            #pragma unroll
            for (int i=0;i<4;i++){
                int m = bm0 + 4*ty + i;
                float2 lo = unpack2(acc[i][0]), hi = unpack2(acc[i][1]);
                float4 vv = *(const float4*)&g_v[(size_t)jr_r[i]*64 + 4*tx];
                float4 o = make_float4(lo.x+pb.x+vv.x, lo.y+pb.y+vv.y,
                                       hi.x+pb.z+vv.z, hi.y+pb.w+vv.w);
                *(float4*)&g_vnb[(size_t)m*64 + 4*tx] = o;
            }
        } else {
            int cb = (nb-1)*64 + 4*tx;
            float4 cv = *(const float4*)&g_cvec[cb];
            float4 a2 = *(const float4*)&aw2[cb];
            #pragma unroll
            for (int i=0;i<4;i++){
                float2 lo = unpack2(acc[i][0]), hi = unpack2(acc[i][1]);
                float4 qv = *(const float4*)&g_qw[(size_t)gq_r[i]*256 + cb];
                float4 kv = *(const float4*)&g_kw[(size_t)jr_r[i]*256 + cb];
                float h0 = fmaxf(lo.x + cv.x + qv.x - kv.x, 0.f);
                float h1_ = fmaxf(lo.y + cv.y + qv.y - kv.y, 0.f);
                float h2 = fmaxf(hi.x + cv.z + qv.z - kv.z, 0.f);
                float h3 = fmaxf(hi.y + cv.w + qv.w - kv.w, 0.f);
                rsum[i] += h0*a2.x + h1_*a2.y + h2*a2.z + h3*a2.w;
            }
        }
    }
    __syncthreads();
    #pragma unroll
    for (int i=0;i<4;i++) red[4*ty+i][tx] = rsum[i];
    __syncthreads();
    if (t < 64){
        float s = ab2[0];
        #pragma unroll
        for (int x=0;x<16;x++) s += red[t][x];
        g_sim[bm0 + t] = s;
    }
}

/* ---------------- softmax over K + weighted sum of v_nb ----------- */
__global__ __launch_bounds__(256) void softmax_kernel(int outsel)
{
    float* xout = outsel ? g_xb : g_xa;
    int gt = blockIdx.x*256 + threadIdx.x;
    int w = gt >> 5, lane = gt & 31;
    float s = (lane < KNB) ? g_sim[w*KNB + lane] : -CUDART_INF_F;
    float m = s;
    #pragma unroll
    for (int off=16; off; off>>=1) m = fmaxf(m, __shfl_xor_sync(0xffffffffu, m, off));
    float e = (lane < KNB) ? expf(s - m) : 0.f;
    float sum = e;
    #pragma unroll
    for (int off=16; off; off>>=1) sum += __shfl_xor_sync(0xffffffffu, sum, off);
    float attn = e / sum;
    float acc0 = 0.f, acc1 = 0.f;
    #pragma unroll
    for (int kk=0; kk<KNB; kk++){
        float a = __shfl_sync(0xffffffffu, attn, kk);
        const float* vb = &g_vnb[(size_t)(w*KNB + kk)*64];
        acc0 += a * vb[lane];
        acc1 += a * vb[32 + lane];
    }
    xout[(size_t)w*64 + lane]      = acc0;
    xout[(size_t)w*64 + 32 + lane] = acc1;
}

/* ---------------- global max pool (partial) ----------------------- */
__global__ void pool_kernel(void)
{
    int b = blockIdx.x, ch = blockIdx.y, c = threadIdx.x;
    float m = -CUDART_INF_F;
    int base = b*NPTS + ch*128;
    #pragma unroll 4
    for (int n=0;n<128;n++) m = fmaxf(m, g_xa[(size_t)(base+n)*64 + c]);
    g_part[(b*64 + ch)*64 + c] = m;
}

/* ---------------- head ------------------------------------------- */
__global__ void head_kernel(
    const float* __restrict__ fc1w, const float* __restrict__ fc1b,
    const float* __restrict__ fc3w, const float* __restrict__ fc3b,
    float* __restrict__ out)
{
    __shared__ float sp[BATCH*64];
    __shared__ float sh[BATCH*32];
    int t = threadIdx.x;
    if (t < 128){
        int b = t >> 6, c = t & 63;
        float m = -CUDART_INF_F;
        for (int ch=0; ch<64; ch++) m = fmaxf(m, g_part[(b*64+ch)*64 + c]);
        sp[b*64 + c] = m;
    }
    __syncthreads();
    if (t < 64){
        int b = t >> 5, cc = t & 31;
        float s = fc1b[cc];
        for (int c=0;c<64;c++) s += sp[b*64+c] * fc1w[c*32 + cc];
        sh[b*32 + cc] = fmaxf(s, 0.f);
    }
    __syncthreads();
    if (t < 6){
        int b = t / 3, o = t % 3;
        float s = fc3b[o];
        for (int cc=0;cc<32;cc++) s += sh[b*32+cc] * fc3w[cc*3 + o];
        out[b*3 + o] = s;
    }
}

/* ------------------------------ launch ---------------------------- */
static void run_layer(const float* pts, const float* const* W, int xsel)
{
    /* W: qkv, pw1, pb1, pw2, pb2, aw1, ab1, aw2, ab2 */
    prep_w2cat_kernel<<<64*320/256, 256>>>(W[3], W[5]);
    prep_cvec_kernel<<<1, 256>>>(W[5], W[4], W[6]);
    qkv_kernel<<<dim3(BN_TOT/64, 3), 256>>>(xsel, W[0]);
    gemm_qk_kernel<<<dim3(BN_TOT/64, 4), 256>>>(g_q, W[5], g_qw);
    gemm_qk_kernel<<<dim3(BN_TOT/64, 4), 256>>>(g_k, W[5], g_kw);
    fused_attn_kernel<<<M2/64, 256>>>(pts, W[1], W[2], W[4], W[7], W[8]);
    softmax_kernel<<<BN_TOT*32/256, 256>>>(xsel == 0 ? 1 : 0);
}

extern "C" void kernel_launch(void* const* d_in, const int* in_sizes, int n_in,
                              void* d_out, int out_size)
{
    (void)in_sizes; (void)n_in; (void)out_size;
    const float* pts = (const float*)d_in[0];
    float* out = (float*)d_out;

    embed_kernel<<<BN_TOT*64/256, 256>>>(pts, (const float*)d_in[1], (const float*)d_in[2]);
    knn_kernel<<<BN_TOT/32, 256>>>(pts);

    const float* W1[9] = {
        (const float*)d_in[3], (const float*)d_in[4], (const float*)d_in[5],
        (const float*)d_in[6], (const float*)d_in[7], (const float*)d_in[8],
        (const float*)d_in[9], (const float*)d_in[10], (const float*)d_in[11]};
    const float* W2[9] = {
        (const float*)d_in[12], (const float*)d_in[13], (const float*)d_in[14],
        (const float*)d_in[15], (const float*)d_in[16], (const float*)d_in[17],
        (const float*)d_in[18], (const float*)d_in[19], (const float*)d_in[20]};

    run_layer(pts, W1, 0);   /* reads g_xa, writes g_xb */
    run_layer(pts, W2, 1);   /* reads g_xb, writes g_xa */

    pool_kernel<<<dim3(BATCH, 64), 64>>>();
    head_kernel<<<1, 128>>>((const float*)d_in[21], (const float*)d_in[22],
                            (const float*)d_in[23], (const float*)d_in[24], out);
}

// round 3
// speedup vs baseline: 1.0386x; 1.0386x over previous
#include <cuda_runtime.h>
#include <math_constants.h>

#define NPTS   8192
#define BATCH  2
#define BN_TOT (BATCH*NPTS)      /* 16384 */
#define KNB    20
#define M2     (BN_TOT*KNB)      /* 327680 */
#define QPB    4                 /* queries per fused block */
#define RPB    (QPB*KNB)         /* 80 pair-rows per block */

/* ------------------------- device scratch ------------------------- */
__device__ float g_xa[BN_TOT*64];
__device__ float g_xb[BN_TOT*64];
__device__ float g_q [BN_TOT*64];
__device__ float g_k [BN_TOT*64];
__device__ float g_v [BN_TOT*64];
__device__ int   g_idx[M2];
__device__ float g_qw[BN_TOT*256];
__device__ float g_kw[BN_TOT*256];
__device__ __align__(16) float g_w2cat[64*320];
__device__ __align__(16) float g_cvec[256];
__device__ float g_part[BATCH*64*64];

/* ------------------------- embed: relu(points @ conv_w + b) -------- */
__global__ __launch_bounds__(256) void embed_kernel(
    const float* __restrict__ pts, const float* __restrict__ w,
    const float* __restrict__ b)
{
    int i = blockIdx.x*256 + threadIdx.x;
    int row = i >> 6, c = i & 63;
    float x = pts[row*3+0], y = pts[row*3+1], z = pts[row*3+2];
    float s = x*w[c] + y*w[64+c] + z*w[128+c] + b[c];
    g_xa[i] = fmaxf(s, 0.f);
}

/* ------------------------- KNN ------------------------------------ */
__device__ __forceinline__ bool kless(float d1,int i1,float d2,int i2){
    return d1 < d2 || (d1 == d2 && i1 < i2);
}

__global__ __launch_bounds__(256) void knn_kernel(const float* __restrict__ pts)
{
    const int SPL=8, QPBK=32, TILE=256;
    __shared__ float4 sp[TILE];
    __shared__ float  sd[QPBK][SPL*KNB];
    __shared__ int    si[QPBK][SPL*KNB];
    int t = threadIdx.x;
    int qi = t >> 3, lane = t & 7;
    int gq = blockIdx.x*QPBK + qi;
    int b  = gq >> 13;
    const float* qp = pts + gq*3;
    float qx=qp[0], qy=qp[1], qz=qp[2];
    float bd[KNB]; int bi[KNB];
    #pragma unroll
    for (int p=0;p<KNB;p++){ bd[p]=CUDART_INF_F; bi[p]=0x7fffffff; }

    for (int t0=0; t0<NPTS; t0+=TILE){
        __syncthreads();
        {
            const float* pp = pts + (size_t)(b*NPTS + t0 + t)*3;
            sp[t] = make_float4(pp[0], pp[1], pp[2], 0.f);
        }
        __syncthreads();
        for (int c=lane; c<TILE; c+=SPL){
            float4 p = sp[c];
            float dx=qx-p.x, dy=qy-p.y, dz=qz-p.z;
            float d2 = dx*dx + dy*dy + dz*dz;
            int id = t0 + c;
            if (kless(d2, id, bd[KNB-1], bi[KNB-1])){
                float nd=d2; int ni=id; bool done=false;
                #pragma unroll
                for (int p=KNB-1; p>=1; --p){
                    bool sh = kless(nd, ni, bd[p-1], bi[p-1]);
                    if (!done){
                        bd[p] = sh ? bd[p-1] : nd;
                        bi[p] = sh ? bi[p-1] : ni;
                    }
                    done = done || !sh;
                }
                if (!done){ bd[0]=nd; bi[0]=ni; }
            }
        }
    }
    #pragma unroll
    for (int p=0;p<KNB;p++){ sd[qi][lane*KNB+p]=bd[p]; si[qi][lane*KNB+p]=bi[p]; }
    __syncthreads();
    if (lane == 0){
        int ptr[SPL];
        #pragma unroll
        for (int s=0;s<SPL;s++) ptr[s]=0;
        for (int r=0;r<KNB;r++){
            float best=CUDART_INF_F; int besti=0x7fffffff; int bs=0;
            #pragma unroll
            for (int s=0;s<SPL;s++){
                if (ptr[s] < KNB){
                    float d = sd[qi][s*KNB+ptr[s]];
                    int  ii = si[qi][s*KNB+ptr[s]];
                    if (kless(d, ii, best, besti)){ best=d; besti=ii; bs=s; }
                }
            }
            ptr[bs]++;
            g_idx[gq*KNB + r] = besti;
        }
    }
}

/* ------------------------- qkv GEMM (M=16384, K=64, N=192) -------- */
__global__ __launch_bounds__(256) void qkv_kernel(int xsel, const float* __restrict__ W)
{
    __shared__ float As[64][68];
    __shared__ __align__(16) float Bs[16][64];
    const float* X = xsel ? g_xb : g_xa;
    int t = threadIdx.x, tx = t & 15, ty = t >> 4;
    int bm0 = blockIdx.x * 64;
    int bn0 = blockIdx.y * 64;
    #pragma unroll
    for (int i=0;i<4;i++){
        int idx4 = t + i*256;
        int r = idx4 >> 4, c4 = idx4 & 15;
        *(float4*)&As[r][4*c4] = *(const float4*)&X[(size_t)(bm0+r)*64 + 4*c4];
    }
    float acc[4][4] = {};
    for (int ch=0; ch<64; ch+=16){
        __syncthreads();
        {
            int r = t >> 4, c4 = t & 15;
            *(float4*)&Bs[r][4*c4] = *(const float4*)&W[(ch+r)*192 + bn0 + 4*c4];
        }
        __syncthreads();
        #pragma unroll
        for (int k=0;k<16;k++){
            float a0=As[4*ty+0][ch+k], a1=As[4*ty+1][ch+k];
            float a2=As[4*ty+2][ch+k], a3=As[4*ty+3][ch+k];
            float4 bq = *(float4*)&Bs[k][4*tx];
            acc[0][0]+=a0*bq.x; acc[0][1]+=a0*bq.y; acc[0][2]+=a0*bq.z; acc[0][3]+=a0*bq.w;
            acc[1][0]+=a1*bq.x; acc[1][1]+=a1*bq.y; acc[1][2]+=a1*bq.z; acc[1][3]+=a1*bq.w;
            acc[2][0]+=a2*bq.x; acc[2][1]+=a2*bq.y; acc[2][2]+=a2*bq.z; acc[2][3]+=a2*bq.w;
            acc[3][0]+=a3*bq.x; acc[3][1]+=a3*bq.y; acc[3][2]+=a3*bq.z; acc[3][3]+=a3*bq.w;
        }
    }
    float* outp = (bn0 == 0) ? g_q : (bn0 == 64) ? g_k : g_v;
    #pragma unroll
    for (int i=0;i<4;i++){
        float4 o = make_float4(acc[i][0], acc[i][1], acc[i][2], acc[i][3]);
        *(float4*)&outp[(size_t)(bm0+4*ty+i)*64 + 4*tx] = o;
    }
}

/* ---------- prep: W2cat = [pw2 | pw2 @ aw1_bot], cvec ------------- */
__global__ __launch_bounds__(256) void prep_w2cat_kernel(
    const float* __restrict__ pw2, const float* __restrict__ aw1)
{
    int i = blockIdx.x*256 + threadIdx.x;     /* 64*320 */
    int r = i / 320, c = i % 320;
    if (c < 64){
        g_w2cat[i] = pw2[r*64 + c];
    } else {
        int cc = c - 64;
        float s = 0.f;
        #pragma unroll 8
        for (int d=0; d<64; d++)
            s += pw2[r*64 + d] * aw1[(64+d)*256 + cc];
        g_w2cat[i] = s;
    }
}

__global__ void prep_cvec_kernel(
    const float* __restrict__ aw1, const float* __restrict__ pb2,
    const float* __restrict__ ab1)
{
    int c = threadIdx.x;                      /* 256 */
    float s = ab1[c];
    #pragma unroll 8
    for (int d=0; d<64; d++)
        s += pb2[d] * aw1[(64+d)*256 + c];
    g_cvec[c] = s;
}

/* ----------- qW/kW: (16384,64) @ aw1_top(64,256), scalar ---------- */
__global__ __launch_bounds__(256) void gemm_qk_kernel(
    const float* __restrict__ X, const float* __restrict__ W,
    float* __restrict__ Y)
{
    __shared__ float As[64][68];
    __shared__ __align__(16) float Bs[16][64];
    int t = threadIdx.x, tx = t & 15, ty = t >> 4;
    int bm0 = blockIdx.x * 64;
    int bn0 = blockIdx.y * 64;
    #pragma unroll
    for (int i=0;i<4;i++){
        int idx4 = t + i*256;
        int r = idx4 >> 4, c4 = idx4 & 15;
        *(float4*)&As[r][4*c4] = *(const float4*)&X[(size_t)(bm0+r)*64 + 4*c4];
    }
    float acc[4][4] = {};
    for (int ch=0; ch<64; ch+=16){
        __syncthreads();
        {
            int r = t >> 4, c4 = t & 15;
            *(float4*)&Bs[r][4*c4] = *(const float4*)&W[(ch+r)*256 + bn0 + 4*c4];
        }
        __syncthreads();
        #pragma unroll
        for (int k=0;k<16;k++){
            float a0=As[4*ty+0][ch+k], a1=As[4*ty+1][ch+k];
            float a2=As[4*ty+2][ch+k], a3=As[4*ty+3][ch+k];
            float4 bq = *(float4*)&Bs[k][4*tx];
            acc[0][0]+=a0*bq.x; acc[0][1]+=a0*bq.y; acc[0][2]+=a0*bq.z; acc[0][3]+=a0*bq.w;
            acc[1][0]+=a1*bq.x; acc[1][1]+=a1*bq.y; acc[1][2]+=a1*bq.z; acc[1][3]+=a1*bq.w;
            acc[2][0]+=a2*bq.x; acc[2][1]+=a2*bq.y; acc[2][2]+=a2*bq.z; acc[2][3]+=a2*bq.w;
            acc[3][0]+=a3*bq.x; acc[3][1]+=a3*bq.y; acc[3][2]+=a3*bq.z; acc[3][3]+=a3*bq.w;
        }
    }
    #pragma unroll
    for (int i=0;i<4;i++){
        float4 o = make_float4(acc[i][0], acc[i][1], acc[i][2], acc[i][3]);
        *(float4*)&Y[(size_t)(bm0+4*ty+i)*256 + bn0 + 4*tx] = o;
    }
}

/* ==== mega-fused: h1 -> H@W2cat -> vnb,sim -> softmax -> output ==== */
/* dynamic smem layout (floats):
   Bs  [64*320]   81920 B
   As  [80*68]    21760 B
   Vs  [80*68]    21760 B
   Rd  [80*17]     5440 B
   Rel [80*4]      1280 B
   Sim [80]         320 B
   Jr  [80] (int)   320 B
   Pw  [256]       1024 B                                   */
#define SMF_B   0
#define SMF_A   (SMF_B + 64*320)
#define SMF_V   (SMF_A + RPB*68)
#define SMF_R   (SMF_V + RPB*68)
#define SMF_REL (SMF_R + RPB*17)
#define SMF_SIM (SMF_REL + RPB*4)
#define SMF_JR  (SMF_SIM + RPB)
#define SMF_PW  (SMF_JR + RPB)
#define SMF_TOT ((SMF_PW + 256) * 4)

__global__ __launch_bounds__(256) void fused_attn_kernel(
    const float* __restrict__ pts,
    const float* __restrict__ pw1, const float* __restrict__ pb1,
    const float* __restrict__ pb2, const float* __restrict__ aw2,
    const float* __restrict__ ab2, int outsel)
{
    extern __shared__ float sm[];
    float* Bs  = sm + SMF_B;
    float* As  = sm + SMF_A;
    float* Vs  = sm + SMF_V;
    float* Rd  = sm + SMF_R;
    float* Rel = sm + SMF_REL;
    float* Sim = sm + SMF_SIM;
    int*   Jr  = (int*)(sm + SMF_JR);
    float* Pw  = sm + SMF_PW;

    int t = threadIdx.x, tx = t & 15, ty = t >> 4;
    int q0 = blockIdx.x * QPB;
    int m0 = q0 * KNB;

    /* stage weights + per-row metadata */
    #pragma unroll
    for (int i=0;i<20;i++)
        ((float4*)Bs)[t + i*256] = ((const float4*)g_w2cat)[t + i*256];
    if (t < 64){
        Pw[t]       = pw1[t];
        Pw[64+t]    = pw1[64+t];
        Pw[128+t]   = pw1[128+t];
        Pw[192+t]   = pb1[t];
    }
    if (t < RPB){
        int gq = q0 + t/KNB;
        int b  = gq >> 13;
        int jr = (b<<13) + g_idx[m0 + t];
        Jr[t] = jr;
        Rel[t*4+0] = pts[gq*3+0] - pts[(size_t)jr*3+0];
        Rel[t*4+1] = pts[gq*3+1] - pts[(size_t)jr*3+1];
        Rel[t*4+2] = pts[gq*3+2] - pts[(size_t)jr*3+2];
    }
    __syncthreads();

    /* h1 = relu(rel_pos @ pw1 + pb1) into As */
    #pragma unroll
    for (int e = t; e < RPB*64; e += 256){
        int r = e >> 6, c = e & 63;
        float h = fmaf(Rel[r*4+0], Pw[c],
                  fmaf(Rel[r*4+1], Pw[64+c],
                  fmaf(Rel[r*4+2], Pw[128+c], Pw[192+c])));
        As[r*68 + c] = fmaxf(h, 0.f);
    }
    __syncthreads();

    /* per-thread rows */
    int jr_r[5], gq_r[5];
    const float* ap[5];
    #pragma unroll
    for (int i=0;i<5;i++){
        int r = ty*5 + i;
        jr_r[i] = Jr[r];
        gq_r[i] = q0 + r/KNB;
        ap[i] = &As[r*68];
    }

    float rsum[5] = {0.f,0.f,0.f,0.f,0.f};
    for (int nb=0; nb<5; nb++){
        float acc[5][4] = {};
        const float* bp = &Bs[nb*64 + 4*tx];
        #pragma unroll 8
        for (int k=0;k<64;k++){
            float4 bq = *(const float4*)&bp[k*320];
            #pragma unroll
            for (int i=0;i<5;i++){
                float a = ap[i][k];
                acc[i][0] += a*bq.x; acc[i][1] += a*bq.y;
                acc[i][2] += a*bq.z; acc[i][3] += a*bq.w;
            }
        }
        if (nb == 0){
            float4 pb = *(const float4*)&pb2[4*tx];
            #pragma unroll
            for (int i=0;i<5;i++){
                int r = ty*5 + i;
                float4 vv = *(const float4*)&g_v[(size_t)jr_r[i]*64 + 4*tx];
                float* vp = &Vs[r*68 + 4*tx];
                vp[0] = acc[i][0] + pb.x + vv.x;
                vp[1] = acc[i][1] + pb.y + vv.y;
                vp[2] = acc[i][2] + pb.z + vv.z;
                vp[3] = acc[i][3] + pb.w + vv.w;
            }
        } else {
            int cb = (nb-1)*64 + 4*tx;
            float4 cv  = *(const float4*)&g_cvec[cb];
            float4 a2v = *(const float4*)&aw2[cb];
            #pragma unroll
            for (int i=0;i<5;i++){
                float4 qv = *(const float4*)&g_qw[(size_t)gq_r[i]*256 + cb];
                float4 kv = *(const float4*)&g_kw[(size_t)jr_r[i]*256 + cb];
                float h0 = fmaxf(acc[i][0] + cv.x + qv.x - kv.x, 0.f);
                float h1 = fmaxf(acc[i][1] + cv.y + qv.y - kv.y, 0.f);
                float h2 = fmaxf(acc[i][2] + cv.z + qv.z - kv.z, 0.f);
                float h3 = fmaxf(acc[i][3] + cv.w + qv.w - kv.w, 0.f);
                rsum[i] += h0*a2v.x + h1*a2v.y + h2*a2v.z + h3*a2v.w;
            }
        }
    }
    #pragma unroll
    for (int i=0;i<5;i++) Rd[(ty*5+i)*17 + tx] = rsum[i];
    __syncthreads();
    if (t < RPB){
        float s = ab2[0];
        #pragma unroll
        for (int x=0;x<16;x++) s += Rd[t*17 + x];
        Sim[t] = s;
    }
    __syncthreads();

    /* softmax over K=20 + weighted sum of Vs -> output */
    if (t < 128){
        int w = t >> 5, lane = t & 31;        /* warp w = query q0+w */
        float s = (lane < KNB) ? Sim[w*KNB + lane] : -CUDART_INF_F;
        float m = s;
        #pragma unroll
        for (int off=16; off; off>>=1) m = fmaxf(m, __shfl_xor_sync(0xffffffffu, m, off));
        float e = (lane < KNB) ? expf(s - m) : 0.f;
        float sum = e;
        #pragma unroll
        for (int off=16; off; off>>=1) sum += __shfl_xor_sync(0xffffffffu, sum, off);
        float attn = e / sum;
        float acc0 = 0.f, acc1 = 0.f;
        #pragma unroll
        for (int kk=0; kk<KNB; kk++){
            float a = __shfl_sync(0xffffffffu, attn, kk);
            const float* vb = &Vs[(w*KNB + kk)*68];
            acc0 += a * vb[lane];
            acc1 += a * vb[32 + lane];
        }
        float* xout = outsel ? g_xb : g_xa;
        xout[(size_t)(q0+w)*64 + lane]      = acc0;
        xout[(size_t)(q0+w)*64 + 32 + lane] = acc1;
    }
}

/* ---------------- global max pool (partial) ----------------------- */
__global__ void pool_kernel(void)
{
    int b = blockIdx.x, ch = blockIdx.y, c = threadIdx.x;
    float m = -CUDART_INF_F;
    int base = b*NPTS + ch*128;
    #pragma unroll 4
    for (int n=0;n<128;n++) m = fmaxf(m, g_xa[(size_t)(base+n)*64 + c]);
    g_part[(b*64 + ch)*64 + c] = m;
}

/* ---------------- head ------------------------------------------- */
__global__ void head_kernel(
    const float* __restrict__ fc1w, const float* __restrict__ fc1b,
    const float* __restrict__ fc3w, const float* __restrict__ fc3b,
    float* __restrict__ out)
{
    __shared__ float sp[BATCH*64];
    __shared__ float sh[BATCH*32];
    int t = threadIdx.x;
    if (t < 128){
        int b = t >> 6, c = t & 63;
        float m = -CUDART_INF_F;
        for (int ch=0; ch<64; ch++) m = fmaxf(m, g_part[(b*64+ch)*64 + c]);
        sp[b*64 + c] = m;
    }
    __syncthreads();
    if (t < 64){
        int b = t >> 5, cc = t & 31;
        float s = fc1b[cc];
        for (int c=0;c<64;c++) s += sp[b*64+c] * fc1w[c*32 + cc];
        sh[b*32 + cc] = fmaxf(s, 0.f);
    }
    __syncthreads();
    if (t < 6){
        int b = t / 3, o = t % 3;
        float s = fc3b[o];
        for (int cc=0;cc<32;cc++) s += sh[b*32+cc] * fc3w[cc*3 + o];
        out[b*3 + o] = s;
    }
}

/* ------------------------------ launch ---------------------------- */
static void run_layer(const float* pts, const float* const* W, int xsel)
{
    /* W: qkv, pw1, pb1, pw2, pb2, aw1, ab1, aw2, ab2 */
    prep_w2cat_kernel<<<64*320/256, 256>>>(W[3], W[5]);
    prep_cvec_kernel<<<1, 256>>>(W[5], W[4], W[6]);
    qkv_kernel<<<dim3(BN_TOT/64, 3), 256>>>(xsel, W[0]);
    gemm_qk_kernel<<<dim3(BN_TOT/64, 4), 256>>>(g_q, W[5], g_qw);
    gemm_qk_kernel<<<dim3(BN_TOT/64, 4), 256>>>(g_k, W[5], g_kw);
    fused_attn_kernel<<<BN_TOT/QPB, 256, SMF_TOT>>>(
        pts, W[1], W[2], W[4], W[7], W[8], xsel == 0 ? 1 : 0);
}

extern "C" void kernel_launch(void* const* d_in, const int* in_sizes, int n_in,
                              void* d_out, int out_size)
{
    (void)in_sizes; (void)n_in; (void)out_size;
    const float* pts = (const float*)d_in[0];
    float* out = (float*)d_out;

    cudaFuncSetAttribute(fused_attn_kernel,
                         cudaFuncAttributeMaxDynamicSharedMemorySize, SMF_TOT);

    embed_kernel<<<BN_TOT*64/256, 256>>>(pts, (const float*)d_in[1], (const float*)d_in[2]);
    knn_kernel<<<BN_TOT/32, 256>>>(pts);

    const float* W1[9] = {
        (const float*)d_in[3], (const float*)d_in[4], (const float*)d_in[5],
        (const float*)d_in[6], (const float*)d_in[7], (const float*)d_in[8],
        (const float*)d_in[9], (const float*)d_in[10], (const float*)d_in[11]};
    const float* W2[9] = {
        (const float*)d_in[12], (const float*)d_in[13], (const float*)d_in[14],
        (const float*)d_in[15], (const float*)d_in[16], (const float*)d_in[17],
        (const float*)d_in[18], (const float*)d_in[19], (const float*)d_in[20]};

    run_layer(pts, W1, 0);   /* reads g_xa, writes g_xb */
    run_layer(pts, W2, 1);   /* reads g_xb, writes g_xa */

    pool_kernel<<<dim3(BATCH, 64), 64>>>();
    head_kernel<<<1, 128>>>((const float*)d_in[21], (const float*)d_in[22],
                            (const float*)d_in[23], (const float*)d_in[24], out);
}

// round 4
// speedup vs baseline: 1.1662x; 1.1229x over previous
#include <cuda_runtime.h>
#include <math_constants.h>

#define NPTS   8192
#define BATCH  2
#define BN_TOT (BATCH*NPTS)      /* 16384 */
#define KNB    20
#define M2     (BN_TOT*KNB)      /* 327680 */
#define QPB    4                 /* queries per fused block */
#define RPB    (QPB*KNB)         /* 80 pair-rows per block */

/* ------------------------- device scratch ------------------------- */
__device__ float g_xa[BN_TOT*64];
__device__ float g_xb[BN_TOT*64];
__device__ float g_q [BN_TOT*64];
__device__ float g_k [BN_TOT*64];
__device__ float g_v [BN_TOT*64];
__device__ int   g_idx[M2];
__device__ float g_qw[BN_TOT*256];
__device__ float g_kw[BN_TOT*256];
__device__ __align__(16) float g_w2cat[64*320];
__device__ __align__(16) float g_cvec[256];
__device__ float g_part[BATCH*64*64];

/* ------------------------- embed: relu(points @ conv_w + b) -------- */
__global__ __launch_bounds__(256) void embed_kernel(
    const float* __restrict__ pts, const float* __restrict__ w,
    const float* __restrict__ b)
{
    int i = blockIdx.x*256 + threadIdx.x;
    int row = i >> 6, c = i & 63;
    float x = pts[row*3+0], y = pts[row*3+1], z = pts[row*3+2];
    float s = x*w[c] + y*w[64+c] + z*w[128+c] + b[c];
    g_xa[i] = fmaxf(s, 0.f);
}

/* ------------------------- KNN ------------------------------------ */
__device__ __forceinline__ bool kless(float d1,int i1,float d2,int i2){
    return d1 < d2 || (d1 == d2 && i1 < i2);
}

__global__ __launch_bounds__(256) void knn_kernel(const float* __restrict__ pts)
{
    const int SPL=8, QPBK=32, TILE=256;
    __shared__ float4 sp[TILE];
    __shared__ float  sd[QPBK][SPL*KNB];
    __shared__ int    si[QPBK][SPL*KNB];
    int t = threadIdx.x;
    int qi = t >> 3, lane = t & 7;
    int gq = blockIdx.x*QPBK + qi;
    int b  = gq >> 13;
    const float* qp = pts + gq*3;
    float qx=qp[0], qy=qp[1], qz=qp[2];
    float bd[KNB]; int bi[KNB];
    #pragma unroll
    for (int p=0;p<KNB;p++){ bd[p]=CUDART_INF_F; bi[p]=0x7fffffff; }

    for (int t0=0; t0<NPTS; t0+=TILE){
        __syncthreads();
        {
            const float* pp = pts + (size_t)(b*NPTS + t0 + t)*3;
            sp[t] = make_float4(pp[0], pp[1], pp[2], 0.f);
        }
        __syncthreads();
        for (int c=lane; c<TILE; c+=SPL){
            float4 p = sp[c];
            float dx=qx-p.x, dy=qy-p.y, dz=qz-p.z;
            float d2 = dx*dx + dy*dy + dz*dz;
            int id = t0 + c;
            if (kless(d2, id, bd[KNB-1], bi[KNB-1])){
                float nd=d2; int ni=id; bool done=false;
                #pragma unroll
                for (int p=KNB-1; p>=1; --p){
                    bool sh = kless(nd, ni, bd[p-1], bi[p-1]);
                    if (!done){
                        bd[p] = sh ? bd[p-1] : nd;
                        bi[p] = sh ? bi[p-1] : ni;
                    }
                    done = done || !sh;
                }
                if (!done){ bd[0]=nd; bi[0]=ni; }
            }
        }
    }
    #pragma unroll
    for (int p=0;p<KNB;p++){ sd[qi][lane*KNB+p]=bd[p]; si[qi][lane*KNB+p]=bi[p]; }
    __syncthreads();
    if (lane == 0){
        int ptr[SPL];
        #pragma unroll
        for (int s=0;s<SPL;s++) ptr[s]=0;
        for (int r=0;r<KNB;r++){
            float best=CUDART_INF_F; int besti=0x7fffffff; int bs=0;
            #pragma unroll
            for (int s=0;s<SPL;s++){
                if (ptr[s] < KNB){
                    float d = sd[qi][s*KNB+ptr[s]];
                    int  ii = si[qi][s*KNB+ptr[s]];
                    if (kless(d, ii, best, besti)){ best=d; besti=ii; bs=s; }
                }
            }
            ptr[bs]++;
            g_idx[gq*KNB + r] = besti;
        }
    }
}

/* ------------------------- qkv GEMM (M=16384, K=64, N=192) -------- */
__global__ __launch_bounds__(256) void qkv_kernel(int xsel, const float* __restrict__ W)
{
    __shared__ float As[64][68];
    __shared__ __align__(16) float Bs[16][64];
    const float* X = xsel ? g_xb : g_xa;
    int t = threadIdx.x, tx = t & 15, ty = t >> 4;
    int bm0 = blockIdx.x * 64;
    int bn0 = blockIdx.y * 64;
    #pragma unroll
    for (int i=0;i<4;i++){
        int idx4 = t + i*256;
        int r = idx4 >> 4, c4 = idx4 & 15;
        *(float4*)&As[r][4*c4] = *(const float4*)&X[(size_t)(bm0+r)*64 + 4*c4];
    }
    float acc[4][4] = {};
    for (int ch=0; ch<64; ch+=16){
        __syncthreads();
        {
            int r = t >> 4, c4 = t & 15;
            *(float4*)&Bs[r][4*c4] = *(const float4*)&W[(ch+r)*192 + bn0 + 4*c4];
        }
        __syncthreads();
        #pragma unroll
        for (int k=0;k<16;k++){
            float a0=As[4*ty+0][ch+k], a1=As[4*ty+1][ch+k];
            float a2=As[4*ty+2][ch+k], a3=As[4*ty+3][ch+k];
            float4 bq = *(float4*)&Bs[k][4*tx];
            acc[0][0]+=a0*bq.x; acc[0][1]+=a0*bq.y; acc[0][2]+=a0*bq.z; acc[0][3]+=a0*bq.w;
            acc[1][0]+=a1*bq.x; acc[1][1]+=a1*bq.y; acc[1][2]+=a1*bq.z; acc[1][3]+=a1*bq.w;
            acc[2][0]+=a2*bq.x; acc[2][1]+=a2*bq.y; acc[2][2]+=a2*bq.z; acc[2][3]+=a2*bq.w;
            acc[3][0]+=a3*bq.x; acc[3][1]+=a3*bq.y; acc[3][2]+=a3*bq.z; acc[3][3]+=a3*bq.w;
        }
    }
    float* outp = (bn0 == 0) ? g_q : (bn0 == 64) ? g_k : g_v;
    #pragma unroll
    for (int i=0;i<4;i++){
        float4 o = make_float4(acc[i][0], acc[i][1], acc[i][2], acc[i][3]);
        *(float4*)&outp[(size_t)(bm0+4*ty+i)*64 + 4*tx] = o;
    }
}

/* ---- prep: W2cat = [pw2 | pw2 @ aw1_bot], cvec (merged) ---------- */
__global__ __launch_bounds__(256) void prep_kernel(
    const float* __restrict__ pw2, const float* __restrict__ aw1,
    const float* __restrict__ pb2, const float* __restrict__ ab1)
{
    int blk = blockIdx.x;
    int t = threadIdx.x;
    if (blk < 80){
        int i = blk*256 + t;                  /* 64*320 */
        int r = i / 320, c = i % 320;
        if (c < 64){
            g_w2cat[i] = pw2[r*64 + c];
        } else {
            int cc = c - 64;
            float s = 0.f;
            #pragma unroll 8
            for (int d=0; d<64; d++)
                s += pw2[r*64 + d] * aw1[(64+d)*256 + cc];
            g_w2cat[i] = s;
        }
    } else {
        float s = ab1[t];
        #pragma unroll 8
        for (int d=0; d<64; d++)
            s += pb2[d] * aw1[(64+d)*256 + t];
        g_cvec[t] = s;
    }
}

/* ----------- qW/kW: (16384,64) @ aw1_top(64,256), scalar ---------- */
__global__ __launch_bounds__(256) void gemm_qk_kernel(
    const float* __restrict__ X, const float* __restrict__ W,
    float* __restrict__ Y)
{
    __shared__ float As[64][68];
    __shared__ __align__(16) float Bs[16][64];
    int t = threadIdx.x, tx = t & 15, ty = t >> 4;
    int bm0 = blockIdx.x * 64;
    int bn0 = blockIdx.y * 64;
    #pragma unroll
    for (int i=0;i<4;i++){
        int idx4 = t + i*256;
        int r = idx4 >> 4, c4 = idx4 & 15;
        *(float4*)&As[r][4*c4] = *(const float4*)&X[(size_t)(bm0+r)*64 + 4*c4];
    }
    float acc[4][4] = {};
    for (int ch=0; ch<64; ch+=16){
        __syncthreads();
        {
            int r = t >> 4, c4 = t & 15;
            *(float4*)&Bs[r][4*c4] = *(const float4*)&W[(ch+r)*256 + bn0 + 4*c4];
        }
        __syncthreads();
        #pragma unroll
        for (int k=0;k<16;k++){
            float a0=As[4*ty+0][ch+k], a1=As[4*ty+1][ch+k];
            float a2=As[4*ty+2][ch+k], a3=As[4*ty+3][ch+k];
            float4 bq = *(float4*)&Bs[k][4*tx];
            acc[0][0]+=a0*bq.x; acc[0][1]+=a0*bq.y; acc[0][2]+=a0*bq.z; acc[0][3]+=a0*bq.w;
            acc[1][0]+=a1*bq.x; acc[1][1]+=a1*bq.y; acc[1][2]+=a1*bq.z; acc[1][3]+=a1*bq.w;
            acc[2][0]+=a2*bq.x; acc[2][1]+=a2*bq.y; acc[2][2]+=a2*bq.z; acc[2][3]+=a2*bq.w;
            acc[3][0]+=a3*bq.x; acc[3][1]+=a3*bq.y; acc[3][2]+=a3*bq.z; acc[3][3]+=a3*bq.w;
        }
    }
    #pragma unroll
    for (int i=0;i<4;i++){
        float4 o = make_float4(acc[i][0], acc[i][1], acc[i][2], acc[i][3]);
        *(float4*)&Y[(size_t)(bm0+4*ty+i)*256 + bn0 + 4*tx] = o;
    }
}

/* ==== mega-fused: h1 -> H@W2cat -> vnb,sim -> softmax -> output ====
   chunked B staging: 56 KB smem -> 4 CTAs/SM -> 32 warps/SM        */
#define SMF_B   0
#define SMF_A   (SMF_B + 16*68)
#define SMF_V   (SMF_A + RPB*68)
#define SMF_R   (SMF_V + RPB*68)
#define SMF_REL (SMF_R + RPB*17)
#define SMF_SIM (SMF_REL + RPB*4)
#define SMF_JR  (SMF_SIM + RPB)
#define SMF_PW  (SMF_JR + RPB)
#define SMF_TOT ((SMF_PW + 256) * 4)

__global__ __launch_bounds__(256) void fused_attn_kernel(
    const float* __restrict__ pts,
    const float* __restrict__ pw1, const float* __restrict__ pb1,
    const float* __restrict__ pb2, const float* __restrict__ aw2,
    const float* __restrict__ ab2, int outsel)
{
    extern __shared__ float sm[];
    float* Bs  = sm + SMF_B;
    float* As  = sm + SMF_A;
    float* Vs  = sm + SMF_V;
    float* Rd  = sm + SMF_R;
    float* Rel = sm + SMF_REL;
    float* Sim = sm + SMF_SIM;
    int*   Jr  = (int*)(sm + SMF_JR);
    float* Pw  = sm + SMF_PW;

    int t = threadIdx.x, tx = t & 15, ty = t >> 4;
    int q0 = blockIdx.x * QPB;
    int m0 = q0 * KNB;

    if (t < 64){
        Pw[t]     = pw1[t];
        Pw[64+t]  = pw1[64+t];
        Pw[128+t] = pw1[128+t];
        Pw[192+t] = pb1[t];
    }
    if (t < RPB){
        int gq = q0 + t/KNB;
        int b  = gq >> 13;
        int jr = (b<<13) + g_idx[m0 + t];
        Jr[t] = jr;
        Rel[t*4+0] = pts[gq*3+0] - pts[(size_t)jr*3+0];
        Rel[t*4+1] = pts[gq*3+1] - pts[(size_t)jr*3+1];
        Rel[t*4+2] = pts[gq*3+2] - pts[(size_t)jr*3+2];
    }
    __syncthreads();

    /* h1 = relu(rel_pos @ pw1 + pb1) into As */
    #pragma unroll
    for (int e = t; e < RPB*64; e += 256){
        int r = e >> 6, c = e & 63;
        float h = fmaf(Rel[r*4+0], Pw[c],
                  fmaf(Rel[r*4+1], Pw[64+c],
                  fmaf(Rel[r*4+2], Pw[128+c], Pw[192+c])));
        As[r*68 + c] = fmaxf(h, 0.f);
    }

    int jr_r[5], gq_r[5];
    #pragma unroll
    for (int i=0;i<5;i++){
        int r = ty*5 + i;
        jr_r[i] = Jr[r];
        gq_r[i] = q0 + r/KNB;
    }

    float rsum[5] = {0.f,0.f,0.f,0.f,0.f};
    for (int nb=0; nb<5; nb++){
        float acc[5][4] = {};
        for (int ch=0; ch<64; ch+=16){
            __syncthreads();
            {
                int r = t >> 4, c4 = t & 15;
                *(float4*)&Bs[r*68 + 4*c4] =
                    *(const float4*)&g_w2cat[(ch+r)*320 + nb*64 + 4*c4];
            }
            __syncthreads();
            #pragma unroll
            for (int k=0;k<16;k++){
                float4 bq = *(const float4*)&Bs[k*68 + 4*tx];
                #pragma unroll
                for (int i=0;i<5;i++){
                    float a = As[(ty*5+i)*68 + ch + k];
                    acc[i][0] += a*bq.x; acc[i][1] += a*bq.y;
                    acc[i][2] += a*bq.z; acc[i][3] += a*bq.w;
                }
            }
        }
        if (nb == 0){
            float4 pb = *(const float4*)&pb2[4*tx];
            #pragma unroll
            for (int i=0;i<5;i++){
                int r = ty*5 + i;
                float4 vv = *(const float4*)&g_v[(size_t)jr_r[i]*64 + 4*tx];
                float* vp = &Vs[r*68 + 4*tx];
                vp[0] = acc[i][0] + pb.x + vv.x;
                vp[1] = acc[i][1] + pb.y + vv.y;
                vp[2] = acc[i][2] + pb.z + vv.z;
                vp[3] = acc[i][3] + pb.w + vv.w;
            }
        } else {
            int cb = (nb-1)*64 + 4*tx;
            float4 cv  = *(const float4*)&g_cvec[cb];
            float4 a2v = *(const float4*)&aw2[cb];
            #pragma unroll
            for (int i=0;i<5;i++){
                float4 qv = *(const float4*)&g_qw[(size_t)gq_r[i]*256 + cb];
                float4 kv = *(const float4*)&g_kw[(size_t)jr_r[i]*256 + cb];
                float h0 = fmaxf(acc[i][0] + cv.x + qv.x - kv.x, 0.f);
                float h1 = fmaxf(acc[i][1] + cv.y + qv.y - kv.y, 0.f);
                float h2 = fmaxf(acc[i][2] + cv.z + qv.z - kv.z, 0.f);
                float h3 = fmaxf(acc[i][3] + cv.w + qv.w - kv.w, 0.f);
                rsum[i] += h0*a2v.x + h1*a2v.y + h2*a2v.z + h3*a2v.w;
            }
        }
    }
    #pragma unroll
    for (int i=0;i<5;i++) Rd[(ty*5+i)*17 + tx] = rsum[i];
    __syncthreads();
    if (t < RPB){
        float s = ab2[0];
        #pragma unroll
        for (int x=0;x<16;x++) s += Rd[t*17 + x];
        Sim[t] = s;
    }
    __syncthreads();

    /* softmax over K=20 + weighted sum of Vs -> output */
    if (t < 128){
        int w = t >> 5, lane = t & 31;
        float s = (lane < KNB) ? Sim[w*KNB + lane] : -CUDART_INF_F;
        float m = s;
        #pragma unroll
        for (int off=16; off; off>>=1) m = fmaxf(m, __shfl_xor_sync(0xffffffffu, m, off));
        float e = (lane < KNB) ? expf(s - m) : 0.f;
        float sum = e;
        #pragma unroll
        for (int off=16; off; off>>=1) sum += __shfl_xor_sync(0xffffffffu, sum, off);
        float attn = e / sum;
        float acc0 = 0.f, acc1 = 0.f;
        #pragma unroll
        for (int kk=0; kk<KNB; kk++){
            float a = __shfl_sync(0xffffffffu, attn, kk);
            const float* vb = &Vs[(w*KNB + kk)*68];
            acc0 += a * vb[lane];
            acc1 += a * vb[32 + lane];
        }
        float* xout = outsel ? g_xb : g_xa;
        xout[(size_t)(q0+w)*64 + lane]      = acc0;
        xout[(size_t)(q0+w)*64 + 32 + lane] = acc1;
    }
}

/* ---------------- global max pool (partial) ----------------------- */
__global__ void pool_kernel(void)
{
    int b = blockIdx.x, ch = blockIdx.y, c = threadIdx.x;
    float m = -CUDART_INF_F;
    int base = b*NPTS + ch*128;
    #pragma unroll 4
    for (int n=0;n<128;n++) m = fmaxf(m, g_xa[(size_t)(base+n)*64 + c]);
    g_part[(b*64 + ch)*64 + c] = m;
}

/* ---------------- head ------------------------------------------- */
__global__ void head_kernel(
    const float* __restrict__ fc1w, const float* __restrict__ fc1b,
    const float* __restrict__ fc3w, const float* __restrict__ fc3b,
    float* __restrict__ out)
{
    __shared__ float sp[BATCH*64];
    __shared__ float sh[BATCH*32];
    int t = threadIdx.x;
    if (t < 128){
        int b = t >> 6, c = t & 63;
        float m = -CUDART_INF_F;
        for (int ch=0; ch<64; ch++) m = fmaxf(m, g_part[(b*64+ch)*64 + c]);
        sp[b*64 + c] = m;
    }
    __syncthreads();
    if (t < 64){
        int b = t >> 5, cc = t & 31;
        float s = fc1b[cc];
        for (int c=0;c<64;c++) s += sp[b*64+c] * fc1w[c*32 + cc];
        sh[b*32 + cc] = fmaxf(s, 0.f);
    }
    __syncthreads();
    if (t < 6){
        int b = t / 3, o = t % 3;
        float s = fc3b[o];
        for (int cc=0;cc<32;cc++) s += sh[b*32+cc] * fc3w[cc*3 + o];
        out[b*3 + o] = s;
    }
}

/* ------------------------------ launch ---------------------------- */
static void run_layer(const float* pts, const float* const* W, int xsel)
{
    /* W: qkv, pw1, pb1, pw2, pb2, aw1, ab1, aw2, ab2 */
    prep_kernel<<<81, 256>>>(W[3], W[5], W[4], W[6]);
    qkv_kernel<<<dim3(BN_TOT/64, 3), 256>>>(xsel, W[0]);
    gemm_qk_kernel<<<dim3(BN_TOT/64, 4), 256>>>(g_q, W[5], g_qw);
    gemm_qk_kernel<<<dim3(BN_TOT/64, 4), 256>>>(g_k, W[5], g_kw);
    fused_attn_kernel<<<BN_TOT/QPB, 256, SMF_TOT>>>(
        pts, W[1], W[2], W[4], W[7], W[8], xsel == 0 ? 1 : 0);
}

extern "C" void kernel_launch(void* const* d_in, const int* in_sizes, int n_in,
                              void* d_out, int out_size)
{
    (void)in_sizes; (void)n_in; (void)out_size;
    const float* pts = (const float*)d_in[0];
    float* out = (float*)d_out;

    cudaFuncSetAttribute(fused_attn_kernel,
                         cudaFuncAttributeMaxDynamicSharedMemorySize, SMF_TOT);

    embed_kernel<<<BN_TOT*64/256, 256>>>(pts, (const float*)d_in[1], (const float*)d_in[2]);
    knn_kernel<<<BN_TOT/32, 256>>>(pts);

    const float* W1[9] = {
        (const float*)d_in[3], (const float*)d_in[4], (const float*)d_in[5],
        (const float*)d_in[6], (const float*)d_in[7], (const float*)d_in[8],
        (const float*)d_in[9], (const float*)d_in[10], (const float*)d_in[11]};
    const float* W2[9] = {
        (const float*)d_in[12], (const float*)d_in[13], (const float*)d_in[14],
        (const float*)d_in[15], (const float*)d_in[16], (const float*)d_in[17],
        (const float*)d_in[18], (const float*)d_in[19], (const float*)d_in[20]};

    run_layer(pts, W1, 0);   /* reads g_xa, writes g_xb */
    run_layer(pts, W2, 1);   /* reads g_xb, writes g_xa */

    pool_kernel<<<dim3(BATCH, 64), 64>>>();
    head_kernel<<<1, 128>>>((const float*)d_in[21], (const float*)d_in[22],
                            (const float*)d_in[23], (const float*)d_in[24], out);
}

// round 5
// speedup vs baseline: 1.4635x; 1.2548x over previous
#include <cuda_runtime.h>
#include <math_constants.h>

#define NPTS   8192
#define BATCH  2
#define BN_TOT (BATCH*NPTS)      /* 16384 */
#define KNB    20
#define M2     (BN_TOT*KNB)      /* 327680 */
#define QPB    4                 /* queries per fused block */
#define RPB    (QPB*KNB)         /* 80 pair-rows per block */

typedef unsigned long long ull;

/* ------------------------- device scratch ------------------------- */
__device__ float g_xa[BN_TOT*64];
__device__ float g_xb[BN_TOT*64];
__device__ float g_q [BN_TOT*64];
__device__ float g_k [BN_TOT*64];
__device__ float g_v [BN_TOT*64];
__device__ int   g_idx[M2];
__device__ float g_qw[BN_TOT*256];
__device__ float g_kw[BN_TOT*256];
__device__ __align__(16) float g_w2cat[64*320];
__device__ __align__(16) float g_cvec[256];
__device__ float g_part[BATCH*64*64];

/* ------------------------- embed: relu(points @ conv_w + b) -------- */
__global__ __launch_bounds__(256) void embed_kernel(
    const float* __restrict__ pts, const float* __restrict__ w,
    const float* __restrict__ b)
{
    int i = blockIdx.x*256 + threadIdx.x;
    int row = i >> 6, c = i & 63;
    float x = pts[row*3+0], y = pts[row*3+1], z = pts[row*3+2];
    float s = x*w[c] + y*w[64+c] + z*w[128+c] + b[c];
    g_xa[i] = fmaxf(s, 0.f);
}

/* ------------------------- KNN: lane-per-query, u64 keys ----------- */
/* dynamic smem: sp 512 float4 (8192 B) | buf 256*17 u64 (34816 B)
   merge phase reuses the whole region as mrg 256*21 u64 (43008 B)   */
#define KNN_SMEM 43008

__global__ __launch_bounds__(256) void knn_kernel(const float* __restrict__ pts)
{
    extern __shared__ ull ksm[];
    float4* sp = (float4*)ksm;          /* [512] */
    ull* buf = ksm + 1024;              /* [256*17], 8192 B offset */
    ull* mrg = ksm;                     /* [256*21], reused at end */

    int t = threadIdx.x;
    int s = t >> 7;                     /* split 0/1 over candidate halves */
    int qi = t & 127;
    int gq = blockIdx.x*128 + qi;
    int b  = gq >> 13;
    float qx = pts[gq*3+0], qy = pts[gq*3+1], qz = pts[gq*3+2];
    const float* cloud = pts + (size_t)b*NPTS*3;

    ull best[KNB];
    #pragma unroll
    for (int p=0;p<KNB;p++) best[p] = 0xFFFFFFFFFFFFFFFFULL;
    int cnt = 0;

    for (int t0 = 0; t0 < 4096; t0 += 256){
        __syncthreads();
        {
            int j0 = t0 + t;
            int j1 = 4096 + j0;
            sp[t]     = make_float4(cloud[j0*3], cloud[j0*3+1], cloud[j0*3+2], 0.f);
            sp[256+t] = make_float4(cloud[j1*3], cloud[j1*3+1], cloud[j1*3+2], 0.f);
        }
        __syncthreads();
        int base = s*256, id0 = s*4096 + t0;
        for (int c = 0; c < 256; c++){
            float4 p = sp[base + c];
            float dx = qx-p.x, dy = qy-p.y, dz = qz-p.z;
            float d2 = fmaf(dx,dx,fmaf(dy,dy,dz*dz));
            ull key;
            asm("mov.b64 %0, {%1, %2};" : "=l"(key)
                : "r"(id0 + c), "r"(__float_as_uint(d2)));
            if (key < best[KNB-1]) buf[t*17 + cnt++] = key;
            if (__any_sync(0xffffffffu, cnt >= 15)){
                int n = cnt;
                for (int j = 0; j < n; j++){
                    ull k2 = buf[t*17 + j];
                    if (k2 < best[KNB-1]){
                        best[KNB-1] = k2;
                        #pragma unroll
                        for (int p = KNB-1; p >= 1; --p){
                            ull a = best[p-1], bb = best[p];
                            bool sw = bb < a;
                            best[p-1] = sw ? bb : a;
                            best[p]   = sw ? a : bb;
                        }
                    }
                }
                cnt = 0;
            }
        }
        {   /* tile-end flush */
            int n = cnt;
            for (int j = 0; j < n; j++){
                ull k2 = buf[t*17 + j];
                if (k2 < best[KNB-1]){
                    best[KNB-1] = k2;
                    #pragma unroll
                    for (int p = KNB-1; p >= 1; --p){
                        ull a = best[p-1], bb = best[p];
                        bool sw = bb < a;
                        best[p-1] = sw ? bb : a;
                        best[p]   = sw ? a : bb;
                    }
                }
            }
            cnt = 0;
        }
    }

    __syncthreads();
    #pragma unroll
    for (int p=0;p<KNB;p++) mrg[t*21+p] = best[p];
    __syncthreads();
    if (t < 128){
        int pa=0, pb=0;
        #pragma unroll 1
        for (int r=0;r<KNB;r++){
            ull a  = mrg[t*21 + ((pa < KNB) ? pa : (KNB-1))];
            ull c2 = mrg[(t+128)*21 + ((pb < KNB) ? pb : (KNB-1))];
            bool ta = (pb >= KNB) || ((pa < KNB) && (a < c2));
            g_idx[gq*KNB + r] = (int)(unsigned)((ta ? a : c2) & 0xFFFFFFFFULL);
            if (ta) pa++; else pb++;
        }
    }
}

/* ------------------------- qkv GEMM (M=16384, K=64, N=192) -------- */
__global__ __launch_bounds__(256) void qkv_kernel(int xsel, const float* __restrict__ W)
{
    __shared__ float As[64][68];
    __shared__ __align__(16) float Bs[16][64];
    const float* X = xsel ? g_xb : g_xa;
    int t = threadIdx.x, tx = t & 15, ty = t >> 4;
    int bm0 = blockIdx.x * 64;
    int bn0 = blockIdx.y * 64;
    #pragma unroll
    for (int i=0;i<4;i++){
        int idx4 = t + i*256;
        int r = idx4 >> 4, c4 = idx4 & 15;
        *(float4*)&As[r][4*c4] = *(const float4*)&X[(size_t)(bm0+r)*64 + 4*c4];
    }
    float acc[4][4] = {};
    for (int ch=0; ch<64; ch+=16){
        __syncthreads();
        {
            int r = t >> 4, c4 = t & 15;
            *(float4*)&Bs[r][4*c4] = *(const float4*)&W[(ch+r)*192 + bn0 + 4*c4];
        }
        __syncthreads();
        #pragma unroll
        for (int k=0;k<16;k++){
            float a0=As[4*ty+0][ch+k], a1=As[4*ty+1][ch+k];
            float a2=As[4*ty+2][ch+k], a3=As[4*ty+3][ch+k];
            float4 bq = *(float4*)&Bs[k][4*tx];
            acc[0][0]+=a0*bq.x; acc[0][1]+=a0*bq.y; acc[0][2]+=a0*bq.z; acc[0][3]+=a0*bq.w;
            acc[1][0]+=a1*bq.x; acc[1][1]+=a1*bq.y; acc[1][2]+=a1*bq.z; acc[1][3]+=a1*bq.w;
            acc[2][0]+=a2*bq.x; acc[2][1]+=a2*bq.y; acc[2][2]+=a2*bq.z; acc[2][3]+=a2*bq.w;
            acc[3][0]+=a3*bq.x; acc[3][1]+=a3*bq.y; acc[3][2]+=a3*bq.z; acc[3][3]+=a3*bq.w;
        }
    }
    float* outp = (bn0 == 0) ? g_q : (bn0 == 64) ? g_k : g_v;
    #pragma unroll
    for (int i=0;i<4;i++){
        float4 o = make_float4(acc[i][0], acc[i][1], acc[i][2], acc[i][3]);
        *(float4*)&outp[(size_t)(bm0+4*ty+i)*64 + 4*tx] = o;
    }
}

/* ---- prep: W2cat = [pw2 | pw2 @ aw1_bot], cvec (merged) ---------- */
__global__ __launch_bounds__(256) void prep_kernel(
    const float* __restrict__ pw2, const float* __restrict__ aw1,
    const float* __restrict__ pb2, const float* __restrict__ ab1)
{
    int blk = blockIdx.x;
    int t = threadIdx.x;
    if (blk < 80){
        int i = blk*256 + t;                  /* 64*320 */
        int r = i / 320, c = i % 320;
        if (c < 64){
            g_w2cat[i] = pw2[r*64 + c];
        } else {
            int cc = c - 64;
            float s = 0.f;
            #pragma unroll 8
            for (int d=0; d<64; d++)
                s += pw2[r*64 + d] * aw1[(64+d)*256 + cc];
            g_w2cat[i] = s;
        }
    } else {
        float s = ab1[t];
        #pragma unroll 8
        for (int d=0; d<64; d++)
            s += pb2[d] * aw1[(64+d)*256 + t];
        g_cvec[t] = s;
    }
}

/* ----------- qW/kW: (16384,64) @ aw1_top(64,256), scalar ---------- */
__global__ __launch_bounds__(256) void gemm_qk_kernel(
    const float* __restrict__ X, const float* __restrict__ W,
    float* __restrict__ Y)
{
    __shared__ float As[64][68];
    __shared__ __align__(16) float Bs[16][64];
    int t = threadIdx.x, tx = t & 15, ty = t >> 4;
    int bm0 = blockIdx.x * 64;
    int bn0 = blockIdx.y * 64;
    #pragma unroll
    for (int i=0;i<4;i++){
        int idx4 = t + i*256;
        int r = idx4 >> 4, c4 = idx4 & 15;
        *(float4*)&As[r][4*c4] = *(const float4*)&X[(size_t)(bm0+r)*64 + 4*c4];
    }
    float acc[4][4] = {};
    for (int ch=0; ch<64; ch+=16){
        __syncthreads();
        {
            int r = t >> 4, c4 = t & 15;
            *(float4*)&Bs[r][4*c4] = *(const float4*)&W[(ch+r)*256 + bn0 + 4*c4];
        }
        __syncthreads();
        #pragma unroll
        for (int k=0;k<16;k++){
            float a0=As[4*ty+0][ch+k], a1=As[4*ty+1][ch+k];
            float a2=As[4*ty+2][ch+k], a3=As[4*ty+3][ch+k];
            float4 bq = *(float4*)&Bs[k][4*tx];
            acc[0][0]+=a0*bq.x; acc[0][1]+=a0*bq.y; acc[0][2]+=a0*bq.z; acc[0][3]+=a0*bq.w;
            acc[1][0]+=a1*bq.x; acc[1][1]+=a1*bq.y; acc[1][2]+=a1*bq.z; acc[1][3]+=a1*bq.w;
            acc[2][0]+=a2*bq.x; acc[2][1]+=a2*bq.y; acc[2][2]+=a2*bq.z; acc[2][3]+=a2*bq.w;
            acc[3][0]+=a3*bq.x; acc[3][1]+=a3*bq.y; acc[3][2]+=a3*bq.z; acc[3][3]+=a3*bq.w;
        }
    }
    #pragma unroll
    for (int i=0;i<4;i++){
        float4 o = make_float4(acc[i][0], acc[i][1], acc[i][2], acc[i][3]);
        *(float4*)&Y[(size_t)(bm0+4*ty+i)*256 + bn0 + 4*tx] = o;
    }
}

/* ==== mega-fused: h1 -> H@W2cat -> vnb,sim -> softmax -> output ==== */
#define SMF_B   0                       /* 16 x 68                   */
#define SMF_A   (SMF_B + 16*68)         /* 80 x 65                   */
#define SMF_V   (SMF_A + RPB*65)        /* 80 x 65                   */
#define SMF_REL (SMF_V + RPB*65)        /* 80 x 4                    */
#define SMF_SIM (SMF_REL + RPB*4)       /* 80                        */
#define SMF_JR  (SMF_SIM + RPB)         /* 80                        */
#define SMF_PW  (SMF_JR + RPB)          /* 256                       */
#define SMF_TOT ((SMF_PW + 256) * 4)

__global__ __launch_bounds__(256, 4) void fused_attn_kernel(
    const float* __restrict__ pts,
    const float* __restrict__ pw1, const float* __restrict__ pb1,
    const float* __restrict__ pb2, const float* __restrict__ aw2,
    const float* __restrict__ ab2, int outsel)
{
    extern __shared__ float sm[];
    float* Bs  = sm + SMF_B;
    float* As  = sm + SMF_A;
    float* Vs  = sm + SMF_V;
    float* Rel = sm + SMF_REL;
    float* Sim = sm + SMF_SIM;
    int*   Jr  = (int*)(sm + SMF_JR);
    float* Pw  = sm + SMF_PW;

    int t = threadIdx.x, tx = t & 15, ty = t >> 4;
    int q0 = blockIdx.x * QPB;
    int m0 = q0 * KNB;

    if (t < 64){
        Pw[t]     = pw1[t];
        Pw[64+t]  = pw1[64+t];
        Pw[128+t] = pw1[128+t];
        Pw[192+t] = pb1[t];
    }
    if (t < RPB){
        int gq = q0 + t/KNB;
        int b  = gq >> 13;
        int jr = (b<<13) + g_idx[m0 + t];
        Jr[t] = jr;
        Rel[t*4+0] = pts[gq*3+0] - pts[(size_t)jr*3+0];
        Rel[t*4+1] = pts[gq*3+1] - pts[(size_t)jr*3+1];
        Rel[t*4+2] = pts[gq*3+2] - pts[(size_t)jr*3+2];
    }
    __syncthreads();

    /* h1 = relu(rel_pos @ pw1 + pb1) into As */
    #pragma unroll
    for (int e = t; e < RPB*64; e += 256){
        int r = e >> 6, c = e & 63;
        float h = fmaf(Rel[r*4+0], Pw[c],
                  fmaf(Rel[r*4+1], Pw[64+c],
                  fmaf(Rel[r*4+2], Pw[128+c], Pw[192+c])));
        As[r*65 + c] = fmaxf(h, 0.f);
    }

    int jr_r[5], gq_r[5];
    #pragma unroll
    for (int i=0;i<5;i++){
        int r = ty*5 + i;
        jr_r[i] = Jr[r];
        gq_r[i] = q0 + r/KNB;
    }

    float rsum[5] = {0.f,0.f,0.f,0.f,0.f};
    for (int nb=0; nb<5; nb++){
        float acc[5][4] = {};
        for (int ch=0; ch<64; ch+=16){
            __syncthreads();
            {
                int r = t >> 4, c4 = t & 15;
                *(float4*)&Bs[r*68 + 4*c4] =
                    *(const float4*)&g_w2cat[(ch+r)*320 + nb*64 + 4*c4];
            }
            __syncthreads();
            #pragma unroll
            for (int k=0;k<16;k++){
                float4 bq = *(const float4*)&Bs[k*68 + 4*tx];
                #pragma unroll
                for (int i=0;i<5;i++){
                    float a = As[(ty*5+i)*65 + ch + k];
                    acc[i][0] += a*bq.x; acc[i][1] += a*bq.y;
                    acc[i][2] += a*bq.z; acc[i][3] += a*bq.w;
                }
            }
        }
        if (nb == 0){
            float4 pb = *(const float4*)&pb2[4*tx];
            #pragma unroll
            for (int i=0;i<5;i++){
                int r = ty*5 + i;
                float4 vv = *(const float4*)&g_v[(size_t)jr_r[i]*64 + 4*tx];
                float* vp = &Vs[r*65 + 4*tx];
                vp[0] = acc[i][0] + pb.x + vv.x;
                vp[1] = acc[i][1] + pb.y + vv.y;
                vp[2] = acc[i][2] + pb.z + vv.z;
                vp[3] = acc[i][3] + pb.w + vv.w;
            }
        } else {
            int cb = (nb-1)*64 + 4*tx;
            float4 cv  = *(const float4*)&g_cvec[cb];
            float4 a2v = *(const float4*)&aw2[cb];
            #pragma unroll
            for (int i=0;i<5;i++){
                float4 qv = *(const float4*)&g_qw[(size_t)gq_r[i]*256 + cb];
                float4 kv = *(const float4*)&g_kw[(size_t)jr_r[i]*256 + cb];
                float h0 = fmaxf(acc[i][0] + cv.x + qv.x - kv.x, 0.f);
                float h1 = fmaxf(acc[i][1] + cv.y + qv.y - kv.y, 0.f);
                float h2 = fmaxf(acc[i][2] + cv.z + qv.z - kv.z, 0.f);
                float h3 = fmaxf(acc[i][3] + cv.w + qv.w - kv.w, 0.f);
                rsum[i] += h0*a2v.x + h1*a2v.y + h2*a2v.z + h3*a2v.w;
            }
        }
    }
    /* half-warp (16-lane) reduce over tx, write Sim */
    float abias = ab2[0];
    #pragma unroll
    for (int i=0;i<5;i++){
        float v = rsum[i];
        v += __shfl_xor_sync(0xffffffffu, v, 8);
        v += __shfl_xor_sync(0xffffffffu, v, 4);
        v += __shfl_xor_sync(0xffffffffu, v, 2);
        v += __shfl_xor_sync(0xffffffffu, v, 1);
        if (tx == 0) Sim[ty*5+i] = v + abias;
    }
    __syncthreads();

    /* softmax over K=20 + weighted sum of Vs -> output */
    if (t < 128){
        int w = t >> 5, lane = t & 31;
        float s = (lane < KNB) ? Sim[w*KNB + lane] : -CUDART_INF_F;
        float m = s;
        #pragma unroll
        for (int off=16; off; off>>=1) m = fmaxf(m, __shfl_xor_sync(0xffffffffu, m, off));
        float e = (lane < KNB) ? expf(s - m) : 0.f;
        float sum = e;
        #pragma unroll
        for (int off=16; off; off>>=1) sum += __shfl_xor_sync(0xffffffffu, sum, off);
        float attn = e / sum;
        float acc0 = 0.f, acc1 = 0.f;
        #pragma unroll
        for (int kk=0; kk<KNB; kk++){
            float a = __shfl_sync(0xffffffffu, attn, kk);
            const float* vb = &Vs[(w*KNB + kk)*65];
            acc0 += a * vb[lane];
            acc1 += a * vb[32 + lane];
        }
        float* xout = outsel ? g_xb : g_xa;
        xout[(size_t)(q0+w)*64 + lane]      = acc0;
        xout[(size_t)(q0+w)*64 + 32 + lane] = acc1;
    }
}

/* ---------------- global max pool (partial) ----------------------- */
__global__ void pool_kernel(void)
{
    int b = blockIdx.x, ch = blockIdx.y, c = threadIdx.x;
    float m = -CUDART_INF_F;
    int base = b*NPTS + ch*128;
    #pragma unroll 4
    for (int n=0;n<128;n++) m = fmaxf(m, g_xa[(size_t)(base+n)*64 + c]);
    g_part[(b*64 + ch)*64 + c] = m;
}

/* ---------------- head ------------------------------------------- */
__global__ void head_kernel(
    const float* __restrict__ fc1w, const float* __restrict__ fc1b,
    const float* __restrict__ fc3w, const float* __restrict__ fc3b,
    float* __restrict__ out)
{
    __shared__ float sp[BATCH*64];
    __shared__ float sh[BATCH*32];
    int t = threadIdx.x;
    if (t < 128){
        int b = t >> 6, c = t & 63;
        float m = -CUDART_INF_F;
        for (int ch=0; ch<64; ch++) m = fmaxf(m, g_part[(b*64+ch)*64 + c]);
        sp[b*64 + c] = m;
    }
    __syncthreads();
    if (t < 64){
        int b = t >> 5, cc = t & 31;
        float s = fc1b[cc];
        for (int c=0;c<64;c++) s += sp[b*64+c] * fc1w[c*32 + cc];
        sh[b*32 + cc] = fmaxf(s, 0.f);
    }
    __syncthreads();
    if (t < 6){
        int b = t / 3, o = t % 3;
        float s = fc3b[o];
        for (int cc=0;cc<32;cc++) s += sh[b*32+cc] * fc3w[cc*3 + o];
        out[b*3 + o] = s;
    }
}

/* ------------------------------ launch ---------------------------- */
extern "C" void kernel_launch(void* const* d_in, const int* in_sizes, int n_in,
                              void* d_out, int out_size)
{
    (void)in_sizes; (void)n_in; (void)out_size;
    const float* pts = (const float*)d_in[0];
    float* out = (float*)d_out;

    cudaFuncSetAttribute(fused_attn_kernel,
                         cudaFuncAttributeMaxDynamicSharedMemorySize, SMF_TOT);

    const float* W1[9] = {
        (const float*)d_in[3], (const float*)d_in[4], (const float*)d_in[5],
        (const float*)d_in[6], (const float*)d_in[7], (const float*)d_in[8],
        (const float*)d_in[9], (const float*)d_in[10], (const float*)d_in[11]};
    const float* W2[9] = {
        (const float*)d_in[12], (const float*)d_in[13], (const float*)d_in[14],
        (const float*)d_in[15], (const float*)d_in[16], (const float*)d_in[17],
        (const float*)d_in[18], (const float*)d_in[19], (const float*)d_in[20]};

    /* ordered so knn is the 4th launch (ncu profile slot) */
    embed_kernel<<<BN_TOT*64/256, 256>>>(pts, (const float*)d_in[1], (const float*)d_in[2]);
    qkv_kernel<<<dim3(BN_TOT/64, 3), 256>>>(0, W1[0]);
    prep_kernel<<<81, 256>>>(W1[3], W1[5], W1[4], W1[6]);
    knn_kernel<<<BN_TOT/128, 256, KNN_SMEM>>>(pts);

    gemm_qk_kernel<<<dim3(BN_TOT/64, 4), 256>>>(g_q, W1[5], g_qw);
    gemm_qk_kernel<<<dim3(BN_TOT/64, 4), 256>>>(g_k, W1[5], g_kw);
    fused_attn_kernel<<<BN_TOT/QPB, 256, SMF_TOT>>>(
        pts, W1[1], W1[2], W1[4], W1[7], W1[8], 1);

    prep_kernel<<<81, 256>>>(W2[3], W2[5], W2[4], W2[6]);
    qkv_kernel<<<dim3(BN_TOT/64, 3), 256>>>(1, W2[0]);
    gemm_qk_kernel<<<dim3(BN_TOT/64, 4), 256>>>(g_q, W2[5], g_qw);
    gemm_qk_kernel<<<dim3(BN_TOT/64, 4), 256>>>(g_k, W2[5], g_kw);
    fused_attn_kernel<<<BN_TOT/QPB, 256, SMF_TOT>>>(
        pts, W2[1], W2[2], W2[4], W2[7], W2[8], 0);

    pool_kernel<<<dim3(BATCH, 64), 64>>>();
    head_kernel<<<1, 128>>>((const float*)d_in[21], (const float*)d_in[22],
                            (const float*)d_in[23], (const float*)d_in[24], out);
}

// round 6
// speedup vs baseline: 1.5362x; 1.0497x over previous
#include <cuda_runtime.h>
#include <math_constants.h>

#define NPTS   8192
#define BATCH  2
#define BN_TOT (BATCH*NPTS)      /* 16384 */
#define KNB    20
#define M2     (BN_TOT*KNB)      /* 327680 */
#define QPB    4                 /* queries per fused block */
#define RPB    (QPB*KNB)         /* 80 pair-rows per block */

typedef unsigned long long ull;

/* ------------------------- device scratch ------------------------- */
__device__ float g_xa[BN_TOT*64];
__device__ float g_xb[BN_TOT*64];
__device__ float g_q [BN_TOT*64];
__device__ float g_k [BN_TOT*64];
__device__ float g_v [BN_TOT*64];
__device__ int   g_idx[M2];
__device__ float g_qw[BN_TOT*256];
__device__ float g_kw[BN_TOT*256];
__device__ __align__(16) float g_w2cat[64*320];
__device__ __align__(16) float g_cvec[256];
__device__ float g_part[BATCH*64*64];

/* ------------------------- embed: relu(points @ conv_w + b) -------- */
__global__ __launch_bounds__(256) void embed_kernel(
    const float* __restrict__ pts, const float* __restrict__ w,
    const float* __restrict__ b)
{
    int i = blockIdx.x*256 + threadIdx.x;
    int row = i >> 6, c = i & 63;
    float x = pts[row*3+0], y = pts[row*3+1], z = pts[row*3+2];
    float s = x*w[c] + y*w[64+c] + z*w[128+c] + b[c];
    g_xa[i] = fmaxf(s, 0.f);
}

/* ---------- KNN v4: 64 q/block, 4-way split, grid 256 ------------- */
#define KQ   64
#define KS   4
#define KCH  (NPTS/KS)           /* 2048 candidates per split */
#define KBUF 12
#define KNN_SMEM 40960
#define INITKEY 0x7F800000FFFFFFFFULL

__global__ __launch_bounds__(256) void knn_kernel(const float* __restrict__ pts)
{
    extern __shared__ ull ksm[];
    float4* sp = (float4*)ksm;          /* [1024] = 16384 B */
    ull* buf = ksm + 2048;              /* [256*12] = 24576 B */

    int t = threadIdx.x;
    int s = t >> 6;                     /* split 0..3 (uniform per warp) */
    int qi = t & 63;
    int gq = blockIdx.x*KQ + qi;
    int b  = gq >> 13;
    float qx = pts[gq*3+0], qy = pts[gq*3+1], qz = pts[gq*3+2];
    const float* cloud = pts + (size_t)b*NPTS*3;

    ull best[KNB];
    #pragma unroll
    for (int p=0;p<KNB;p++) best[p] = INITKEY;
    float bd19 = CUDART_INF_F;
    int cnt = 0;

    for (int iter = 0; iter < KCH/256; iter++){
        __syncthreads();
        #pragma unroll
        for (int u=0; u<4; u++){
            const float* pp = cloud + (size_t)(u*KCH + iter*256 + t)*3;
            sp[u*256 + t] = make_float4(pp[0], pp[1], pp[2], 0.f);
        }
        __syncthreads();
        int base = s*256;
        int id0  = s*KCH + iter*256;
        for (int c8 = 0; c8 < 256; c8 += 8){
            #pragma unroll
            for (int j=0;j<8;j++){
                float4 p = sp[base + c8 + j];
                float dx = qx-p.x, dy = qy-p.y, dz = qz-p.z;
                float d2 = fmaf(dx,dx,fmaf(dy,dy,dz*dz));
                if (d2 <= bd19){
                    ull key;
                    asm("mov.b64 %0, {%1, %2};" : "=l"(key)
                        : "r"(id0 + c8 + j), "r"(__float_as_uint(d2)));
                    buf[t*KBUF + cnt++] = key;
                }
            }
            if (__any_sync(0xffffffffu, cnt >= KBUF-7)){
                int n = cnt;
                for (int j2 = 0; j2 < n; j2++){
                    ull k2 = buf[t*KBUF + j2];
                    if (k2 < best[KNB-1]){
                        best[KNB-1] = k2;
                        #pragma unroll
                        for (int p = KNB-1; p >= 1; --p){
                            ull a = best[p-1], bb = best[p];
                            bool sw = bb < a;
                            best[p-1] = sw ? bb : a;
                            best[p]   = sw ? a : bb;
                        }
                    }
                }
                cnt = 0;
                bd19 = __uint_as_float((unsigned)(best[KNB-1] >> 32));
            }
        }
    }
    /* final flush (divergent, rare) */
    for (int j2 = 0; j2 < cnt; j2++){
        ull k2 = buf[t*KBUF + j2];
        if (k2 < best[KNB-1]){
            best[KNB-1] = k2;
            #pragma unroll
            for (int p = KNB-1; p >= 1; --p){
                ull a = best[p-1], bb = best[p];
                bool sw = bb < a;
                best[p-1] = sw ? bb : a;
                best[p]   = sw ? a : bb;
            }
        }
    }

    __syncthreads();
    ull* mrg = ksm;                     /* [64*4*20] = 40960 B */
    #pragma unroll
    for (int p=0;p<KNB;p++) mrg[(qi*KS + s)*KNB + p] = best[p];
    __syncthreads();

    if (t < KQ){
        int ptr[KS] = {0,0,0,0};
        int outq = blockIdx.x*KQ + t;
        #pragma unroll 1
        for (int r=0;r<KNB;r++){
            ull bk = ~0ULL; int bs = 0;
            #pragma unroll
            for (int s2=0;s2<KS;s2++){
                if (ptr[s2] < KNB){
                    ull k2 = mrg[(t*KS + s2)*KNB + ptr[s2]];
                    if (k2 < bk){ bk = k2; bs = s2; }
                }
            }
            ptr[bs]++;
            g_idx[outq*KNB + r] = (int)(unsigned)(bk & 0xFFFFFFFFULL);
        }
    }
}

/* ------------------------- qkv GEMM (M=16384, K=64, N=192) -------- */
__global__ __launch_bounds__(256) void qkv_kernel(int xsel, const float* __restrict__ W)
{
    __shared__ float As[64][68];
    __shared__ __align__(16) float Bs[16][64];
    const float* X = xsel ? g_xb : g_xa;
    int t = threadIdx.x, tx = t & 15, ty = t >> 4;
    int bm0 = blockIdx.x * 64;
    int bn0 = blockIdx.y * 64;
    #pragma unroll
    for (int i=0;i<4;i++){
        int idx4 = t + i*256;
        int r = idx4 >> 4, c4 = idx4 & 15;
        *(float4*)&As[r][4*c4] = *(const float4*)&X[(size_t)(bm0+r)*64 + 4*c4];
    }
    float acc[4][4] = {};
    for (int ch=0; ch<64; ch+=16){
        __syncthreads();
        {
            int r = t >> 4, c4 = t & 15;
            *(float4*)&Bs[r][4*c4] = *(const float4*)&W[(ch+r)*192 + bn0 + 4*c4];
        }
        __syncthreads();
        #pragma unroll
        for (int k=0;k<16;k++){
            float a0=As[4*ty+0][ch+k], a1=As[4*ty+1][ch+k];
            float a2=As[4*ty+2][ch+k], a3=As[4*ty+3][ch+k];
            float4 bq = *(float4*)&Bs[k][4*tx];
            acc[0][0]+=a0*bq.x; acc[0][1]+=a0*bq.y; acc[0][2]+=a0*bq.z; acc[0][3]+=a0*bq.w;
            acc[1][0]+=a1*bq.x; acc[1][1]+=a1*bq.y; acc[1][2]+=a1*bq.z; acc[1][3]+=a1*bq.w;
            acc[2][0]+=a2*bq.x; acc[2][1]+=a2*bq.y; acc[2][2]+=a2*bq.z; acc[2][3]+=a2*bq.w;
            acc[3][0]+=a3*bq.x; acc[3][1]+=a3*bq.y; acc[3][2]+=a3*bq.z; acc[3][3]+=a3*bq.w;
        }
    }
    float* outp = (bn0 == 0) ? g_q : (bn0 == 64) ? g_k : g_v;
    #pragma unroll
    for (int i=0;i<4;i++){
        float4 o = make_float4(acc[i][0], acc[i][1], acc[i][2], acc[i][3]);
        *(float4*)&outp[(size_t)(bm0+4*ty+i)*64 + 4*tx] = o;
    }
}

/* ---- prep: W2cat = [pw2 | pw2 @ aw1_bot], cvec (merged) ---------- */
__global__ __launch_bounds__(256) void prep_kernel(
    const float* __restrict__ pw2, const float* __restrict__ aw1,
    const float* __restrict__ pb2, const float* __restrict__ ab1)
{
    int blk = blockIdx.x;
    int t = threadIdx.x;
    if (blk < 80){
        int i = blk*256 + t;                  /* 64*320 */
        int r = i / 320, c = i % 320;
        if (c < 64){
            g_w2cat[i] = pw2[r*64 + c];
        } else {
            int cc = c - 64;
            float s = 0.f;
            #pragma unroll 8
            for (int d=0; d<64; d++)
                s += pw2[r*64 + d] * aw1[(64+d)*256 + cc];
            g_w2cat[i] = s;
        }
    } else {
        float s = ab1[t];
        #pragma unroll 8
        for (int d=0; d<64; d++)
            s += pb2[d] * aw1[(64+d)*256 + t];
        g_cvec[t] = s;
    }
}

/* ----------- qW/kW: (16384,64) @ aw1_top(64,256), scalar ---------- */
__global__ __launch_bounds__(256) void gemm_qk_kernel(
    const float* __restrict__ X, const float* __restrict__ W,
    float* __restrict__ Y)
{
    __shared__ float As[64][68];
    __shared__ __align__(16) float Bs[16][64];
    int t = threadIdx.x, tx = t & 15, ty = t >> 4;
    int bm0 = blockIdx.x * 64;
    int bn0 = blockIdx.y * 64;
    #pragma unroll
    for (int i=0;i<4;i++){
        int idx4 = t + i*256;
        int r = idx4 >> 4, c4 = idx4 & 15;
        *(float4*)&As[r][4*c4] = *(const float4*)&X[(size_t)(bm0+r)*64 + 4*c4];
    }
    float acc[4][4] = {};
    for (int ch=0; ch<64; ch+=16){
        __syncthreads();
        {
            int r = t >> 4, c4 = t & 15;
            *(float4*)&Bs[r][4*c4] = *(const float4*)&W[(ch+r)*256 + bn0 + 4*c4];
        }
        __syncthreads();
        #pragma unroll
        for (int k=0;k<16;k++){
            float a0=As[4*ty+0][ch+k], a1=As[4*ty+1][ch+k];
            float a2=As[4*ty+2][ch+k], a3=As[4*ty+3][ch+k];
            float4 bq = *(float4*)&Bs[k][4*tx];
            acc[0][0]+=a0*bq.x; acc[0][1]+=a0*bq.y; acc[0][2]+=a0*bq.z; acc[0][3]+=a0*bq.w;
            acc[1][0]+=a1*bq.x; acc[1][1]+=a1*bq.y; acc[1][2]+=a1*bq.z; acc[1][3]+=a1*bq.w;
            acc[2][0]+=a2*bq.x; acc[2][1]+=a2*bq.y; acc[2][2]+=a2*bq.z; acc[2][3]+=a2*bq.w;
            acc[3][0]+=a3*bq.x; acc[3][1]+=a3*bq.y; acc[3][2]+=a3*bq.z; acc[3][3]+=a3*bq.w;
        }
    }
    #pragma unroll
    for (int i=0;i<4;i++){
        float4 o = make_float4(acc[i][0], acc[i][1], acc[i][2], acc[i][3]);
        *(float4*)&Y[(size_t)(bm0+4*ty+i)*256 + bn0 + 4*tx] = o;
    }
}

/* ==== mega-fused: h1 -> H@W2cat -> vnb,sim -> softmax -> output ====
   double-buffered B tiles: one __syncthreads per 16-k chunk         */
#define SMF_B   0                       /* 2 x 16 x 68 = 2176        */
#define SMF_A   (SMF_B + 2176)          /* 80 x 65                   */
#define SMF_V   (SMF_A + RPB*65)        /* 80 x 65                   */
#define SMF_REL (SMF_V + RPB*65)        /* 80 x 4                    */
#define SMF_SIM (SMF_REL + RPB*4)       /* 80                        */
#define SMF_JR  (SMF_SIM + RPB)         /* 80                        */
#define SMF_PW  (SMF_JR + RPB)          /* 256                       */
#define SMF_TOT ((SMF_PW + 256) * 4)

__global__ __launch_bounds__(256, 4) void fused_attn_kernel(
    const float* __restrict__ pts,
    const float* __restrict__ pw1, const float* __restrict__ pb1,
    const float* __restrict__ pb2, const float* __restrict__ aw2,
    const float* __restrict__ ab2, int outsel)
{
    extern __shared__ float sm[];
    float* Bs  = sm + SMF_B;
    float* As  = sm + SMF_A;
    float* Vs  = sm + SMF_V;
    float* Rel = sm + SMF_REL;
    float* Sim = sm + SMF_SIM;
    int*   Jr  = (int*)(sm + SMF_JR);
    float* Pw  = sm + SMF_PW;

    int t = threadIdx.x, tx = t & 15, ty = t >> 4;
    int ldr = t >> 4, ldc = t & 15;     /* B-tile loader coords */
    int q0 = blockIdx.x * QPB;
    int m0 = q0 * KNB;

    if (t < 64){
        Pw[t]     = pw1[t];
        Pw[64+t]  = pw1[64+t];
        Pw[128+t] = pw1[128+t];
        Pw[192+t] = pb1[t];
    }
    if (t < RPB){
        int gq = q0 + t/KNB;
        int b  = gq >> 13;
        int jr = (b<<13) + g_idx[m0 + t];
        Jr[t] = jr;
        Rel[t*4+0] = pts[gq*3+0] - pts[(size_t)jr*3+0];
        Rel[t*4+1] = pts[gq*3+1] - pts[(size_t)jr*3+1];
        Rel[t*4+2] = pts[gq*3+2] - pts[(size_t)jr*3+2];
    }
    /* stage first B tile (nb=0, ch=0) */
    *(float4*)&Bs[ldr*68 + 4*ldc] = *(const float4*)&g_w2cat[ldr*320 + 4*ldc];
    __syncthreads();

    /* h1 = relu(rel_pos @ pw1 + pb1) into As */
    #pragma unroll
    for (int e = t; e < RPB*64; e += 256){
        int r = e >> 6, c = e & 63;
        float h = fmaf(Rel[r*4+0], Pw[c],
                  fmaf(Rel[r*4+1], Pw[64+c],
                  fmaf(Rel[r*4+2], Pw[128+c], Pw[192+c])));
        As[r*65 + c] = fmaxf(h, 0.f);
    }
    __syncthreads();

    int jr_r[5], gq_r[5];
    #pragma unroll
    for (int i=0;i<5;i++){
        int r = ty*5 + i;
        jr_r[i] = Jr[r];
        gq_r[i] = q0 + r/KNB;
    }

    float rsum[5] = {0.f,0.f,0.f,0.f,0.f};
    float acc[5][4];
    for (int it = 0; it < 20; it++){
        int nb = it >> 2, ch = (it & 3) * 16;
        int cur = it & 1;
        float4 nxt;
        if (it < 19){
            int nit = it + 1, nnb = nit >> 2, nch = (nit & 3) * 16;
            nxt = *(const float4*)&g_w2cat[(nch+ldr)*320 + nnb*64 + 4*ldc];
        }
        if ((it & 3) == 0){
            #pragma unroll
            for (int i=0;i<5;i++){ acc[i][0]=acc[i][1]=acc[i][2]=acc[i][3]=0.f; }
        }
        const float* Bc = &Bs[cur*1088];
        #pragma unroll
        for (int k=0;k<16;k++){
            float4 bq = *(const float4*)&Bc[k*68 + 4*tx];
            #pragma unroll
            for (int i=0;i<5;i++){
                float a = As[(ty*5+i)*65 + ch + k];
                acc[i][0] += a*bq.x; acc[i][1] += a*bq.y;
                acc[i][2] += a*bq.z; acc[i][3] += a*bq.w;
            }
        }
        if ((it & 3) == 3){
            if (nb == 0){
                float4 pb = *(const float4*)&pb2[4*tx];
                #pragma unroll
                for (int i=0;i<5;i++){
                    int r = ty*5 + i;
                    float4 vv = *(const float4*)&g_v[(size_t)jr_r[i]*64 + 4*tx];
                    float* vp = &Vs[r*65 + 4*tx];
                    vp[0] = acc[i][0] + pb.x + vv.x;
                    vp[1] = acc[i][1] + pb.y + vv.y;
                    vp[2] = acc[i][2] + pb.z + vv.z;
                    vp[3] = acc[i][3] + pb.w + vv.w;
                }
            } else {
                int cb = (nb-1)*64 + 4*tx;
                float4 cv  = *(const float4*)&g_cvec[cb];
                float4 a2v = *(const float4*)&aw2[cb];
                #pragma unroll
                for (int i=0;i<5;i++){
                    float4 qv = *(const float4*)&g_qw[(size_t)gq_r[i]*256 + cb];
                    float4 kv = *(const float4*)&g_kw[(size_t)jr_r[i]*256 + cb];
                    float h0 = fmaxf(acc[i][0] + cv.x + qv.x - kv.x, 0.f);
                    float h1 = fmaxf(acc[i][1] + cv.y + qv.y - kv.y, 0.f);
                    float h2 = fmaxf(acc[i][2] + cv.z + qv.z - kv.z, 0.f);
                    float h3 = fmaxf(acc[i][3] + cv.w + qv.w - kv.w, 0.f);
                    rsum[i] += h0*a2v.x + h1*a2v.y + h2*a2v.z + h3*a2v.w;
                }
            }
        }
        if (it < 19){
            *(float4*)&Bs[(cur^1)*1088 + ldr*68 + 4*ldc] = nxt;
            __syncthreads();
        }
    }
    /* half-warp (16-lane) reduce over tx, write Sim */
    float abias = ab2[0];
    #pragma unroll
    for (int i=0;i<5;i++){
        float v = rsum[i];
        v += __shfl_xor_sync(0xffffffffu, v, 8);
        v += __shfl_xor_sync(0xffffffffu, v, 4);
        v += __shfl_xor_sync(0xffffffffu, v, 2);
        v += __shfl_xor_sync(0xffffffffu, v, 1);
        if (tx == 0) Sim[ty*5+i] = v + abias;
    }
    __syncthreads();

    /* softmax over K=20 + weighted sum of Vs -> output */
    if (t < 128){
        int w = t >> 5, lane = t & 31;
        float s = (lane < KNB) ? Sim[w*KNB + lane] : -CUDART_INF_F;
        float m = s;
        #pragma unroll
        for (int off=16; off; off>>=1) m = fmaxf(m, __shfl_xor_sync(0xffffffffu, m, off));
        float e = (lane < KNB) ? expf(s - m) : 0.f;
        float sum = e;
        #pragma unroll
        for (int off=16; off; off>>=1) sum += __shfl_xor_sync(0xffffffffu, sum, off);
        float attn = e / sum;
        float acc0 = 0.f, acc1 = 0.f;
        #pragma unroll
        for (int kk=0; kk<KNB; kk++){
            float a = __shfl_sync(0xffffffffu, attn, kk);
            const float* vb = &Vs[(w*KNB + kk)*65];
            acc0 += a * vb[lane];
            acc1 += a * vb[32 + lane];
        }
        float* xout = outsel ? g_xb : g_xa;
        xout[(size_t)(q0+w)*64 + lane]      = acc0;
        xout[(size_t)(q0+w)*64 + 32 + lane] = acc1;
    }
}

/* ---------------- global max pool (partial) ----------------------- */
__global__ void pool_kernel(void)
{
    int b = blockIdx.x, ch = blockIdx.y, c = threadIdx.x;
    float m = -CUDART_INF_F;
    int base = b*NPTS + ch*128;
    #pragma unroll 4
    for (int n=0;n<128;n++) m = fmaxf(m, g_xa[(size_t)(base+n)*64 + c]);
    g_part[(b*64 + ch)*64 + c] = m;
}

/* ---------------- head ------------------------------------------- */
__global__ void head_kernel(
    const float* __restrict__ fc1w, const float* __restrict__ fc1b,
    const float* __restrict__ fc3w, const float* __restrict__ fc3b,
    float* __restrict__ out)
{
    __shared__ float sp[BATCH*64];
    __shared__ float sh[BATCH*32];
    int t = threadIdx.x;
    if (t < 128){
        int b = t >> 6, c = t & 63;
        float m = -CUDART_INF_F;
        for (int ch=0; ch<64; ch++) m = fmaxf(m, g_part[(b*64+ch)*64 + c]);
        sp[b*64 + c] = m;
    }
    __syncthreads();
    if (t < 64){
        int b = t >> 5, cc = t & 31;
        float s = fc1b[cc];
        for (int c=0;c<64;c++) s += sp[b*64+c] * fc1w[c*32 + cc];
        sh[b*32 + cc] = fmaxf(s, 0.f);
    }
    __syncthreads();
    if (t < 6){
        int b = t / 3, o = t % 3;
        float s = fc3b[o];
        for (int cc=0;cc<32;cc++) s += sh[b*32+cc] * fc3w[cc*3 + o];
        out[b*3 + o] = s;
    }
}

/* ------------------------------ launch ---------------------------- */
extern "C" void kernel_launch(void* const* d_in, const int* in_sizes, int n_in,
                              void* d_out, int out_size)
{
    (void)in_sizes; (void)n_in; (void)out_size;
    const float* pts = (const float*)d_in[0];
    float* out = (float*)d_out;

    cudaFuncSetAttribute(fused_attn_kernel,
                         cudaFuncAttributeMaxDynamicSharedMemorySize, SMF_TOT);

    const float* W1[9] = {
        (const float*)d_in[3], (const float*)d_in[4], (const float*)d_in[5],
        (const float*)d_in[6], (const float*)d_in[7], (const float*)d_in[8],
        (const float*)d_in[9], (const float*)d_in[10], (const float*)d_in[11]};
    const float* W2[9] = {
        (const float*)d_in[12], (const float*)d_in[13], (const float*)d_in[14],
        (const float*)d_in[15], (const float*)d_in[16], (const float*)d_in[17],
        (const float*)d_in[18], (const float*)d_in[19], (const float*)d_in[20]};

    /* ordered so knn is the 4th launch (ncu profile slot) */
    embed_kernel<<<BN_TOT*64/256, 256>>>(pts, (const float*)d_in[1], (const float*)d_in[2]);
    qkv_kernel<<<dim3(BN_TOT/64, 3), 256>>>(0, W1[0]);
    prep_kernel<<<81, 256>>>(W1[3], W1[5], W1[4], W1[6]);
    knn_kernel<<<BN_TOT/KQ, 256, KNN_SMEM>>>(pts);

    gemm_qk_kernel<<<dim3(BN_TOT/64, 4), 256>>>(g_q, W1[5], g_qw);
    gemm_qk_kernel<<<dim3(BN_TOT/64, 4), 256>>>(g_k, W1[5], g_kw);
    fused_attn_kernel<<<BN_TOT/QPB, 256, SMF_TOT>>>(
        pts, W1[1], W1[2], W1[4], W1[7], W1[8], 1);

    prep_kernel<<<81, 256>>>(W2[3], W2[5], W2[4], W2[6]);
    qkv_kernel<<<dim3(BN_TOT/64, 3), 256>>>(1, W2[0]);
    gemm_qk_kernel<<<dim3(BN_TOT/64, 4), 256>>>(g_q, W2[5], g_qw);
    gemm_qk_kernel<<<dim3(BN_TOT/64, 4), 256>>>(g_k, W2[5], g_kw);
    fused_attn_kernel<<<BN_TOT/QPB, 256, SMF_TOT>>>(
        pts, W2[1], W2[2], W2[4], W2[7], W2[8], 0);

    pool_kernel<<<dim3(BATCH, 64), 64>>>();
    head_kernel<<<1, 128>>>((const float*)d_in[21], (const float*)d_in[22],
                            (const float*)d_in[23], (const float*)d_in[24], out);
}

// round 7
// speedup vs baseline: 1.7790x; 1.1580x over previous
#include <cuda_runtime.h>
#include <math_constants.h>

#define NPTS   8192
#define BATCH  2
#define BN_TOT (BATCH*NPTS)      /* 16384 */
#define KNB    20
#define M2     (BN_TOT*KNB)      /* 327680 */
#define QPB    4                 /* queries per fused block */
#define RPB    (QPB*KNB)         /* 80 pair-rows per block */

typedef unsigned long long ull;

/* ------------------------- device scratch ------------------------- */
__device__ float g_xa[BN_TOT*64];
__device__ float g_xb[BN_TOT*64];
__device__ float g_q [BN_TOT*64];
__device__ float g_k [BN_TOT*64];
__device__ float g_v [BN_TOT*64];
__device__ int   g_idx[M2];
__device__ float g_qw[BN_TOT*256];
__device__ float g_kw[BN_TOT*256];
__device__ __align__(16) float g_w2cat[64*320];
__device__ __align__(16) float g_cvec[256];
__device__ float g_part[BATCH*64*64];

/* ============ setup: embed (blocks 0..4095) + prep (4096..4176) === */
__global__ __launch_bounds__(256) void setup_kernel(
    const float* __restrict__ pts, const float* __restrict__ cw,
    const float* __restrict__ cb,  const float* __restrict__ pw2,
    const float* __restrict__ aw1, const float* __restrict__ pb2,
    const float* __restrict__ ab1)
{
    int blk = blockIdx.x, t = threadIdx.x;
    if (blk < 4096){
        int i = blk*256 + t;
        int row = i >> 6, c = i & 63;
        float x = pts[row*3+0], y = pts[row*3+1], z = pts[row*3+2];
        float s = x*cw[c] + y*cw[64+c] + z*cw[128+c] + cb[c];
        g_xa[i] = fmaxf(s, 0.f);
    } else if (blk < 4176){
        int i = (blk-4096)*256 + t;           /* 64*320 */
        int r = i / 320, c = i % 320;
        if (c < 64){
            g_w2cat[i] = pw2[r*64 + c];
        } else {
            int cc = c - 64;
            float s = 0.f;
            #pragma unroll 8
            for (int d=0; d<64; d++)
                s += pw2[r*64 + d] * aw1[(64+d)*256 + cc];
            g_w2cat[i] = s;
        }
    } else {
        float s = ab1[t];
        #pragma unroll 8
        for (int d=0; d<64; d++)
            s += pb2[d] * aw1[(64+d)*256 + t];
        g_cvec[t] = s;
    }
}

/* ---------- KNN v5: 32 q/block, 8 splits (1 per warp), grid 512 --- */
#define KQ   32
#define KS   8
#define KCH  1024                /* candidates per split */
#define KBUF 16
#define KNN_SMEM 65536
#define INITKEY 0x7F800000FFFFFFFFULL

__device__ __forceinline__ void knn_body(const float* __restrict__ pts,
                                         int blk, char* smraw)
{
    float4* sp = (float4*)smraw;            /* [2048] = 32768 B */
    ull* buf = (ull*)(smraw + 32768);       /* [256*16] = 32768 B */

    int t = threadIdx.x;
    int s = t >> 5;                         /* warp = split 0..7 */
    int qi = t & 31;
    int gq = blk*KQ + qi;
    int b  = gq >> 13;
    float qx = pts[gq*3+0], qy = pts[gq*3+1], qz = pts[gq*3+2];
    const float* cloud = pts + (size_t)b*NPTS*3;

    ull best[KNB];
    #pragma unroll
    for (int p=0;p<KNB;p++) best[p] = INITKEY;
    float bd19 = CUDART_INF_F;
    int cnt = 0;

    for (int iter = 0; iter < KCH/256; iter++){
        __syncthreads();
        #pragma unroll
        for (int u=0; u<8; u++){
            const float* pp = cloud + (size_t)(u*KCH + iter*256 + t)*3;
            sp[u*256 + t] = make_float4(pp[0], pp[1], pp[2], 0.f);
        }
        __syncthreads();
        int base = s*256;
        int id0  = s*KCH + iter*256;
        for (int c8 = 0; c8 < 256; c8 += 8){
            #pragma unroll
            for (int j=0;j<8;j++){
                float4 p = sp[base + c8 + j];
                float dx = qx-p.x, dy = qy-p.y, dz = qz-p.z;
                float d2 = fmaf(dx,dx,fmaf(dy,dy,dz*dz));
                if (d2 <= bd19){
                    ull key;
                    asm("mov.b64 %0, {%1, %2};" : "=l"(key)
                        : "r"(id0 + c8 + j), "r"(__float_as_uint(d2)));
                    buf[t*KBUF + cnt++] = key;
                }
            }
            if (__any_sync(0xffffffffu, cnt >= KBUF-7)){
                int n = cnt;
                for (int j2 = 0; j2 < n; j2++){
                    ull k2 = buf[t*KBUF + j2];
                    if (k2 < best[KNB-1]){
                        best[KNB-1] = k2;
                        #pragma unroll
                        for (int p = KNB-1; p >= 1; --p){
                            ull a = best[p-1], bb = best[p];
                            bool sw = bb < a;
                            best[p-1] = sw ? bb : a;
                            best[p]   = sw ? a : bb;
                        }
                    }
                }
                cnt = 0;
                bd19 = __uint_as_float((unsigned)(best[KNB-1] >> 32));
            }
        }
    }
    /* final flush (divergent, rare) */
    for (int j2 = 0; j2 < cnt; j2++){
        ull k2 = buf[t*KBUF + j2];
        if (k2 < best[KNB-1]){
            best[KNB-1] = k2;
            #pragma unroll
            for (int p = KNB-1; p >= 1; --p){
                ull a = best[p-1], bb = best[p];
                bool sw = bb < a;
                best[p-1] = sw ? bb : a;
                best[p]   = sw ? a : bb;
            }
        }
    }

    __syncthreads();
    ull* mrg = (ull*)smraw;                 /* [32*8*20] = 40960 B */
    #pragma unroll
    for (int p=0;p<KNB;p++) mrg[(qi*KS + s)*KNB + p] = best[p];
    __syncthreads();

    if (t < KQ){
        int ptr[KS] = {0,0,0,0,0,0,0,0};
        int outq = blk*KQ + t;
        #pragma unroll 1
        for (int r=0;r<KNB;r++){
            ull bk = ~0ULL; int bs = 0;
            #pragma unroll
            for (int s2=0;s2<KS;s2++){
                if (ptr[s2] < KNB){
                    ull k2 = mrg[(t*KS + s2)*KNB + ptr[s2]];
                    if (k2 < bk){ bk = k2; bs = s2; }
                }
            }
            ptr[bs]++;
            g_idx[outq*KNB + r] = (int)(unsigned)(bk & 0xFFFFFFFFULL);
        }
    }
}

/* ---- gemm body (64x64 tile, K=64, B row stride 256) in dyn smem -- */
__device__ __forceinline__ void gemm_body(
    const float* __restrict__ X, const float* __restrict__ W,
    float* __restrict__ Y, int bm0, int bn0, char* smraw)
{
    float* As = (float*)smraw;              /* 64*68 = 17408 B */
    float* Bs = (float*)(smraw + 17408);    /* 16*64 =  4096 B */
    int t = threadIdx.x, tx = t & 15, ty = t >> 4;
    #pragma unroll
    for (int i=0;i<4;i++){
        int idx4 = t + i*256;
        int r = idx4 >> 4, c4 = idx4 & 15;
        *(float4*)&As[r*68 + 4*c4] = *(const float4*)&X[(size_t)(bm0+r)*64 + 4*c4];
    }
    float acc[4][4] = {};
    for (int ch=0; ch<64; ch+=16){
        __syncthreads();
        {
            int r = t >> 4, c4 = t & 15;
            *(float4*)&Bs[r*64 + 4*c4] = *(const float4*)&W[(ch+r)*256 + bn0 + 4*c4];
        }
        __syncthreads();
        #pragma unroll
        for (int k=0;k<16;k++){
            float a0=As[(4*ty+0)*68+ch+k], a1=As[(4*ty+1)*68+ch+k];
            float a2=As[(4*ty+2)*68+ch+k], a3=As[(4*ty+3)*68+ch+k];
            float4 bq = *(float4*)&Bs[k*64 + 4*tx];
            acc[0][0]+=a0*bq.x; acc[0][1]+=a0*bq.y; acc[0][2]+=a0*bq.z; acc[0][3]+=a0*bq.w;
            acc[1][0]+=a1*bq.x; acc[1][1]+=a1*bq.y; acc[1][2]+=a1*bq.z; acc[1][3]+=a1*bq.w;
            acc[2][0]+=a2*bq.x; acc[2][1]+=a2*bq.y; acc[2][2]+=a2*bq.z; acc[2][3]+=a2*bq.w;
            acc[3][0]+=a3*bq.x; acc[3][1]+=a3*bq.y; acc[3][2]+=a3*bq.z; acc[3][3]+=a3*bq.w;
        }
    }
    #pragma unroll
    for (int i=0;i<4;i++){
        float4 o = make_float4(acc[i][0], acc[i][1], acc[i][2], acc[i][3]);
        *(float4*)&Y[(size_t)(bm0+4*ty+i)*256 + bn0 + 4*tx] = o;
    }
}

/* ---- combo: knn (blocks 0..511) + qW/kW gemms (512..2559) -------- */
__global__ __launch_bounds__(256) void knn_gemm_kernel(
    const float* __restrict__ pts, const float* __restrict__ aw1)
{
    extern __shared__ char smraw[];
    int blk = blockIdx.x;
    if (blk < 512){
        knn_body(pts, blk, smraw);
    } else {
        int i = blk - 512;
        const float* X = (i < 1024) ? g_q : g_k;
        float* Y       = (i < 1024) ? g_qw : g_kw;
        int j = i & 1023;
        gemm_body(X, aw1, Y, (j & 255)*64, (j >> 8)*64, smraw);
    }
}

/* ------------------------- qkv GEMM (M=16384, K=64, N=192) -------- */
__global__ __launch_bounds__(256) void qkv_kernel(int xsel, const float* __restrict__ W)
{
    __shared__ float As[64][68];
    __shared__ __align__(16) float Bs[16][64];
    const float* X = xsel ? g_xb : g_xa;
    int t = threadIdx.x, tx = t & 15, ty = t >> 4;
    int bm0 = blockIdx.x * 64;
    int bn0 = blockIdx.y * 64;
    #pragma unroll
    for (int i=0;i<4;i++){
        int idx4 = t + i*256;
        int r = idx4 >> 4, c4 = idx4 & 15;
        *(float4*)&As[r][4*c4] = *(const float4*)&X[(size_t)(bm0+r)*64 + 4*c4];
    }
    float acc[4][4] = {};
    for (int ch=0; ch<64; ch+=16){
        __syncthreads();
        {
            int r = t >> 4, c4 = t & 15;
            *(float4*)&Bs[r][4*c4] = *(const float4*)&W[(ch+r)*192 + bn0 + 4*c4];
        }
        __syncthreads();
        #pragma unroll
        for (int k=0;k<16;k++){
            float a0=As[4*ty+0][ch+k], a1=As[4*ty+1][ch+k];
            float a2=As[4*ty+2][ch+k], a3=As[4*ty+3][ch+k];
            float4 bq = *(float4*)&Bs[k][4*tx];
            acc[0][0]+=a0*bq.x; acc[0][1]+=a0*bq.y; acc[0][2]+=a0*bq.z; acc[0][3]+=a0*bq.w;
            acc[1][0]+=a1*bq.x; acc[1][1]+=a1*bq.y; acc[1][2]+=a1*bq.z; acc[1][3]+=a1*bq.w;
            acc[2][0]+=a2*bq.x; acc[2][1]+=a2*bq.y; acc[2][2]+=a2*bq.z; acc[2][3]+=a2*bq.w;
            acc[3][0]+=a3*bq.x; acc[3][1]+=a3*bq.y; acc[3][2]+=a3*bq.z; acc[3][3]+=a3*bq.w;
        }
    }
    float* outp = (bn0 == 0) ? g_q : (bn0 == 64) ? g_k : g_v;
    #pragma unroll
    for (int i=0;i<4;i++){
        float4 o = make_float4(acc[i][0], acc[i][1], acc[i][2], acc[i][3]);
        *(float4*)&outp[(size_t)(bm0+4*ty+i)*64 + 4*tx] = o;
    }
}

/* ---- prep (layer 2): W2cat / cvec ------------------------------- */
__global__ __launch_bounds__(256) void prep_kernel(
    const float* __restrict__ pw2, const float* __restrict__ aw1,
    const float* __restrict__ pb2, const float* __restrict__ ab1)
{
    int blk = blockIdx.x;
    int t = threadIdx.x;
    if (blk < 80){
        int i = blk*256 + t;
        int r = i / 320, c = i % 320;
        if (c < 64){
            g_w2cat[i] = pw2[r*64 + c];
        } else {
            int cc = c - 64;
            float s = 0.f;
            #pragma unroll 8
            for (int d=0; d<64; d++)
                s += pw2[r*64 + d] * aw1[(64+d)*256 + cc];
            g_w2cat[i] = s;
        }
    } else {
        float s = ab1[t];
        #pragma unroll 8
        for (int d=0; d<64; d++)
            s += pb2[d] * aw1[(64+d)*256 + t];
        g_cvec[t] = s;
    }
}

/* ----------- standalone qW/kW gemm (layer 2) ---------------------- */
__global__ __launch_bounds__(256) void gemm_qk_kernel(
    const float* __restrict__ X, const float* __restrict__ W,
    float* __restrict__ Y)
{
    __shared__ char smr[17408 + 4096];
    gemm_body(X, W, Y, blockIdx.x*64, blockIdx.y*64, smr);
}

/* ==== mega-fused: h1 -> H@W2cat -> vnb,sim -> softmax -> output ==== */
#define SMF_B   0                       /* 2 x 16 x 68 = 2176        */
#define SMF_A   (SMF_B + 2176)          /* 80 x 65                   */
#define SMF_V   (SMF_A + RPB*65)        /* 80 x 65                   */
#define SMF_REL (SMF_V + RPB*65)        /* 80 x 4                    */
#define SMF_SIM (SMF_REL + RPB*4)       /* 80                        */
#define SMF_JR  (SMF_SIM + RPB)         /* 80                        */
#define SMF_PW  (SMF_JR + RPB)          /* 256                       */
#define SMF_TOT ((SMF_PW + 256) * 4)

__global__ __launch_bounds__(256, 4) void fused_attn_kernel(
    const float* __restrict__ pts,
    const float* __restrict__ pw1, const float* __restrict__ pb1,
    const float* __restrict__ pb2, const float* __restrict__ aw2,
    const float* __restrict__ ab2, int outsel)
{
    extern __shared__ float sm[];
    float* Bs  = sm + SMF_B;
    float* As  = sm + SMF_A;
    float* Vs  = sm + SMF_V;
    float* Rel = sm + SMF_REL;
    float* Sim = sm + SMF_SIM;
    int*   Jr  = (int*)(sm + SMF_JR);
    float* Pw  = sm + SMF_PW;

    int t = threadIdx.x, tx = t & 15, ty = t >> 4;
    int ldr = t >> 4, ldc = t & 15;
    int q0 = blockIdx.x * QPB;
    int m0 = q0 * KNB;

    if (t < 64){
        Pw[t]     = pw1[t];
        Pw[64+t]  = pw1[64+t];
        Pw[128+t] = pw1[128+t];
        Pw[192+t] = pb1[t];
    }
    if (t < RPB){
        int gq = q0 + t/KNB;
        int b  = gq >> 13;
        int jr = (b<<13) + g_idx[m0 + t];
        Jr[t] = jr;
        Rel[t*4+0] = pts[gq*3+0] - pts[(size_t)jr*3+0];
        Rel[t*4+1] = pts[gq*3+1] - pts[(size_t)jr*3+1];
        Rel[t*4+2] = pts[gq*3+2] - pts[(size_t)jr*3+2];
    }
    *(float4*)&Bs[ldr*68 + 4*ldc] = *(const float4*)&g_w2cat[ldr*320 + 4*ldc];
    __syncthreads();

    #pragma unroll
    for (int e = t; e < RPB*64; e += 256){
        int r = e >> 6, c = e & 63;
        float h = fmaf(Rel[r*4+0], Pw[c],
                  fmaf(Rel[r*4+1], Pw[64+c],
                  fmaf(Rel[r*4+2], Pw[128+c], Pw[192+c])));
        As[r*65 + c] = fmaxf(h, 0.f);
    }
    __syncthreads();

    int jr_r[5], gq_r[5];
    #pragma unroll
    for (int i=0;i<5;i++){
        int r = ty*5 + i;
        jr_r[i] = Jr[r];
        gq_r[i] = q0 + r/KNB;
    }

    float rsum[5] = {0.f,0.f,0.f,0.f,0.f};
    float acc[5][4];
    for (int it = 0; it < 20; it++){
        int nb = it >> 2, ch = (it & 3) * 16;
        int cur = it & 1;
        float4 nxt;
        if (it < 19){
            int nit = it + 1, nnb = nit >> 2, nch = (nit & 3) * 16;
            nxt = *(const float4*)&g_w2cat[(nch+ldr)*320 + nnb*64 + 4*ldc];
        }
        if ((it & 3) == 0){
            #pragma unroll
            for (int i=0;i<5;i++){ acc[i][0]=acc[i][1]=acc[i][2]=acc[i][3]=0.f; }
        }
        const float* Bc = &Bs[cur*1088];
        #pragma unroll
        for (int k=0;k<16;k++){
            float4 bq = *(const float4*)&Bc[k*68 + 4*tx];
            #pragma unroll
            for (int i=0;i<5;i++){
                float a = As[(ty*5+i)*65 + ch + k];
                acc[i][0] += a*bq.x; acc[i][1] += a*bq.y;
                acc[i][2] += a*bq.z; acc[i][3] += a*bq.w;
            }
        }
        if ((it & 3) == 3){
            if (nb == 0){
                float4 pb = *(const float4*)&pb2[4*tx];
                #pragma unroll
                for (int i=0;i<5;i++){
                    int r = ty*5 + i;
                    float4 vv = *(const float4*)&g_v[(size_t)jr_r[i]*64 + 4*tx];
                    float* vp = &Vs[r*65 + 4*tx];
                    vp[0] = acc[i][0] + pb.x + vv.x;
                    vp[1] = acc[i][1] + pb.y + vv.y;
                    vp[2] = acc[i][2] + pb.z + vv.z;
                    vp[3] = acc[i][3] + pb.w + vv.w;
                }
            } else {
                int cb = (nb-1)*64 + 4*tx;
                float4 cv  = *(const float4*)&g_cvec[cb];
                float4 a2v = *(const float4*)&aw2[cb];
                #pragma unroll
                for (int i=0;i<5;i++){
                    float4 qv = *(const float4*)&g_qw[(size_t)gq_r[i]*256 + cb];
                    float4 kv = *(const float4*)&g_kw[(size_t)jr_r[i]*256 + cb];
                    float h0 = fmaxf(acc[i][0] + cv.x + qv.x - kv.x, 0.f);
                    float h1 = fmaxf(acc[i][1] + cv.y + qv.y - kv.y, 0.f);
                    float h2 = fmaxf(acc[i][2] + cv.z + qv.z - kv.z, 0.f);
                    float h3 = fmaxf(acc[i][3] + cv.w + qv.w - kv.w, 0.f);
                    rsum[i] += h0*a2v.x + h1*a2v.y + h2*a2v.z + h3*a2v.w;
                }
            }
        }
        if (it < 19){
            *(float4*)&Bs[(cur^1)*1088 + ldr*68 + 4*ldc] = nxt;
            __syncthreads();
        }
    }
    float abias = ab2[0];
    #pragma unroll
    for (int i=0;i<5;i++){
        float v = rsum[i];
        v += __shfl_xor_sync(0xffffffffu, v, 8);
        v += __shfl_xor_sync(0xffffffffu, v, 4);
        v += __shfl_xor_sync(0xffffffffu, v, 2);
        v += __shfl_xor_sync(0xffffffffu, v, 1);
        if (tx == 0) Sim[ty*5+i] = v + abias;
    }
    __syncthreads();

    if (t < 128){
        int w = t >> 5, lane = t & 31;
        float s = (lane < KNB) ? Sim[w*KNB + lane] : -CUDART_INF_F;
        float m = s;
        #pragma unroll
        for (int off=16; off; off>>=1) m = fmaxf(m, __shfl_xor_sync(0xffffffffu, m, off));
        float e = (lane < KNB) ? expf(s - m) : 0.f;
        float sum = e;
        #pragma unroll
        for (int off=16; off; off>>=1) sum += __shfl_xor_sync(0xffffffffu, sum, off);
        float attn = e / sum;
        float acc0 = 0.f, acc1 = 0.f;
        #pragma unroll
        for (int kk=0; kk<KNB; kk++){
            float a = __shfl_sync(0xffffffffu, attn, kk);
            const float* vb = &Vs[(w*KNB + kk)*65];
            acc0 += a * vb[lane];
            acc1 += a * vb[32 + lane];
        }
        float* xout = outsel ? g_xb : g_xa;
        xout[(size_t)(q0+w)*64 + lane]      = acc0;
        xout[(size_t)(q0+w)*64 + 32 + lane] = acc1;
    }
}

/* ---------------- global max pool (partial) ----------------------- */
__global__ void pool_kernel(void)
{
    int b = blockIdx.x, ch = blockIdx.y, c = threadIdx.x;
    float m = -CUDART_INF_F;
    int base = b*NPTS + ch*128;
    #pragma unroll 4
    for (int n=0;n<128;n++) m = fmaxf(m, g_xa[(size_t)(base+n)*64 + c]);
    g_part[(b*64 + ch)*64 + c] = m;
}

/* ---------------- head ------------------------------------------- */
__global__ void head_kernel(
    const float* __restrict__ fc1w, const float* __restrict__ fc1b,
    const float* __restrict__ fc3w, const float* __restrict__ fc3b,
    float* __restrict__ out)
{
    __shared__ float sp[BATCH*64];
    __shared__ float sh[BATCH*32];
    int t = threadIdx.x;
    if (t < 128){
        int b = t >> 6, c = t & 63;
        float m = -CUDART_INF_F;
        for (int ch=0; ch<64; ch++) m = fmaxf(m, g_part[(b*64+ch)*64 + c]);
        sp[b*64 + c] = m;
    }
    __syncthreads();
    if (t < 64){
        int b = t >> 5, cc = t & 31;
        float s = fc1b[cc];
        for (int c=0;c<64;c++) s += sp[b*64+c] * fc1w[c*32 + cc];
        sh[b*32 + cc] = fmaxf(s, 0.f);
    }
    __syncthreads();
    if (t < 6){
        int b = t / 3, o = t % 3;
        float s = fc3b[o];
        for (int cc=0;cc<32;cc++) s += sh[b*32+cc] * fc3w[cc*3 + o];
        out[b*3 + o] = s;
    }
}

/* ------------------------------ launch ---------------------------- */
extern "C" void kernel_launch(void* const* d_in, const int* in_sizes, int n_in,
                              void* d_out, int out_size)
{
    (void)in_sizes; (void)n_in; (void)out_size;
    const float* pts = (const float*)d_in[0];
    float* out = (float*)d_out;

    cudaFuncSetAttribute(fused_attn_kernel,
                         cudaFuncAttributeMaxDynamicSharedMemorySize, SMF_TOT);
    cudaFuncSetAttribute(knn_gemm_kernel,
                         cudaFuncAttributeMaxDynamicSharedMemorySize, KNN_SMEM);

    const float* W1[9] = {
        (const float*)d_in[3], (const float*)d_in[4], (const float*)d_in[5],
        (const float*)d_in[6], (const float*)d_in[7], (const float*)d_in[8],
        (const float*)d_in[9], (const float*)d_in[10], (const float*)d_in[11]};
    const float* W2[9] = {
        (const float*)d_in[12], (const float*)d_in[13], (const float*)d_in[14],
        (const float*)d_in[15], (const float*)d_in[16], (const float*)d_in[17],
        (const float*)d_in[18], (const float*)d_in[19], (const float*)d_in[20]};

    /* launch #1: embed + prep(L1); #2: qkv(L1); #3: knn + qk gemms;
       #4: fused_attn(L1)  <- ncu profile slot                        */
    setup_kernel<<<4177, 256>>>(pts, (const float*)d_in[1], (const float*)d_in[2],
                                W1[3], W1[5], W1[4], W1[6]);
    qkv_kernel<<<dim3(BN_TOT/64, 3), 256>>>(0, W1[0]);
    knn_gemm_kernel<<<2560, 256, KNN_SMEM>>>(pts, W1[5]);
    fused_attn_kernel<<<BN_TOT/QPB, 256, SMF_TOT>>>(
        pts, W1[1], W1[2], W1[4], W1[7], W1[8], 1);

    prep_kernel<<<81, 256>>>(W2[3], W2[5], W2[4], W2[6]);
    qkv_kernel<<<dim3(BN_TOT/64, 3), 256>>>(1, W2[0]);
    gemm_qk_kernel<<<dim3(BN_TOT/64, 4), 256>>>(g_q, W2[5], g_qw);
    gemm_qk_kernel<<<dim3(BN_TOT/64, 4), 256>>>(g_k, W2[5], g_kw);
    fused_attn_kernel<<<BN_TOT/QPB, 256, SMF_TOT>>>(
        pts, W2[1], W2[2], W2[4], W2[7], W2[8], 0);

    pool_kernel<<<dim3(BATCH, 64), 64>>>();
    head_kernel<<<1, 128>>>((const float*)d_in[21], (const float*)d_in[22],
                            (const float*)d_in[23], (const float*)d_in[24], out);
}

// round 8
// speedup vs baseline: 1.8115x; 1.0183x over previous
#include <cuda_runtime.h>
#include <math_constants.h>

#define NPTS   8192
#define BATCH  2
#define BN_TOT (BATCH*NPTS)      /* 16384 */
#define KNB    20
#define M2     (BN_TOT*KNB)      /* 327680 */
#define QPB    4                 /* queries per fused block */
#define RPB    (QPB*KNB)         /* 80 pair-rows per block */

typedef unsigned long long ull;

/* ------------------------- device scratch ------------------------- */
__device__ float g_xa[BN_TOT*64];
__device__ float g_xb[BN_TOT*64];
__device__ float g_q [BN_TOT*64];
__device__ float g_k [BN_TOT*64];
__device__ float g_v [BN_TOT*64];
__device__ int   g_idx[M2];
__device__ float g_qw[BN_TOT*256];
__device__ float g_kw[BN_TOT*256];
__device__ __align__(16) float g_w2cat[64*320];
__device__ __align__(16) float g_cvec[256];
__device__ float g_part[BATCH*64*64];

/* ============ setup: embed (blocks 0..4095) + prep (4096..4176) === */
__global__ __launch_bounds__(256) void setup_kernel(
    const float* __restrict__ pts, const float* __restrict__ cw,
    const float* __restrict__ cb,  const float* __restrict__ pw2,
    const float* __restrict__ aw1, const float* __restrict__ pb2,
    const float* __restrict__ ab1)
{
    int blk = blockIdx.x, t = threadIdx.x;
    if (blk < 4096){
        int i = blk*256 + t;
        int row = i >> 6, c = i & 63;
        float x = pts[row*3+0], y = pts[row*3+1], z = pts[row*3+2];
        float s = x*cw[c] + y*cw[64+c] + z*cw[128+c] + cb[c];
        g_xa[i] = fmaxf(s, 0.f);
    } else if (blk < 4176){
        int i = (blk-4096)*256 + t;           /* 64*320 */
        int r = i / 320, c = i % 320;
        if (c < 64){
            g_w2cat[i] = pw2[r*64 + c];
        } else {
            int cc = c - 64;
            float s = 0.f;
            #pragma unroll 8
            for (int d=0; d<64; d++)
                s += pw2[r*64 + d] * aw1[(64+d)*256 + cc];
            g_w2cat[i] = s;
        }
    } else {
        float s = ab1[t];
        #pragma unroll 8
        for (int d=0; d<64; d++)
            s += pb2[d] * aw1[(64+d)*256 + t];
        g_cvec[t] = s;
    }
}

/* ---------- KNN v5: 32 q/block, 8 splits (1 per warp), grid 512 --- */
#define KQ   32
#define KS   8
#define KCH  1024                /* candidates per split */
#define KBUF 16
#define KNN_SMEM 65536
#define INITKEY 0x7F800000FFFFFFFFULL

__device__ __forceinline__ void knn_body(const float* __restrict__ pts,
                                         int blk, char* smraw)
{
    float4* sp = (float4*)smraw;            /* [2048] = 32768 B */
    ull* buf = (ull*)(smraw + 32768);       /* [256*16] = 32768 B */

    int t = threadIdx.x;
    int s = t >> 5;                         /* warp = split 0..7 */
    int qi = t & 31;
    int gq = blk*KQ + qi;
    int b  = gq >> 13;
    float qx = pts[gq*3+0], qy = pts[gq*3+1], qz = pts[gq*3+2];
    const float* cloud = pts + (size_t)b*NPTS*3;

    ull best[KNB];
    #pragma unroll
    for (int p=0;p<KNB;p++) best[p] = INITKEY;
    float bd19 = CUDART_INF_F;
    int cnt = 0;

    for (int iter = 0; iter < KCH/256; iter++){
        __syncthreads();
        #pragma unroll
        for (int u=0; u<8; u++){
            const float* pp = cloud + (size_t)(u*KCH + iter*256 + t)*3;
            sp[u*256 + t] = make_float4(pp[0], pp[1], pp[2], 0.f);
        }
        __syncthreads();
        int base = s*256;
        int id0  = s*KCH + iter*256;
        for (int c8 = 0; c8 < 256; c8 += 8){
            #pragma unroll
            for (int j=0;j<8;j++){
                float4 p = sp[base + c8 + j];
                float dx = qx-p.x, dy = qy-p.y, dz = qz-p.z;
                float d2 = fmaf(dx,dx,fmaf(dy,dy,dz*dz));
                if (d2 <= bd19){
                    ull key;
                    asm("mov.b64 %0, {%1, %2};" : "=l"(key)
                        : "r"(id0 + c8 + j), "r"(__float_as_uint(d2)));
                    buf[t*KBUF + cnt++] = key;
                }
            }
            if (__any_sync(0xffffffffu, cnt >= KBUF-7)){
                int n = cnt;
                for (int j2 = 0; j2 < n; j2++){
                    ull k2 = buf[t*KBUF + j2];
                    if (k2 < best[KNB-1]){
                        best[KNB-1] = k2;
                        #pragma unroll
                        for (int p = KNB-1; p >= 1; --p){
                            ull a = best[p-1], bb = best[p];
                            bool sw = bb < a;
                            best[p-1] = sw ? bb : a;
                            best[p]   = sw ? a : bb;
                        }
                    }
                }
                cnt = 0;
                bd19 = __uint_as_float((unsigned)(best[KNB-1] >> 32));
            }
        }
    }
    for (int j2 = 0; j2 < cnt; j2++){
        ull k2 = buf[t*KBUF + j2];
        if (k2 < best[KNB-1]){
            best[KNB-1] = k2;
            #pragma unroll
            for (int p = KNB-1; p >= 1; --p){
                ull a = best[p-1], bb = best[p];
                bool sw = bb < a;
                best[p-1] = sw ? bb : a;
                best[p]   = sw ? a : bb;
            }
        }
    }

    __syncthreads();
    ull* mrg = (ull*)smraw;
    #pragma unroll
    for (int p=0;p<KNB;p++) mrg[(qi*KS + s)*KNB + p] = best[p];
    __syncthreads();

    if (t < KQ){
        int ptr[KS] = {0,0,0,0,0,0,0,0};
        int outq = blk*KQ + t;
        #pragma unroll 1
        for (int r=0;r<KNB;r++){
            ull bk = ~0ULL; int bs = 0;
            #pragma unroll
            for (int s2=0;s2<KS;s2++){
                if (ptr[s2] < KNB){
                    ull k2 = mrg[(t*KS + s2)*KNB + ptr[s2]];
                    if (k2 < bk){ bk = k2; bs = s2; }
                }
            }
            ptr[bs]++;
            g_idx[outq*KNB + r] = (int)(unsigned)(bk & 0xFFFFFFFFULL);
        }
    }
}

/* ---- gemm body (64x64 tile, K=64, B row stride 256), vec-A ------- */
__device__ __forceinline__ void gemm_body(
    const float* __restrict__ X, const float* __restrict__ W,
    float* __restrict__ Y, int bm0, int bn0, char* smraw)
{
    float* As = (float*)smraw;              /* 64*68 = 17408 B */
    float* Bs = (float*)(smraw + 17408);    /* 16*64 =  4096 B */
    int t = threadIdx.x, tx = t & 15, ty = t >> 4;
    #pragma unroll
    for (int i=0;i<4;i++){
        int idx4 = t + i*256;
        int r = idx4 >> 4, c4 = idx4 & 15;
        *(float4*)&As[r*68 + 4*c4] = *(const float4*)&X[(size_t)(bm0+r)*64 + 4*c4];
    }
    float acc[4][4] = {};
    for (int ch=0; ch<64; ch+=16){
        __syncthreads();
        {
            int r = t >> 4, c4 = t & 15;
            *(float4*)&Bs[r*64 + 4*c4] = *(const float4*)&W[(ch+r)*256 + bn0 + 4*c4];
        }
        __syncthreads();
        #pragma unroll
        for (int k4=0;k4<4;k4++){
            float4 b0 = *(float4*)&Bs[(4*k4+0)*64 + 4*tx];
            float4 b1 = *(float4*)&Bs[(4*k4+1)*64 + 4*tx];
            float4 b2 = *(float4*)&Bs[(4*k4+2)*64 + 4*tx];
            float4 b3 = *(float4*)&Bs[(4*k4+3)*64 + 4*tx];
            #pragma unroll
            for (int i=0;i<4;i++){
                float4 a = *(float4*)&As[(4*ty+i)*68 + ch + 4*k4];
                acc[i][0] += a.x*b0.x + a.y*b1.x + a.z*b2.x + a.w*b3.x;
                acc[i][1] += a.x*b0.y + a.y*b1.y + a.z*b2.y + a.w*b3.y;
                acc[i][2] += a.x*b0.z + a.y*b1.z + a.z*b2.z + a.w*b3.z;
                acc[i][3] += a.x*b0.w + a.y*b1.w + a.z*b2.w + a.w*b3.w;
            }
        }
    }
    #pragma unroll
    for (int i=0;i<4;i++){
        float4 o = make_float4(acc[i][0], acc[i][1], acc[i][2], acc[i][3]);
        *(float4*)&Y[(size_t)(bm0+4*ty+i)*256 + bn0 + 4*tx] = o;
    }
}

/* ---- combo: knn (blocks 0..511) + qW/kW gemms (512..2559) -------- */
__global__ __launch_bounds__(256) void knn_gemm_kernel(
    const float* __restrict__ pts, const float* __restrict__ aw1)
{
    extern __shared__ char smraw[];
    int blk = blockIdx.x;
    if (blk < 512){
        knn_body(pts, blk, smraw);
    } else {
        int i = blk - 512;
        const float* X = (i < 1024) ? g_q : g_k;
        float* Y       = (i < 1024) ? g_qw : g_kw;
        int j = i & 1023;
        gemm_body(X, aw1, Y, (j & 255)*64, (j >> 8)*64, smraw);
    }
}

/* ------------------------- qkv GEMM (M=16384, K=64, N=192) -------- */
__global__ __launch_bounds__(256) void qkv_kernel(int xsel, const float* __restrict__ W)
{
    __shared__ __align__(16) float As[64][68];
    __shared__ __align__(16) float Bs[16][64];
    const float* X = xsel ? g_xb : g_xa;
    int t = threadIdx.x, tx = t & 15, ty = t >> 4;
    int bm0 = blockIdx.x * 64;
    int bn0 = blockIdx.y * 64;
    #pragma unroll
    for (int i=0;i<4;i++){
        int idx4 = t + i*256;
        int r = idx4 >> 4, c4 = idx4 & 15;
        *(float4*)&As[r][4*c4] = *(const float4*)&X[(size_t)(bm0+r)*64 + 4*c4];
    }
    float acc[4][4] = {};
    for (int ch=0; ch<64; ch+=16){
        __syncthreads();
        {
            int r = t >> 4, c4 = t & 15;
            *(float4*)&Bs[r][4*c4] = *(const float4*)&W[(ch+r)*192 + bn0 + 4*c4];
        }
        __syncthreads();
        #pragma unroll
        for (int k4=0;k4<4;k4++){
            float4 b0 = *(float4*)&Bs[4*k4+0][4*tx];
            float4 b1 = *(float4*)&Bs[4*k4+1][4*tx];
            float4 b2 = *(float4*)&Bs[4*k4+2][4*tx];
            float4 b3 = *(float4*)&Bs[4*k4+3][4*tx];
            #pragma unroll
            for (int i=0;i<4;i++){
                float4 a = *(float4*)&As[4*ty+i][ch + 4*k4];
                acc[i][0] += a.x*b0.x + a.y*b1.x + a.z*b2.x + a.w*b3.x;
                acc[i][1] += a.x*b0.y + a.y*b1.y + a.z*b2.y + a.w*b3.y;
                acc[i][2] += a.x*b0.z + a.y*b1.z + a.z*b2.z + a.w*b3.z;
                acc[i][3] += a.x*b0.w + a.y*b1.w + a.z*b2.w + a.w*b3.w;
            }
        }
    }
    float* outp = (bn0 == 0) ? g_q : (bn0 == 64) ? g_k : g_v;
    #pragma unroll
    for (int i=0;i<4;i++){
        float4 o = make_float4(acc[i][0], acc[i][1], acc[i][2], acc[i][3]);
        *(float4*)&outp[(size_t)(bm0+4*ty+i)*64 + 4*tx] = o;
    }
}

/* ---- prep (layer 2): W2cat / cvec ------------------------------- */
__global__ __launch_bounds__(256) void prep_kernel(
    const float* __restrict__ pw2, const float* __restrict__ aw1,
    const float* __restrict__ pb2, const float* __restrict__ ab1)
{
    int blk = blockIdx.x;
    int t = threadIdx.x;
    if (blk < 80){
        int i = blk*256 + t;
        int r = i / 320, c = i % 320;
        if (c < 64){
            g_w2cat[i] = pw2[r*64 + c];
        } else {
            int cc = c - 64;
            float s = 0.f;
            #pragma unroll 8
            for (int d=0; d<64; d++)
                s += pw2[r*64 + d] * aw1[(64+d)*256 + cc];
            g_w2cat[i] = s;
        }
    } else {
        float s = ab1[t];
        #pragma unroll 8
        for (int d=0; d<64; d++)
            s += pb2[d] * aw1[(64+d)*256 + t];
        g_cvec[t] = s;
    }
}

/* ----------- standalone qW/kW gemm (layer 2) ---------------------- */
__global__ __launch_bounds__(256) void gemm_qk_kernel(
    const float* __restrict__ X, const float* __restrict__ W,
    float* __restrict__ Y)
{
    __shared__ __align__(16) char smr[17408 + 4096];
    gemm_body(X, W, Y, blockIdx.x*64, blockIdx.y*64, smr);
}

/* ==== mega-fused: h1 -> H@W2cat -> vnb,sim -> softmax -> output ====
   vectorized A reads (LDS.128), strides 68                          */
#define SMF_B   0                       /* 2 x 16 x 68 = 2176        */
#define SMF_A   (SMF_B + 2176)          /* 80 x 68 = 5440            */
#define SMF_V   (SMF_A + RPB*68)        /* 80 x 68 = 5440            */
#define SMF_REL (SMF_V + RPB*68)        /* 80 x 4                    */
#define SMF_SIM (SMF_REL + RPB*4)       /* 80                        */
#define SMF_JR  (SMF_SIM + RPB)         /* 80                        */
#define SMF_PW  (SMF_JR + RPB)          /* 256                       */
#define SMF_TOT ((SMF_PW + 256) * 4)

__global__ __launch_bounds__(256, 4) void fused_attn_kernel(
    const float* __restrict__ pts,
    const float* __restrict__ pw1, const float* __restrict__ pb1,
    const float* __restrict__ pb2, const float* __restrict__ aw2,
    const float* __restrict__ ab2, int outsel)
{
    extern __shared__ float sm[];
    float* Bs  = sm + SMF_B;
    float* As  = sm + SMF_A;
    float* Vs  = sm + SMF_V;
    float* Rel = sm + SMF_REL;
    float* Sim = sm + SMF_SIM;
    int*   Jr  = (int*)(sm + SMF_JR);
    float* Pw  = sm + SMF_PW;

    int t = threadIdx.x, tx = t & 15, ty = t >> 4;
    int ldr = t >> 4, ldc = t & 15;
    int q0 = blockIdx.x * QPB;
    int m0 = q0 * KNB;

    if (t < 64){
        Pw[t]     = pw1[t];
        Pw[64+t]  = pw1[64+t];
        Pw[128+t] = pw1[128+t];
        Pw[192+t] = pb1[t];
    }
    if (t < RPB){
        int gq = q0 + t/KNB;
        int b  = gq >> 13;
        int jr = (b<<13) + g_idx[m0 + t];
        Jr[t] = jr;
        Rel[t*4+0] = pts[gq*3+0] - pts[(size_t)jr*3+0];
        Rel[t*4+1] = pts[gq*3+1] - pts[(size_t)jr*3+1];
        Rel[t*4+2] = pts[gq*3+2] - pts[(size_t)jr*3+2];
    }
    *(float4*)&Bs[ldr*68 + 4*ldc] = *(const float4*)&g_w2cat[ldr*320 + 4*ldc];
    __syncthreads();

    #pragma unroll
    for (int e = t; e < RPB*64; e += 256){
        int r = e >> 6, c = e & 63;
        float h = fmaf(Rel[r*4+0], Pw[c],
                  fmaf(Rel[r*4+1], Pw[64+c],
                  fmaf(Rel[r*4+2], Pw[128+c], Pw[192+c])));
        As[r*68 + c] = fmaxf(h, 0.f);
    }
    __syncthreads();

    int jr_r[5], gq_r[5];
    #pragma unroll
    for (int i=0;i<5;i++){
        int r = ty*5 + i;
        jr_r[i] = Jr[r];
        gq_r[i] = q0 + r/KNB;
    }

    float rsum[5] = {0.f,0.f,0.f,0.f,0.f};
    float acc[5][4];
    for (int it = 0; it < 20; it++){
        int nb = it >> 2, ch = (it & 3) * 16;
        int cur = it & 1;
        float4 nxt;
        if (it < 19){
            int nit = it + 1, nnb = nit >> 2, nch = (nit & 3) * 16;
            nxt = *(const float4*)&g_w2cat[(nch+ldr)*320 + nnb*64 + 4*ldc];
        }
        if ((it & 3) == 0){
            #pragma unroll
            for (int i=0;i<5;i++){ acc[i][0]=acc[i][1]=acc[i][2]=acc[i][3]=0.f; }
        }
        const float* Bc = &Bs[cur*1088];
        #pragma unroll
        for (int k4=0;k4<4;k4++){
            float4 b0 = *(const float4*)&Bc[(4*k4+0)*68 + 4*tx];
            float4 b1 = *(const float4*)&Bc[(4*k4+1)*68 + 4*tx];
            float4 b2 = *(const float4*)&Bc[(4*k4+2)*68 + 4*tx];
            float4 b3 = *(const float4*)&Bc[(4*k4+3)*68 + 4*tx];
            #pragma unroll
            for (int i=0;i<5;i++){
                float4 a = *(const float4*)&As[(ty*5+i)*68 + ch + 4*k4];
                acc[i][0] += a.x*b0.x + a.y*b1.x + a.z*b2.x + a.w*b3.x;
                acc[i][1] += a.x*b0.y + a.y*b1.y + a.z*b2.y + a.w*b3.y;
                acc[i][2] += a.x*b0.z + a.y*b1.z + a.z*b2.z + a.w*b3.z;
                acc[i][3] += a.x*b0.w + a.y*b1.w + a.z*b2.w + a.w*b3.w;
            }
        }
        if ((it & 3) == 3){
            if (nb == 0){
                float4 pb = *(const float4*)&pb2[4*tx];
                #pragma unroll
                for (int i=0;i<5;i++){
                    int r = ty*5 + i;
                    float4 vv = *(const float4*)&g_v[(size_t)jr_r[i]*64 + 4*tx];
                    float4 o = make_float4(acc[i][0]+pb.x+vv.x, acc[i][1]+pb.y+vv.y,
                                           acc[i][2]+pb.z+vv.z, acc[i][3]+pb.w+vv.w);
                    *(float4*)&Vs[r*68 + 4*tx] = o;
                }
            } else {
                int cb = (nb-1)*64 + 4*tx;
                float4 cv  = *(const float4*)&g_cvec[cb];
                float4 a2v = *(const float4*)&aw2[cb];
                #pragma unroll
                for (int i=0;i<5;i++){
                    float4 qv = *(const float4*)&g_qw[(size_t)gq_r[i]*256 + cb];
                    float4 kv = *(const float4*)&g_kw[(size_t)jr_r[i]*256 + cb];
                    float h0 = fmaxf(acc[i][0] + cv.x + qv.x - kv.x, 0.f);
                    float h1 = fmaxf(acc[i][1] + cv.y + qv.y - kv.y, 0.f);
                    float h2 = fmaxf(acc[i][2] + cv.z + qv.z - kv.z, 0.f);
                    float h3 = fmaxf(acc[i][3] + cv.w + qv.w - kv.w, 0.f);
                    rsum[i] += h0*a2v.x + h1*a2v.y + h2*a2v.z + h3*a2v.w;
                }
            }
        }
        if (it < 19){
            *(float4*)&Bs[(cur^1)*1088 + ldr*68 + 4*ldc] = nxt;
            __syncthreads();
        }
    }
    float abias = ab2[0];
    #pragma unroll
    for (int i=0;i<5;i++){
        float v = rsum[i];
        v += __shfl_xor_sync(0xffffffffu, v, 8);
        v += __shfl_xor_sync(0xffffffffu, v, 4);
        v += __shfl_xor_sync(0xffffffffu, v, 2);
        v += __shfl_xor_sync(0xffffffffu, v, 1);
        if (tx == 0) Sim[ty*5+i] = v + abias;
    }
    __syncthreads();

    if (t < 128){
        int w = t >> 5, lane = t & 31;
        float s = (lane < KNB) ? Sim[w*KNB + lane] : -CUDART_INF_F;
        float m = s;
        #pragma unroll
        for (int off=16; off; off>>=1) m = fmaxf(m, __shfl_xor_sync(0xffffffffu, m, off));
        float e = (lane < KNB) ? expf(s - m) : 0.f;
        float sum = e;
        #pragma unroll
        for (int off=16; off; off>>=1) sum += __shfl_xor_sync(0xffffffffu, sum, off);
        float attn = e / sum;
        float acc0 = 0.f, acc1 = 0.f;
        #pragma unroll
        for (int kk=0; kk<KNB; kk++){
            float a = __shfl_sync(0xffffffffu, attn, kk);
            const float* vb = &Vs[(w*KNB + kk)*68];
            acc0 += a * vb[lane];
            acc1 += a * vb[32 + lane];
        }
        float* xout = outsel ? g_xb : g_xa;
        xout[(size_t)(q0+w)*64 + lane]      = acc0;
        xout[(size_t)(q0+w)*64 + 32 + lane] = acc1;
    }
}

/* ---------------- global max pool (partial) ----------------------- */
__global__ void pool_kernel(void)
{
    int b = blockIdx.x, ch = blockIdx.y, c = threadIdx.x;
    float m = -CUDART_INF_F;
    int base = b*NPTS + ch*128;
    #pragma unroll 4
    for (int n=0;n<128;n++) m = fmaxf(m, g_xa[(size_t)(base+n)*64 + c]);
    g_part[(b*64 + ch)*64 + c] = m;
}

/* ---------------- head ------------------------------------------- */
__global__ void head_kernel(
    const float* __restrict__ fc1w, const float* __restrict__ fc1b,
    const float* __restrict__ fc3w, const float* __restrict__ fc3b,
    float* __restrict__ out)
{
    __shared__ float sp[BATCH*64];
    __shared__ float sh[BATCH*32];
    int t = threadIdx.x;
    if (t < 128){
        int b = t >> 6, c = t & 63;
        float m = -CUDART_INF_F;
        for (int ch=0; ch<64; ch++) m = fmaxf(m, g_part[(b*64+ch)*64 + c]);
        sp[b*64 + c] = m;
    }
    __syncthreads();
    if (t < 64){
        int b = t >> 5, cc = t & 31;
        float s = fc1b[cc];
        for (int c=0;c<64;c++) s += sp[b*64+c] * fc1w[c*32 + cc];
        sh[b*32 + cc] = fmaxf(s, 0.f);
    }
    __syncthreads();
    if (t < 6){
        int b = t / 3, o = t % 3;
        float s = fc3b[o];
        for (int cc=0;cc<32;cc++) s += sh[b*32+cc] * fc3w[cc*3 + o];
        out[b*3 + o] = s;
    }
}

/* ------------------------------ launch ---------------------------- */
extern "C" void kernel_launch(void* const* d_in, const int* in_sizes, int n_in,
                              void* d_out, int out_size)
{
    (void)in_sizes; (void)n_in; (void)out_size;
    const float* pts = (const float*)d_in[0];
    float* out = (float*)d_out;

    cudaFuncSetAttribute(fused_attn_kernel,
                         cudaFuncAttributeMaxDynamicSharedMemorySize, SMF_TOT);
    cudaFuncSetAttribute(knn_gemm_kernel,
                         cudaFuncAttributeMaxDynamicSharedMemorySize, KNN_SMEM);

    const float* W1[9] = {
        (const float*)d_in[3], (const float*)d_in[4], (const float*)d_in[5],
        (const float*)d_in[6], (const float*)d_in[7], (const float*)d_in[8],
        (const float*)d_in[9], (const float*)d_in[10], (const float*)d_in[11]};
    const float* W2[9] = {
        (const float*)d_in[12], (const float*)d_in[13], (const float*)d_in[14],
        (const float*)d_in[15], (const float*)d_in[16], (const float*)d_in[17],
        (const float*)d_in[18], (const float*)d_in[19], (const float*)d_in[20]};

    setup_kernel<<<4177, 256>>>(pts, (const float*)d_in[1], (const float*)d_in[2],
                                W1[3], W1[5], W1[4], W1[6]);
    qkv_kernel<<<dim3(BN_TOT/64, 3), 256>>>(0, W1[0]);
    knn_gemm_kernel<<<2560, 256, KNN_SMEM>>>(pts, W1[5]);
    fused_attn_kernel<<<BN_TOT/QPB, 256, SMF_TOT>>>(
        pts, W1[1], W1[2], W1[4], W1[7], W1[8], 1);

    prep_kernel<<<81, 256>>>(W2[3], W2[5], W2[4], W2[6]);
    qkv_kernel<<<dim3(BN_TOT/64, 3), 256>>>(1, W2[0]);
    gemm_qk_kernel<<<dim3(BN_TOT/64, 4), 256>>>(g_q, W2[5], g_qw);
    gemm_qk_kernel<<<dim3(BN_TOT/64, 4), 256>>>(g_k, W2[5], g_kw);
    fused_attn_kernel<<<BN_TOT/QPB, 256, SMF_TOT>>>(
        pts, W2[1], W2[2], W2[4], W2[7], W2[8], 0);

    pool_kernel<<<dim3(BATCH, 64), 64>>>();
    head_kernel<<<1, 128>>>((const float*)d_in[21], (const float*)d_in[22],
                            (const float*)d_in[23], (const float*)d_in[24], out);
}

// round 9
// speedup vs baseline: 2.1967x; 1.2126x over previous
#include <cuda_runtime.h>
#include <math_constants.h>

#define NPTS   8192
#define BATCH  2
#define BN_TOT (BATCH*NPTS)      /* 16384 */
#define KNB    20
#define M2     (BN_TOT*KNB)      /* 327680 */
#define QPB    4                 /* queries per fused block */
#define RPB    (QPB*KNB)         /* 80 pair-rows per block */

typedef unsigned long long ull;

/* ------------------------- device scratch ------------------------- */
__device__ float g_xa[BN_TOT*64];
__device__ float g_xb[BN_TOT*64];
__device__ float g_v [BN_TOT*64];
__device__ int   g_idx[M2];
__device__ float g_qw[BN_TOT*256];
__device__ float g_kw[BN_TOT*256];
__device__ __align__(16) float g_w2cat[2*64*320];
__device__ __align__(16) float g_cvec[2*256];
__device__ __align__(16) float g_wcat[2*64*576];
__device__ float g_part[BATCH*64*64];

/* ==== setup: embed (0..4095) + per-layer prep (4096..4545) ======== */
__global__ __launch_bounds__(256) void setup_kernel(
    const float* __restrict__ pts, const float* __restrict__ cw,
    const float* __restrict__ cb,
    const float* __restrict__ qkv1, const float* __restrict__ pw2_1,
    const float* __restrict__ aw1_1, const float* __restrict__ pb2_1,
    const float* __restrict__ ab1_1,
    const float* __restrict__ qkv2, const float* __restrict__ pw2_2,
    const float* __restrict__ aw1_2, const float* __restrict__ pb2_2,
    const float* __restrict__ ab1_2)
{
    int blk = blockIdx.x, t = threadIdx.x;
    if (blk < 4096){
        int i = blk*256 + t;
        int row = i >> 6, c = i & 63;
        float x = pts[row*3+0], y = pts[row*3+1], z = pts[row*3+2];
        float s = x*cw[c] + y*cw[64+c] + z*cw[128+c] + cb[c];
        g_xa[i] = fmaxf(s, 0.f);
        return;
    }
    int r = blk - 4096;                 /* 0..449 */
    int L  = r / 225;
    int rr = r % 225;
    const float* qkvw = L ? qkv2 : qkv1;
    const float* pw2  = L ? pw2_2 : pw2_1;
    const float* aw1  = L ? aw1_2 : aw1_1;
    const float* pb2  = L ? pb2_2 : pb2_1;
    const float* ab1  = L ? ab1_2 : ab1_1;
    float* w2 = g_w2cat + L*64*320;
    float* cv = g_cvec  + L*256;
    float* wc = g_wcat  + L*64*576;

    if (rr < 80){                       /* w2cat = [pw2 | pw2@aw1_bot] */
        int i = rr*256 + t;             /* 64*320 */
        int row = i / 320, c = i % 320;
        if (c < 64){
            w2[i] = pw2[row*64 + c];
        } else {
            int cc = c - 64;
            float s = 0.f;
            #pragma unroll 8
            for (int d=0; d<64; d++)
                s += pw2[row*64 + d] * aw1[(64+d)*256 + cc];
            w2[i] = s;
        }
    } else if (rr == 80){               /* cvec = ab1 + pb2@aw1_bot */
        float s = ab1[t];
        #pragma unroll 8
        for (int d=0; d<64; d++)
            s += pb2[d] * aw1[(64+d)*256 + t];
        cv[t] = s;
    } else {                            /* wcat = [Wv | Wq@aw1t | Wk@aw1t] */
        int i = (rr-81)*256 + t;        /* 64*576 */
        int row = i / 576, c = i % 576;
        float s;
        if (c < 64){
            s = qkvw[row*192 + 128 + c];            /* Wv */
        } else if (c < 320){
            int cc = c - 64;
            s = 0.f;
            #pragma unroll 8
            for (int d=0; d<64; d++)                /* Wq@aw1_top */
                s += qkvw[row*192 + d] * aw1[d*256 + cc];
        } else {
            int cc = c - 320;
            s = 0.f;
            #pragma unroll 8
            for (int d=0; d<64; d++)                /* Wk@aw1_top */
                s += qkvw[row*192 + 64 + d] * aw1[d*256 + cc];
        }
        wc[i] = s;
    }
}

/* ---------- KNN v6: shared union-threshold pruning ---------------- */
#define KQ   32
#define KS   8
#define KCH  1024
#define KBUF 15
#define KNN_SMEM 64512
#define INITKEY 0x7F800000FFFFFFFFULL

__global__ __launch_bounds__(256) void knn_kernel(const float* __restrict__ pts)
{
    extern __shared__ char smraw[];
    float4* sp  = (float4*)smraw;               /* [2048] = 32768 B */
    ull* buf    = (ull*)(smraw + 32768);        /* [256*15] = 30720 B */
    float* thrs = (float*)(smraw + 63488);      /* [256] */

    int t = threadIdx.x;
    int s = t >> 5;                             /* warp = split 0..7 */
    int qi = t & 31;
    int gq = blockIdx.x*KQ + qi;
    int b  = gq >> 13;
    float qx = pts[gq*3+0], qy = pts[gq*3+1], qz = pts[gq*3+2];
    const float* cloud = pts + (size_t)b*NPTS*3;

    ull best[KNB];
    #pragma unroll
    for (int p=0;p<KNB;p++) best[p] = INITKEY;
    float thrq = CUDART_INF_F;
    int cnt = 0;
    thrs[t] = CUDART_INF_F;

    for (int iter = 0; iter < KCH/256; iter++){
        __syncthreads();
        #pragma unroll
        for (int u=0; u<8; u++){
            const float* pp = cloud + (size_t)(u*KCH + iter*256 + t)*3;
            sp[u*256 + t] = make_float4(pp[0], pp[1], pp[2], 0.f);
        }
        __syncthreads();
        int base = s*256;
        int id0  = s*KCH + iter*256;
        for (int c8 = 0; c8 < 256; c8 += 8){
            if ((c8 & 31) == 0){        /* advisory union threshold */
                float m0 = fminf(fminf(thrs[qi],     thrs[qi+32]),
                                 fminf(thrs[qi+64],  thrs[qi+96]));
                float m1 = fminf(fminf(thrs[qi+128], thrs[qi+160]),
                                 fminf(thrs[qi+192], thrs[qi+224]));
                thrq = fminf(thrq, fminf(m0, m1));
            }
            #pragma unroll
            for (int j=0;j<8;j++){
                float4 p = sp[base + c8 + j];
                float dx = qx-p.x, dy = qy-p.y, dz = qz-p.z;
                float d2 = fmaf(dx,dx,fmaf(dy,dy,dz*dz));
                if (d2 <= thrq){
                    ull key;
                    asm("mov.b64 %0, {%1, %2};" : "=l"(key)
                        : "r"(id0 + c8 + j), "r"(__float_as_uint(d2)));
                    buf[t*KBUF + cnt++] = key;
                }
            }
            if (__any_sync(0xffffffffu, cnt >= KBUF-7)){
                int n = cnt;
                for (int j2 = 0; j2 < n; j2++){
                    ull k2 = buf[t*KBUF + j2];
                    if (k2 < best[KNB-1]){
                        best[KNB-1] = k2;
                        #pragma unroll
                        for (int p = KNB-1; p >= 1; --p){
                            ull a = best[p-1], bb = best[p];
                            bool sw = bb < a;
                            best[p-1] = sw ? bb : a;
                            best[p]   = sw ? a : bb;
                        }
                    }
                }
                cnt = 0;
                float bd19 = __uint_as_float((unsigned)(best[KNB-1] >> 32));
                thrq = fminf(thrq, bd19);
                thrs[t] = bd19;
            }
        }
    }
    for (int j2 = 0; j2 < cnt; j2++){
        ull k2 = buf[t*KBUF + j2];
        if (k2 < best[KNB-1]){
            best[KNB-1] = k2;
            #pragma unroll
            for (int p = KNB-1; p >= 1; --p){
                ull a = best[p-1], bb = best[p];
                bool sw = bb < a;
                best[p-1] = sw ? bb : a;
                best[p]   = sw ? a : bb;
            }
        }
    }

    __syncthreads();
    ull* mrg = (ull*)smraw;                     /* [32*8*20] = 40960 B */
    #pragma unroll
    for (int p=0;p<KNB;p++) mrg[(qi*KS + s)*KNB + p] = best[p];
    __syncthreads();

    if (t < KQ){
        int ptr[KS] = {0,0,0,0,0,0,0,0};
        int outq = blockIdx.x*KQ + t;
        #pragma unroll 1
        for (int r=0;r<KNB;r++){
            ull bk = ~0ULL; int bs = 0;
            #pragma unroll
            for (int s2=0;s2<KS;s2++){
                if (ptr[s2] < KNB){
                    ull k2 = mrg[(t*KS + s2)*KNB + ptr[s2]];
                    if (k2 < bk){ bk = k2; bs = s2; }
                }
            }
            ptr[bs]++;
            g_idx[outq*KNB + r] = (int)(unsigned)(bk & 0xFFFFFFFFULL);
        }
    }
}

/* ---- point_gemm: [v|qW|kW] = x @ wcat (M=16384, K=64, N=576) ----- */
__global__ __launch_bounds__(256) void point_gemm_kernel(int layer, int xsel)
{
    __shared__ __align__(16) float As[64][68];
    __shared__ __align__(16) float Bs[16][64];
    const float* X = xsel ? g_xb : g_xa;
    const float* W = g_wcat + layer*64*576;
    int t = threadIdx.x, tx = t & 15, ty = t >> 4;
    int bm0 = blockIdx.x * 64;
    int by  = blockIdx.y;
    int n0  = by * 64;
    #pragma unroll
    for (int i=0;i<4;i++){
        int idx4 = t + i*256;
        int r = idx4 >> 4, c4 = idx4 & 15;
        *(float4*)&As[r][4*c4] = *(const float4*)&X[(size_t)(bm0+r)*64 + 4*c4];
    }
    float acc[4][4] = {};
    for (int ch=0; ch<64; ch+=16){
        __syncthreads();
        {
            int r = t >> 4, c4 = t & 15;
            *(float4*)&Bs[r][4*c4] = *(const float4*)&W[(ch+r)*576 + n0 + 4*c4];
        }
        __syncthreads();
        #pragma unroll
        for (int k4=0;k4<4;k4++){
            float4 b0 = *(float4*)&Bs[4*k4+0][4*tx];
            float4 b1 = *(float4*)&Bs[4*k4+1][4*tx];
            float4 b2 = *(float4*)&Bs[4*k4+2][4*tx];
            float4 b3 = *(float4*)&Bs[4*k4+3][4*tx];
            #pragma unroll
            for (int i=0;i<4;i++){
                float4 a = *(float4*)&As[4*ty+i][ch + 4*k4];
                acc[i][0] += a.x*b0.x + a.y*b1.x + a.z*b2.x + a.w*b3.x;
                acc[i][1] += a.x*b0.y + a.y*b1.y + a.z*b2.y + a.w*b3.y;
                acc[i][2] += a.x*b0.z + a.y*b1.z + a.z*b2.z + a.w*b3.z;
                acc[i][3] += a.x*b0.w + a.y*b1.w + a.z*b2.w + a.w*b3.w;
            }
        }
    }
    float* outp; int stride, c0;
    if (by == 0){ outp = g_v;  stride = 64;  c0 = 0; }
    else if (by < 5){ outp = g_qw; stride = 256; c0 = (by-1)*64; }
    else { outp = g_kw; stride = 256; c0 = (by-5)*64; }
    #pragma unroll
    for (int i=0;i<4;i++){
        float4 o = make_float4(acc[i][0], acc[i][1], acc[i][2], acc[i][3]);
        *(float4*)&outp[(size_t)(bm0+4*ty+i)*stride + c0 + 4*tx] = o;
    }
}

/* ==== mega-fused: h1 -> H@W2cat -> vnb,sim -> softmax -> output ==== */
#define SMF_B   0                       /* 2 x 16 x 68 = 2176        */
#define SMF_A   (SMF_B + 2176)          /* 80 x 68 = 5440            */
#define SMF_V   (SMF_A + RPB*68)        /* 80 x 68 = 5440            */
#define SMF_REL (SMF_V + RPB*68)        /* 80 x 4                    */
#define SMF_SIM (SMF_REL + RPB*4)       /* 80                        */
#define SMF_JR  (SMF_SIM + RPB)         /* 80                        */
#define SMF_PW  (SMF_JR + RPB)          /* 256                       */
#define SMF_TOT ((SMF_PW + 256) * 4)

__global__ __launch_bounds__(256, 4) void fused_attn_kernel(
    const float* __restrict__ pts,
    const float* __restrict__ pw1, const float* __restrict__ pb1,
    const float* __restrict__ pb2, const float* __restrict__ aw2,
    const float* __restrict__ ab2, int layer, int outsel)
{
    extern __shared__ float sm[];
    float* Bs  = sm + SMF_B;
    float* As  = sm + SMF_A;
    float* Vs  = sm + SMF_V;
    float* Rel = sm + SMF_REL;
    float* Sim = sm + SMF_SIM;
    int*   Jr  = (int*)(sm + SMF_JR);
    float* Pw  = sm + SMF_PW;

    const float* W2 = g_w2cat + layer*64*320;
    const float* CV = g_cvec  + layer*256;

    int t = threadIdx.x, tx = t & 15, ty = t >> 4;
    int ldr = t >> 4, ldc = t & 15;
    int q0 = blockIdx.x * QPB;
    int m0 = q0 * KNB;

    if (t < 64){
        Pw[t]     = pw1[t];
        Pw[64+t]  = pw1[64+t];
        Pw[128+t] = pw1[128+t];
        Pw[192+t] = pb1[t];
    }
    if (t < RPB){
        int gq = q0 + t/KNB;
        int b  = gq >> 13;
        int jr = (b<<13) + g_idx[m0 + t];
        Jr[t] = jr;
        Rel[t*4+0] = pts[gq*3+0] - pts[(size_t)jr*3+0];
        Rel[t*4+1] = pts[gq*3+1] - pts[(size_t)jr*3+1];
        Rel[t*4+2] = pts[gq*3+2] - pts[(size_t)jr*3+2];
    }
    *(float4*)&Bs[ldr*68 + 4*ldc] = *(const float4*)&W2[ldr*320 + 4*ldc];
    __syncthreads();

    #pragma unroll
    for (int e = t; e < RPB*64; e += 256){
        int r = e >> 6, c = e & 63;
        float h = fmaf(Rel[r*4+0], Pw[c],
                  fmaf(Rel[r*4+1], Pw[64+c],
                  fmaf(Rel[r*4+2], Pw[128+c], Pw[192+c])));
        As[r*68 + c] = fmaxf(h, 0.f);
    }
    __syncthreads();

    int jr_r[5], gq_r[5];
    #pragma unroll
    for (int i=0;i<5;i++){
        int r = ty*5 + i;
        jr_r[i] = Jr[r];
        gq_r[i] = q0 + r/KNB;
    }

    float rsum[5] = {0.f,0.f,0.f,0.f,0.f};
    float acc[5][4];
    for (int it = 0; it < 20; it++){
        int nb = it >> 2, ch = (it & 3) * 16;
        int cur = it & 1;
        float4 nxt;
        if (it < 19){
            int nit = it + 1, nnb = nit >> 2, nch = (nit & 3) * 16;
            nxt = *(const float4*)&W2[(nch+ldr)*320 + nnb*64 + 4*ldc];
        }
        if ((it & 3) == 0){
            #pragma unroll
            for (int i=0;i<5;i++){ acc[i][0]=acc[i][1]=acc[i][2]=acc[i][3]=0.f; }
        }
        const float* Bc = &Bs[cur*1088];
        #pragma unroll
        for (int k4=0;k4<4;k4++){
            float4 b0 = *(const float4*)&Bc[(4*k4+0)*68 + 4*tx];
            float4 b1 = *(const float4*)&Bc[(4*k4+1)*68 + 4*tx];
            float4 b2 = *(const float4*)&Bc[(4*k4+2)*68 + 4*tx];
            float4 b3 = *(const float4*)&Bc[(4*k4+3)*68 + 4*tx];
            #pragma unroll
            for (int i=0;i<5;i++){
                float4 a = *(const float4*)&As[(ty*5+i)*68 + ch + 4*k4];
                acc[i][0] += a.x*b0.x + a.y*b1.x + a.z*b2.x + a.w*b3.x;
                acc[i][1] += a.x*b0.y + a.y*b1.y + a.z*b2.y + a.w*b3.y;
                acc[i][2] += a.x*b0.z + a.y*b1.z + a.z*b2.z + a.w*b3.z;
                acc[i][3] += a.x*b0.w + a.y*b1.w + a.z*b2.w + a.w*b3.w;
            }
        }
        if ((it & 3) == 3){
            if (nb == 0){
                float4 pb = *(const float4*)&pb2[4*tx];
                #pragma unroll
                for (int i=0;i<5;i++){
                    int r = ty*5 + i;
                    float4 vv = *(const float4*)&g_v[(size_t)jr_r[i]*64 + 4*tx];
                    float4 o = make_float4(acc[i][0]+pb.x+vv.x, acc[i][1]+pb.y+vv.y,
                                           acc[i][2]+pb.z+vv.z, acc[i][3]+pb.w+vv.w);
                    *(float4*)&Vs[r*68 + 4*tx] = o;
                }
            } else {
                int cb = (nb-1)*64 + 4*tx;
                float4 cv  = *(const float4*)&CV[cb];
                float4 a2v = *(const float4*)&aw2[cb];
                #pragma unroll
                for (int i=0;i<5;i++){
                    float4 qv = *(const float4*)&g_qw[(size_t)gq_r[i]*256 + cb];
                    float4 kv = *(const float4*)&g_kw[(size_t)jr_r[i]*256 + cb];
                    float h0 = fmaxf(acc[i][0] + cv.x + qv.x - kv.x, 0.f);
                    float h1 = fmaxf(acc[i][1] + cv.y + qv.y - kv.y, 0.f);
                    float h2 = fmaxf(acc[i][2] + cv.z + qv.z - kv.z, 0.f);
                    float h3 = fmaxf(acc[i][3] + cv.w + qv.w - kv.w, 0.f);
                    rsum[i] += h0*a2v.x + h1*a2v.y + h2*a2v.z + h3*a2v.w;
                }
            }
        }
        if (it < 19){
            *(float4*)&Bs[(cur^1)*1088 + ldr*68 + 4*ldc] = nxt;
            __syncthreads();
        }
    }
    float abias = ab2[0];
    #pragma unroll
    for (int i=0;i<5;i++){
        float v = rsum[i];
        v += __shfl_xor_sync(0xffffffffu, v, 8);
        v += __shfl_xor_sync(0xffffffffu, v, 4);
        v += __shfl_xor_sync(0xffffffffu, v, 2);
        v += __shfl_xor_sync(0xffffffffu, v, 1);
        if (tx == 0) Sim[ty*5+i] = v + abias;
    }
    __syncthreads();

    if (t < 128){
        int w = t >> 5, lane = t & 31;
        float s = (lane < KNB) ? Sim[w*KNB + lane] : -CUDART_INF_F;
        float m = s;
        #pragma unroll
        for (int off=16; off; off>>=1) m = fmaxf(m, __shfl_xor_sync(0xffffffffu, m, off));
        float e = (lane < KNB) ? expf(s - m) : 0.f;
        float sum = e;
        #pragma unroll
        for (int off=16; off; off>>=1) sum += __shfl_xor_sync(0xffffffffu, sum, off);
        float attn = e / sum;
        float acc0 = 0.f, acc1 = 0.f;
        #pragma unroll
        for (int kk=0; kk<KNB; kk++){
            float a = __shfl_sync(0xffffffffu, attn, kk);
            const float* vb = &Vs[(w*KNB + kk)*68];
            acc0 += a * vb[lane];
            acc1 += a * vb[32 + lane];
        }
        float* xout = outsel ? g_xb : g_xa;
        xout[(size_t)(q0+w)*64 + lane]      = acc0;
        xout[(size_t)(q0+w)*64 + 32 + lane] = acc1;
    }
}

/* ---------------- global max pool (partial) ----------------------- */
__global__ void pool_kernel(void)
{
    int b = blockIdx.x, ch = blockIdx.y, c = threadIdx.x;
    float m = -CUDART_INF_F;
    int base = b*NPTS + ch*128;
    #pragma unroll 4
    for (int n=0;n<128;n++) m = fmaxf(m, g_xa[(size_t)(base+n)*64 + c]);
    g_part[(b*64 + ch)*64 + c] = m;
}

/* ---------------- head ------------------------------------------- */
__global__ void head_kernel(
    const float* __restrict__ fc1w, const float* __restrict__ fc1b,
    const float* __restrict__ fc3w, const float* __restrict__ fc3b,
    float* __restrict__ out)
{
    __shared__ float sp[BATCH*64];
    __shared__ float sh[BATCH*32];
    int t = threadIdx.x;
    if (t < 128){
        int b = t >> 6, c = t & 63;
        float m = -CUDART_INF_F;
        for (int ch=0; ch<64; ch++) m = fmaxf(m, g_part[(b*64+ch)*64 + c]);
        sp[b*64 + c] = m;
    }
    __syncthreads();
    if (t < 64){
        int b = t >> 5, cc = t & 31;
        float s = fc1b[cc];
        for (int c=0;c<64;c++) s += sp[b*64+c] * fc1w[c*32 + cc];
        sh[b*32 + cc] = fmaxf(s, 0.f);
    }
    __syncthreads();
    if (t < 6){
        int b = t / 3, o = t % 3;
        float s = fc3b[o];
        for (int cc=0;cc<32;cc++) s += sh[b*32+cc] * fc3w[cc*3 + o];
        out[b*3 + o] = s;
    }
}

/* ------------------------------ launch ---------------------------- */
extern "C" void kernel_launch(void* const* d_in, const int* in_sizes, int n_in,
                              void* d_out, int out_size)
{
    (void)in_sizes; (void)n_in; (void)out_size;
    const float* pts = (const float*)d_in[0];
    float* out = (float*)d_out;

    cudaFuncSetAttribute(fused_attn_kernel,
                         cudaFuncAttributeMaxDynamicSharedMemorySize, SMF_TOT);
    cudaFuncSetAttribute(knn_kernel,
                         cudaFuncAttributeMaxDynamicSharedMemorySize, KNN_SMEM);

    const float* W1[9] = {
        (const float*)d_in[3], (const float*)d_in[4], (const float*)d_in[5],
        (const float*)d_in[6], (const float*)d_in[7], (const float*)d_in[8],
        (const float*)d_in[9], (const float*)d_in[10], (const float*)d_in[11]};
    const float* W2[9] = {
        (const float*)d_in[12], (const float*)d_in[13], (const float*)d_in[14],
        (const float*)d_in[15], (const float*)d_in[16], (const float*)d_in[17],
        (const float*)d_in[18], (const float*)d_in[19], (const float*)d_in[20]};

    /* #1 knn, #2 setup, #3 point_gemm L1, #4 fused L1 (ncu slot),
       #5 point_gemm L2, #6 fused L2, #7 pool, #8 head              */
    knn_kernel<<<BN_TOT/KQ, 256, KNN_SMEM>>>(pts);
    setup_kernel<<<4546, 256>>>(pts, (const float*)d_in[1], (const float*)d_in[2],
                                W1[0], W1[3], W1[5], W1[4], W1[6],
                                W2[0], W2[3], W2[5], W2[4], W2[6]);
    point_gemm_kernel<<<dim3(BN_TOT/64, 9), 256>>>(0, 0);
    fused_attn_kernel<<<BN_TOT/QPB, 256, SMF_TOT>>>(
        pts, W1[1], W1[2], W1[4], W1[7], W1[8], 0, 1);

    point_gemm_kernel<<<dim3(BN_TOT/64, 9), 256>>>(1, 1);
    fused_attn_kernel<<<BN_TOT/QPB, 256, SMF_TOT>>>(
        pts, W2[1], W2[2], W2[4], W2[7], W2[8], 1, 0);

    pool_kernel<<<dim3(BATCH, 64), 64>>>();
    head_kernel<<<1, 128>>>((const float*)d_in[21], (const float*)d_in[22],
                            (const float*)d_in[23], (const float*)d_in[24], out);
}

// round 10
// speedup vs baseline: 2.5722x; 1.1709x over previous
#include <cuda_runtime.h>
#include <math_constants.h>

#define NPTS   8192
#define BATCH  2
#define BN_TOT (BATCH*NPTS)      /* 16384 */
#define KNB    20
#define M2     (BN_TOT*KNB)      /* 327680 */
#define QPB    4                 /* queries per fused block */
#define RPB    (QPB*KNB)         /* 80 pair-rows per block */

typedef unsigned long long ull;

/* ------------------------- device scratch ------------------------- */
__device__ float g_xa[BN_TOT*64];
__device__ float g_xb[BN_TOT*64];
__device__ float g_v [BN_TOT*64];
__device__ int   g_idx[M2];
__device__ float g_qw[BN_TOT*256];
__device__ float g_kw[BN_TOT*256];
__device__ __align__(16) float g_w2cat[2*64*320];
__device__ __align__(16) float g_cvec[2*256];
__device__ __align__(16) float g_wcat[2*64*576];
__device__ float g_part[BATCH*64*64];

/* ------------------------- f32x2 helpers -------------------------- */
__device__ __forceinline__ void fma2(ull &d, ull a, ull b){
    asm("fma.rn.f32x2 %0, %1, %2, %0;" : "+l"(d) : "l"(a), "l"(b));
}
__device__ __forceinline__ ull dup2(float a){
    ull r; asm("mov.b64 %0, {%1, %1};" : "=l"(r) : "f"(a)); return r;
}
__device__ __forceinline__ float2 unpack2(ull v){
    float2 f; asm("mov.b64 {%0,%1}, %2;" : "=f"(f.x), "=f"(f.y) : "l"(v));
    return f;
}

/* ==== setup: embed (0..4095) + per-layer prep (4096..4545) ======== */
__global__ __launch_bounds__(256) void setup_kernel(
    const float* __restrict__ pts, const float* __restrict__ cw,
    const float* __restrict__ cb,
    const float* __restrict__ qkv1, const float* __restrict__ pw2_1,
    const float* __restrict__ aw1_1, const float* __restrict__ pb2_1,
    const float* __restrict__ ab1_1,
    const float* __restrict__ qkv2, const float* __restrict__ pw2_2,
    const float* __restrict__ aw1_2, const float* __restrict__ pb2_2,
    const float* __restrict__ ab1_2)
{
    int blk = blockIdx.x, t = threadIdx.x;
    if (blk < 4096){
        int i = blk*256 + t;
        int row = i >> 6, c = i & 63;
        float x = pts[row*3+0], y = pts[row*3+1], z = pts[row*3+2];
        float s = x*cw[c] + y*cw[64+c] + z*cw[128+c] + cb[c];
        g_xa[i] = fmaxf(s, 0.f);
        return;
    }
    int r = blk - 4096;                 /* 0..449 */
    int L  = r / 225;
    int rr = r % 225;
    const float* qkvw = L ? qkv2 : qkv1;
    const float* pw2  = L ? pw2_2 : pw2_1;
    const float* aw1  = L ? aw1_2 : aw1_1;
    const float* pb2  = L ? pb2_2 : pb2_1;
    const float* ab1  = L ? ab1_2 : ab1_1;
    float* w2 = g_w2cat + L*64*320;
    float* cv = g_cvec  + L*256;
    float* wc = g_wcat  + L*64*576;

    if (rr < 80){                       /* w2cat = [pw2 | pw2@aw1_bot] */
        int i = rr*256 + t;             /* 64*320 */
        int row = i / 320, c = i % 320;
        if (c < 64){
            w2[i] = pw2[row*64 + c];
        } else {
            int cc = c - 64;
            float s = 0.f;
            #pragma unroll 8
            for (int d=0; d<64; d++)
                s += pw2[row*64 + d] * aw1[(64+d)*256 + cc];
            w2[i] = s;
        }
    } else if (rr == 80){               /* cvec = ab1 + pb2@aw1_bot */
        float s = ab1[t];
        #pragma unroll 8
        for (int d=0; d<64; d++)
            s += pb2[d] * aw1[(64+d)*256 + t];
        cv[t] = s;
    } else {                            /* wcat = [Wv | Wq@aw1t | Wk@aw1t] */
        int i = (rr-81)*256 + t;        /* 64*576 */
        int row = i / 576, c = i % 576;
        float s;
        if (c < 64){
            s = qkvw[row*192 + 128 + c];            /* Wv */
        } else if (c < 320){
            int cc = c - 64;
            s = 0.f;
            #pragma unroll 8
            for (int d=0; d<64; d++)                /* Wq@aw1_top */
                s += qkvw[row*192 + d] * aw1[d*256 + cc];
        } else {
            int cc = c - 320;
            s = 0.f;
            #pragma unroll 8
            for (int d=0; d<64; d++)                /* Wk@aw1_top */
                s += qkvw[row*192 + 64 + d] * aw1[d*256 + cc];
        }
        wc[i] = s;
    }
}

/* ---------- KNN v6: shared union-threshold pruning ---------------- */
#define KQ   32
#define KS   8
#define KCH  1024
#define KBUF 15
#define KNN_SMEM 64512
#define INITKEY 0x7F800000FFFFFFFFULL

__global__ __launch_bounds__(256) void knn_kernel(const float* __restrict__ pts)
{
    extern __shared__ char smraw[];
    float4* sp  = (float4*)smraw;               /* [2048] = 32768 B */
    ull* buf    = (ull*)(smraw + 32768);        /* [256*15] = 30720 B */
    float* thrs = (float*)(smraw + 63488);      /* [256] */

    int t = threadIdx.x;
    int s = t >> 5;                             /* warp = split 0..7 */
    int qi = t & 31;
    int gq = blockIdx.x*KQ + qi;
    int b  = gq >> 13;
    float qx = pts[gq*3+0], qy = pts[gq*3+1], qz = pts[gq*3+2];
    const float* cloud = pts + (size_t)b*NPTS*3;

    ull best[KNB];
    #pragma unroll
    for (int p=0;p<KNB;p++) best[p] = INITKEY;
    float thrq = CUDART_INF_F;
    int cnt = 0;
    thrs[t] = CUDART_INF_F;

    for (int iter = 0; iter < KCH/256; iter++){
        __syncthreads();
        #pragma unroll
        for (int u=0; u<8; u++){
            const float* pp = cloud + (size_t)(u*KCH + iter*256 + t)*3;
            sp[u*256 + t] = make_float4(pp[0], pp[1], pp[2], 0.f);
        }
        __syncthreads();
        int base = s*256;
        int id0  = s*KCH + iter*256;
        for (int c8 = 0; c8 < 256; c8 += 8){
            if ((c8 & 31) == 0){        /* advisory union threshold */
                float m0 = fminf(fminf(thrs[qi],     thrs[qi+32]),
                                 fminf(thrs[qi+64],  thrs[qi+96]));
                float m1 = fminf(fminf(thrs[qi+128], thrs[qi+160]),
                                 fminf(thrs[qi+192], thrs[qi+224]));
                thrq = fminf(thrq, fminf(m0, m1));
            }
            #pragma unroll
            for (int j=0;j<8;j++){
                float4 p = sp[base + c8 + j];
                float dx = qx-p.x, dy = qy-p.y, dz = qz-p.z;
                float d2 = fmaf(dx,dx,fmaf(dy,dy,dz*dz));
                if (d2 <= thrq){
                    ull key;
                    asm("mov.b64 %0, {%1, %2};" : "=l"(key)
                        : "r"(id0 + c8 + j), "r"(__float_as_uint(d2)));
                    buf[t*KBUF + cnt++] = key;
                }
            }
            if (__any_sync(0xffffffffu, cnt >= KBUF-7)){
                int n = cnt;
                for (int j2 = 0; j2 < n; j2++){
                    ull k2 = buf[t*KBUF + j2];
                    if (k2 < best[KNB-1]){
                        best[KNB-1] = k2;
                        #pragma unroll
                        for (int p = KNB-1; p >= 1; --p){
                            ull a = best[p-1], bb = best[p];
                            bool sw = bb < a;
                            best[p-1] = sw ? bb : a;
                            best[p]   = sw ? a : bb;
                        }
                    }
                }
                cnt = 0;
                float bd19 = __uint_as_float((unsigned)(best[KNB-1] >> 32));
                thrq = fminf(thrq, bd19);
                thrs[t] = bd19;
            }
        }
    }
    for (int j2 = 0; j2 < cnt; j2++){
        ull k2 = buf[t*KBUF + j2];
        if (k2 < best[KNB-1]){
            best[KNB-1] = k2;
            #pragma unroll
            for (int p = KNB-1; p >= 1; --p){
                ull a = best[p-1], bb = best[p];
                bool sw = bb < a;
                best[p-1] = sw ? bb : a;
                best[p]   = sw ? a : bb;
            }
        }
    }

    __syncthreads();
    ull* mrg = (ull*)smraw;                     /* [32*8*20] = 40960 B */
    #pragma unroll
    for (int p=0;p<KNB;p++) mrg[(qi*KS + s)*KNB + p] = best[p];
    __syncthreads();

    if (t < KQ){
        int ptr[KS] = {0,0,0,0,0,0,0,0};
        int outq = blockIdx.x*KQ + t;
        #pragma unroll 1
        for (int r=0;r<KNB;r++){
            ull bk = ~0ULL; int bs = 0;
            #pragma unroll
            for (int s2=0;s2<KS;s2++){
                if (ptr[s2] < KNB){
                    ull k2 = mrg[(t*KS + s2)*KNB + ptr[s2]];
                    if (k2 < bk){ bk = k2; bs = s2; }
                }
            }
            ptr[bs]++;
            g_idx[outq*KNB + r] = (int)(unsigned)(bk & 0xFFFFFFFFULL);
        }
    }
}

/* ---- point_gemm: [v|qW|kW] = x @ wcat (M=16384, K=64, N=576) ----- */
__global__ __launch_bounds__(256) void point_gemm_kernel(int layer, int xsel)
{
    __shared__ __align__(16) float As[64][68];
    __shared__ __align__(16) float Bs[16][64];
    const float* X = xsel ? g_xb : g_xa;
    const float* W = g_wcat + layer*64*576;
    int t = threadIdx.x, tx = t & 15, ty = t >> 4;
    int bm0 = blockIdx.x * 64;
    int by  = blockIdx.y;
    int n0  = by * 64;
    #pragma unroll
    for (int i=0;i<4;i++){
        int idx4 = t + i*256;
        int r = idx4 >> 4, c4 = idx4 & 15;
        *(float4*)&As[r][4*c4] = *(const float4*)&X[(size_t)(bm0+r)*64 + 4*c4];
    }
    float acc[4][4] = {};
    for (int ch=0; ch<64; ch+=16){
        __syncthreads();
        {
            int r = t >> 4, c4 = t & 15;
            *(float4*)&Bs[r][4*c4] = *(const float4*)&W[(ch+r)*576 + n0 + 4*c4];
        }
        __syncthreads();
        #pragma unroll
        for (int k4=0;k4<4;k4++){
            float4 b0 = *(float4*)&Bs[4*k4+0][4*tx];
            float4 b1 = *(float4*)&Bs[4*k4+1][4*tx];
            float4 b2 = *(float4*)&Bs[4*k4+2][4*tx];
            float4 b3 = *(float4*)&Bs[4*k4+3][4*tx];
            #pragma unroll
            for (int i=0;i<4;i++){
                float4 a = *(float4*)&As[4*ty+i][ch + 4*k4];
                acc[i][0] += a.x*b0.x + a.y*b1.x + a.z*b2.x + a.w*b3.x;
                acc[i][1] += a.x*b0.y + a.y*b1.y + a.z*b2.y + a.w*b3.y;
                acc[i][2] += a.x*b0.z + a.y*b1.z + a.z*b2.z + a.w*b3.z;
                acc[i][3] += a.x*b0.w + a.y*b1.w + a.z*b2.w + a.w*b3.w;
            }
        }
    }
    float* outp; int stride, c0;
    if (by == 0){ outp = g_v;  stride = 64;  c0 = 0; }
    else if (by < 5){ outp = g_qw; stride = 256; c0 = (by-1)*64; }
    else { outp = g_kw; stride = 256; c0 = (by-5)*64; }
    #pragma unroll
    for (int i=0;i<4;i++){
        float4 o = make_float4(acc[i][0], acc[i][1], acc[i][2], acc[i][3]);
        *(float4*)&outp[(size_t)(bm0+4*ty+i)*stride + c0 + 4*tx] = o;
    }
}

/* ==== mega-fused: h1 -> H@W2cat (FFMA2) -> vnb,sim -> softmax ====== */
#define SMF_B   0                       /* 2 x 16 x 68 = 2176        */
#define SMF_A   (SMF_B + 2176)          /* 80 x 68 = 5440            */
#define SMF_V   (SMF_A + RPB*68)        /* 80 x 68 = 5440            */
#define SMF_REL (SMF_V + RPB*68)        /* 80 x 4                    */
#define SMF_SIM (SMF_REL + RPB*4)       /* 80                        */
#define SMF_JR  (SMF_SIM + RPB)         /* 80                        */
#define SMF_PW  (SMF_JR + RPB)          /* 256                       */
#define SMF_TOT ((SMF_PW + 256) * 4)

__global__ __launch_bounds__(256, 3) void fused_attn_kernel(
    const float* __restrict__ pts,
    const float* __restrict__ pw1, const float* __restrict__ pb1,
    const float* __restrict__ pb2, const float* __restrict__ aw2,
    const float* __restrict__ ab2, int layer, int outsel)
{
    extern __shared__ float sm[];
    float* Bs  = sm + SMF_B;
    float* As  = sm + SMF_A;
    float* Vs  = sm + SMF_V;
    float* Rel = sm + SMF_REL;
    float* Sim = sm + SMF_SIM;
    int*   Jr  = (int*)(sm + SMF_JR);
    float* Pw  = sm + SMF_PW;

    const float* W2 = g_w2cat + layer*64*320;
    const float* CV = g_cvec  + layer*256;

    int t = threadIdx.x, tx = t & 15, ty = t >> 4;
    int ldr = t >> 4, ldc = t & 15;
    int q0 = blockIdx.x * QPB;
    int m0 = q0 * KNB;

    if (t < 64){
        Pw[t]     = pw1[t];
        Pw[64+t]  = pw1[64+t];
        Pw[128+t] = pw1[128+t];
        Pw[192+t] = pb1[t];
    }
    if (t < RPB){
        int gq = q0 + t/KNB;
        int b  = gq >> 13;
        int jr = (b<<13) + g_idx[m0 + t];
        Jr[t] = jr;
        Rel[t*4+0] = pts[gq*3+0] - pts[(size_t)jr*3+0];
        Rel[t*4+1] = pts[gq*3+1] - pts[(size_t)jr*3+1];
        Rel[t*4+2] = pts[gq*3+2] - pts[(size_t)jr*3+2];
    }
    *(float4*)&Bs[ldr*68 + 4*ldc] = *(const float4*)&W2[ldr*320 + 4*ldc];
    __syncthreads();

    #pragma unroll
    for (int e = t; e < RPB*64; e += 256){
        int r = e >> 6, c = e & 63;
        float h = fmaf(Rel[r*4+0], Pw[c],
                  fmaf(Rel[r*4+1], Pw[64+c],
                  fmaf(Rel[r*4+2], Pw[128+c], Pw[192+c])));
        As[r*68 + c] = fmaxf(h, 0.f);
    }
    __syncthreads();

    int jr_r[5], gq_r[5];
    #pragma unroll
    for (int i=0;i<5;i++){
        int r = ty*5 + i;
        jr_r[i] = Jr[r];
        gq_r[i] = q0 + r/KNB;
    }

    float rsum[5] = {0.f,0.f,0.f,0.f,0.f};
    ull acc2[5][2];
    for (int it = 0; it < 20; it++){
        int nb = it >> 2, ch = (it & 3) * 16;
        int cur = it & 1;
        float4 nxt;
        if (it < 19){
            int nit = it + 1, nnb = nit >> 2, nch = (nit & 3) * 16;
            nxt = *(const float4*)&W2[(nch+ldr)*320 + nnb*64 + 4*ldc];
        }
        if ((it & 3) == 0){
            #pragma unroll
            for (int i=0;i<5;i++){ acc2[i][0] = 0ULL; acc2[i][1] = 0ULL; }
        }
        const float* Bc = &Bs[cur*1088];
        #pragma unroll
        for (int k4=0;k4<4;k4++){
            ulonglong2 b0 = *(const ulonglong2*)&Bc[(4*k4+0)*68 + 4*tx];
            ulonglong2 b1 = *(const ulonglong2*)&Bc[(4*k4+1)*68 + 4*tx];
            ulonglong2 b2 = *(const ulonglong2*)&Bc[(4*k4+2)*68 + 4*tx];
            ulonglong2 b3 = *(const ulonglong2*)&Bc[(4*k4+3)*68 + 4*tx];
            #pragma unroll
            for (int i=0;i<5;i++){
                float4 a = *(const float4*)&As[(ty*5+i)*68 + ch + 4*k4];
                ull ax = dup2(a.x), ay = dup2(a.y);
                ull az = dup2(a.z), aw = dup2(a.w);
                fma2(acc2[i][0], ax, b0.x); fma2(acc2[i][1], ax, b0.y);
                fma2(acc2[i][0], ay, b1.x); fma2(acc2[i][1], ay, b1.y);
                fma2(acc2[i][0], az, b2.x); fma2(acc2[i][1], az, b2.y);
                fma2(acc2[i][0], aw, b3.x); fma2(acc2[i][1], aw, b3.y);
            }
        }
        if ((it & 3) == 3){
            if (nb == 0){
                float4 pb = *(const float4*)&pb2[4*tx];
                #pragma unroll
                for (int i=0;i<5;i++){
                    int r = ty*5 + i;
                    float2 lo = unpack2(acc2[i][0]);
                    float2 hi = unpack2(acc2[i][1]);
                    float4 vv = *(const float4*)&g_v[(size_t)jr_r[i]*64 + 4*tx];
                    float4 o = make_float4(lo.x+pb.x+vv.x, lo.y+pb.y+vv.y,
                                           hi.x+pb.z+vv.z, hi.y+pb.w+vv.w);
                    *(float4*)&Vs[r*68 + 4*tx] = o;
                }
            } else {
                int cb = (nb-1)*64 + 4*tx;
                float4 cv  = *(const float4*)&CV[cb];
                float4 a2v = *(const float4*)&aw2[cb];
                #pragma unroll
                for (int i=0;i<5;i++){
                    float2 lo = unpack2(acc2[i][0]);
                    float2 hi = unpack2(acc2[i][1]);
                    float4 qv = *(const float4*)&g_qw[(size_t)gq_r[i]*256 + cb];
                    float4 kv = *(const float4*)&g_kw[(size_t)jr_r[i]*256 + cb];
                    float h0 = fmaxf(lo.x + cv.x + qv.x - kv.x, 0.f);
                    float h1 = fmaxf(lo.y + cv.y + qv.y - kv.y, 0.f);
                    float h2 = fmaxf(hi.x + cv.z + qv.z - kv.z, 0.f);
                    float h3 = fmaxf(hi.y + cv.w + qv.w - kv.w, 0.f);
                    rsum[i] += h0*a2v.x + h1*a2v.y + h2*a2v.z + h3*a2v.w;
                }
            }
        }
        if (it < 19){
            *(float4*)&Bs[(cur^1)*1088 + ldr*68 + 4*ldc] = nxt;
            __syncthreads();
        }
    }
    float abias = ab2[0];
    #pragma unroll
    for (int i=0;i<5;i++){
        float v = rsum[i];
        v += __shfl_xor_sync(0xffffffffu, v, 8);
        v += __shfl_xor_sync(0xffffffffu, v, 4);
        v += __shfl_xor_sync(0xffffffffu, v, 2);
        v += __shfl_xor_sync(0xffffffffu, v, 1);
        if (tx == 0) Sim[ty*5+i] = v + abias;
    }
    __syncthreads();

    if (t < 128){
        int w = t >> 5, lane = t & 31;
        float s = (lane < KNB) ? Sim[w*KNB + lane] : -CUDART_INF_F;
        float m = s;
        #pragma unroll
        for (int off=16; off; off>>=1) m = fmaxf(m, __shfl_xor_sync(0xffffffffu, m, off));
        float e = (lane < KNB) ? expf(s - m) : 0.f;
        float sum = e;
        #pragma unroll
        for (int off=16; off; off>>=1) sum += __shfl_xor_sync(0xffffffffu, sum, off);
        float attn = e / sum;
        float acc0 = 0.f, acc1 = 0.f;
        #pragma unroll
        for (int kk=0; kk<KNB; kk++){
            float a = __shfl_sync(0xffffffffu, attn, kk);
            const float* vb = &Vs[(w*KNB + kk)*68];
            acc0 += a * vb[lane];
            acc1 += a * vb[32 + lane];
        }
        float* xout = outsel ? g_xb : g_xa;
        xout[(size_t)(q0+w)*64 + lane]      = acc0;
        xout[(size_t)(q0+w)*64 + 32 + lane] = acc1;
    }
}

/* ---------------- global max pool (partial) ----------------------- */
__global__ void pool_kernel(void)
{
    int b = blockIdx.x, ch = blockIdx.y, c = threadIdx.x;
    float m = -CUDART_INF_F;
    int base = b*NPTS + ch*128;
    #pragma unroll 4
    for (int n=0;n<128;n++) m = fmaxf(m, g_xa[(size_t)(base+n)*64 + c]);
    g_part[(b*64 + ch)*64 + c] = m;
}

/* ---------------- head ------------------------------------------- */
__global__ void head_kernel(
    const float* __restrict__ fc1w, const float* __restrict__ fc1b,
    const float* __restrict__ fc3w, const float* __restrict__ fc3b,
    float* __restrict__ out)
{
    __shared__ float sp[BATCH*64];
    __shared__ float sh[BATCH*32];
    int t = threadIdx.x;
    if (t < 128){
        int b = t >> 6, c = t & 63;
        float m = -CUDART_INF_F;
        for (int ch=0; ch<64; ch++) m = fmaxf(m, g_part[(b*64+ch)*64 + c]);
        sp[b*64 + c] = m;
    }
    __syncthreads();
    if (t < 64){
        int b = t >> 5, cc = t & 31;
        float s = fc1b[cc];
        for (int c=0;c<64;c++) s += sp[b*64+c] * fc1w[c*32 + cc];
        sh[b*32 + cc] = fmaxf(s, 0.f);
    }
    __syncthreads();
    if (t < 6){
        int b = t / 3, o = t % 3;
        float s = fc3b[o];
        for (int cc=0;cc<32;cc++) s += sh[b*32+cc] * fc3w[cc*3 + o];
        out[b*3 + o] = s;
    }
}

/* ------------------------------ launch ---------------------------- */
extern "C" void kernel_launch(void* const* d_in, const int* in_sizes, int n_in,
                              void* d_out, int out_size)
{
    (void)in_sizes; (void)n_in; (void)out_size;
    const float* pts = (const float*)d_in[0];
    float* out = (float*)d_out;

    cudaFuncSetAttribute(fused_attn_kernel,
                         cudaFuncAttributeMaxDynamicSharedMemorySize, SMF_TOT);
    cudaFuncSetAttribute(knn_kernel,
                         cudaFuncAttributeMaxDynamicSharedMemorySize, KNN_SMEM);

    const float* W1[9] = {
        (const float*)d_in[3], (const float*)d_in[4], (const float*)d_in[5],
        (const float*)d_in[6], (const float*)d_in[7], (const float*)d_in[8],
        (const float*)d_in[9], (const float*)d_in[10], (const float*)d_in[11]};
    const float* W2[9] = {
        (const float*)d_in[12], (const float*)d_in[13], (const float*)d_in[14],
        (const float*)d_in[15], (const float*)d_in[16], (const float*)d_in[17],
        (const float*)d_in[18], (const float*)d_in[19], (const float*)d_in[20]};

    /* #1 knn, #2 setup, #3 point_gemm L1, #4 fused L1 (ncu slot),
       #5 point_gemm L2, #6 fused L2, #7 pool, #8 head              */
    knn_kernel<<<BN_TOT/KQ, 256, KNN_SMEM>>>(pts);
    setup_kernel<<<4546, 256>>>(pts, (const float*)d_in[1], (const float*)d_in[2],
                                W1[0], W1[3], W1[5], W1[4], W1[6],
                                W2[0], W2[3], W2[5], W2[4], W2[6]);
    point_gemm_kernel<<<dim3(BN_TOT/64, 9), 256>>>(0, 0);
    fused_attn_kernel<<<BN_TOT/QPB, 256, SMF_TOT>>>(
        pts, W1[1], W1[2], W1[4], W1[7], W1[8], 0, 1);

    point_gemm_kernel<<<dim3(BN_TOT/64, 9), 256>>>(1, 1);
    fused_attn_kernel<<<BN_TOT/QPB, 256, SMF_TOT>>>(
        pts, W2[1], W2[2], W2[4], W2[7], W2[8], 1, 0);

    pool_kernel<<<dim3(BATCH, 64), 64>>>();
    head_kernel<<<1, 128>>>((const float*)d_in[21], (const float*)d_in[22],
                            (const float*)d_in[23], (const float*)d_in[24], out);
}